// round 8
// baseline (speedup 1.0000x reference)
#include <cuda_runtime.h>
#include <cuda_bf16.h>
#include <math.h>
#include <stdint.h>

#define BATCH   8
#define NTOK    1025
#define DMODEL  768
#define NH      12
#define HDIM    64
#define NPATCH  1024
#define QKVW    (3*DMODEL)          // 2304
#define EPS     1e-5f
#define LOG2E   1.4426950408889634f
#define SCALE   0.03608439182435161f   // 768^-0.5
#define MTOT    (BATCH*NTOK)        // 8200

// ---------------- scratch (device globals; no allocation) ----------------
__device__ __nv_bfloat16 g_xn_hi [(size_t)MTOT * DMODEL];
__device__ __nv_bfloat16 g_xn_lo [(size_t)MTOT * DMODEL];
__device__ __nv_bfloat16 g_qkv_hi[(size_t)MTOT * QKVW];
__device__ __nv_bfloat16 g_qkv_lo[(size_t)MTOT * QKVW];
__device__ __nv_bfloat16 g_ctx_hi[(size_t)MTOT * DMODEL];
__device__ __nv_bfloat16 g_ctx_lo[(size_t)MTOT * DMODEL];
__device__ __nv_bfloat16 g_wqkvT_hi[(size_t)QKVW * DMODEL];
__device__ __nv_bfloat16 g_wqkvT_lo[(size_t)QKVW * DMODEL];
__device__ __nv_bfloat16 g_woutT_hi[(size_t)DMODEL * DMODEL];
__device__ __nv_bfloat16 g_woutT_lo[(size_t)DMODEL * DMODEL];

// ---------------- helpers ----------------
__device__ __forceinline__ uint32_t smem_u32(const void* p) {
    uint32_t a;
    asm("{ .reg .u64 t; cvta.to.shared.u64 t, %1; cvt.u32.u64 %0, t; }" : "=r"(a) : "l"(p));
    return a;
}

__device__ __forceinline__ void mma_bf16(float* c, const uint32_t* a, const uint32_t* b) {
    asm volatile(
        "mma.sync.aligned.m16n8k16.row.col.f32.bf16.bf16.f32 "
        "{%0,%1,%2,%3}, {%4,%5,%6,%7}, {%8,%9}, {%0,%1,%2,%3};"
        : "+f"(c[0]), "+f"(c[1]), "+f"(c[2]), "+f"(c[3])
        : "r"(a[0]), "r"(a[1]), "r"(a[2]), "r"(a[3]), "r"(b[0]), "r"(b[1]));
}

__device__ __forceinline__ void ldsm_x4(uint32_t* f, uint32_t addr) {
    asm volatile("ldmatrix.sync.aligned.m8n8.x4.shared.b16 {%0,%1,%2,%3}, [%4];"
        : "=r"(f[0]), "=r"(f[1]), "=r"(f[2]), "=r"(f[3]) : "r"(addr));
}
__device__ __forceinline__ void ldsm_x2(uint32_t* f, uint32_t addr) {
    asm volatile("ldmatrix.sync.aligned.m8n8.x2.shared.b16 {%0,%1}, [%2];"
        : "=r"(f[0]), "=r"(f[1]) : "r"(addr));
}

#define CP_ASYNC16(dst, src, nbytes) \
    asm volatile("cp.async.cg.shared.global [%0], [%1], 16, %2;" \
                 :: "r"(dst), "l"(src), "r"(nbytes))
#define CP_COMMIT() asm volatile("cp.async.commit_group;")
#define CP_WAIT1()  asm volatile("cp.async.wait_group 1;")
#define CP_WAIT0()  asm volatile("cp.async.wait_group 0;")

// hi/lo bf16 split of two floats -> packed bf16x2 (hi, lo); a in low half
__device__ __forceinline__ void split2(float a, float b, uint32_t& hp, uint32_t& lp) {
    __nv_bfloat16 ha = __float2bfloat16_rn(a), hb = __float2bfloat16_rn(b);
    float ra = a - __bfloat162float(ha), rb = b - __bfloat162float(hb);
    __nv_bfloat16 la = __float2bfloat16_rn(ra), lb = __float2bfloat16_rn(rb);
    hp = (uint32_t)__bfloat16_as_ushort(ha) | ((uint32_t)__bfloat16_as_ushort(hb) << 16);
    lp = (uint32_t)__bfloat16_as_ushort(la) | ((uint32_t)__bfloat16_as_ushort(lb) << 16);
}

// ---------------- weight transpose + split ----------------
__global__ __launch_bounds__(256) void transpose_split_kernel(const float* __restrict__ src,
                                                              __nv_bfloat16* __restrict__ dh,
                                                              __nv_bfloat16* __restrict__ dl,
                                                              int K, int N) {
    __shared__ float t[32][33];
    int nx = blockIdx.x * 32, kx = blockIdx.y * 32;
    int lx = threadIdx.x & 31, ly = threadIdx.x >> 5;
    #pragma unroll
    for (int i = ly; i < 32; i += 8)
        t[i][lx] = src[(size_t)(kx + i) * N + nx + lx];
    __syncthreads();
    #pragma unroll
    for (int i = ly; i < 32; i += 8) {
        float v = t[lx][i];
        __nv_bfloat16 h = __float2bfloat16_rn(v);
        size_t o = (size_t)(nx + i) * K + kx + lx;
        dh[o] = h;
        dl[o] = __float2bfloat16_rn(v - __bfloat162float(h));
    }
}

// ================= tensor-core GEMM (3-stage cp.async, 1 barrier/chunk) =================
#define SM_STRIDE 20
#define ARR_BYTES (128 * SM_STRIDE * 4)     // 10240
#define STG_BYTES (4 * ARR_BYTES)           // 40960
#define GEMM_SMEM (3 * STG_BYTES)           // 122880

template<int SEL>
__global__ __launch_bounds__(256) void gemm_mma(const __nv_bfloat16* __restrict__ Bh,
                                                const __nv_bfloat16* __restrict__ Bl,
                                                const float* __restrict__ bias,
                                                float* __restrict__ Cext,
                                                int M, int N, int K) {
    const __nv_bfloat16* Ah = (SEL == 0) ? g_xn_hi : g_ctx_hi;
    const __nv_bfloat16* Al = (SEL == 0) ? g_xn_lo : g_ctx_lo;

    extern __shared__ char smem[];
    uint32_t sbase = smem_u32(smem);

    int tid = threadIdx.x;
    int wid = tid >> 5, lane = tid & 31;
    int g = lane >> 2, t = lane & 3;
    int wm = wid & 1, wn = wid >> 1;
    int m0 = blockIdx.y * 128, n0 = blockIdx.x * 128;
    int mw = wm * 64, nw = wn * 32;

    int rA = (lane & 7) + ((lane >> 3) & 1) * 8;
    int cA = (lane >> 4) * 4;
    uint32_t aoff = (uint32_t)(rA * SM_STRIDE + cA) * 4u;
    int rB = lane & 7;
    int cB = ((lane >> 3) & 1) * 4;
    uint32_t boff = (uint32_t)(rB * SM_STRIDE + cB) * 4u;

    int lr = tid >> 2, lq = tid & 3;

    float acc[4][4][4];
    #pragma unroll
    for (int i = 0; i < 4; i++)
        #pragma unroll
        for (int j = 0; j < 4; j++)
            #pragma unroll
            for (int q = 0; q < 4; q++) acc[i][j][q] = 0.f;

    int nch = K / 32;

    auto load_stage = [&](int ch, int s) {
        int kb = ch * 32;
        uint32_t so = sbase + (uint32_t)s * STG_BYTES;
        #pragma unroll
        for (int l = 0; l < 2; l++) {
            int r = lr + l * 64;
            uint32_t d = (uint32_t)(r * SM_STRIDE + lq * 4) * 4u;
            int okA = (m0 + r < M) ? 16 : 0;
            size_t ao = (size_t)(m0 + r) * K + kb + lq * 8;
            size_t bo = (size_t)(n0 + r) * K + kb + lq * 8;
            CP_ASYNC16(so + d,                 Ah + ao, okA);
            CP_ASYNC16(so + ARR_BYTES + d,     Al + ao, okA);
            CP_ASYNC16(so + 2 * ARR_BYTES + d, Bh + bo, 16);
            CP_ASYNC16(so + 3 * ARR_BYTES + d, Bl + bo, 16);
        }
    };

    load_stage(0, 0);
    CP_COMMIT();
    load_stage(1, 1);
    CP_COMMIT();

    for (int ch = 0; ch < nch; ch++) {
        int s = ch % 3;
        if (ch + 1 < nch) CP_WAIT1(); else CP_WAIT0();
        __syncthreads();
        if (ch + 2 < nch) {
            load_stage(ch + 2, (ch + 2) % 3);
            CP_COMMIT();
        }

        uint32_t uAH = sbase + (uint32_t)s * STG_BYTES;
        uint32_t uAL = uAH + ARR_BYTES;
        uint32_t uBH = uAH + 2 * ARR_BYTES;
        uint32_t uBL = uAH + 3 * ARR_BYTES;

        // ---- preload ALL fragments for both k-steps ----
        uint32_t ah[2][4][4], al[2][4][4], bh[2][4][2], bl[2][4][2];
        #pragma unroll
        for (int kk = 0; kk < 2; kk++) {
            uint32_t kcb = (uint32_t)(kk * 8) * 4u;
            #pragma unroll
            for (int mi = 0; mi < 4; mi++) {
                uint32_t base = (uint32_t)((mw + mi * 16) * SM_STRIDE) * 4u + kcb + aoff;
                ldsm_x4(ah[kk][mi], uAH + base);
                ldsm_x4(al[kk][mi], uAL + base);
            }
            #pragma unroll
            for (int nj = 0; nj < 4; nj++) {
                uint32_t base = (uint32_t)((nw + nj * 8) * SM_STRIDE) * 4u + kcb + boff;
                ldsm_x2(bh[kk][nj], uBH + base);
                ldsm_x2(bl[kk][nj], uBL + base);
            }
        }
        // ---- MMA stream ----
        #pragma unroll
        for (int kk = 0; kk < 2; kk++)
            #pragma unroll
            for (int mi = 0; mi < 4; mi++)
                #pragma unroll
                for (int nj = 0; nj < 4; nj++) {
                    mma_bf16(acc[mi][nj], ah[kk][mi], bh[kk][nj]);
                    mma_bf16(acc[mi][nj], al[kk][mi], bh[kk][nj]);
                    mma_bf16(acc[mi][nj], ah[kk][mi], bl[kk][nj]);
                }
        // no trailing barrier: 3-stage ring guarantees safety
    }

    // ---- epilogue ----
    #pragma unroll
    for (int mi = 0; mi < 4; mi++) {
        int r0e = m0 + mw + mi * 16 + g;
        #pragma unroll
        for (int nj = 0; nj < 4; nj++) {
            int col = n0 + nw + nj * 8 + t * 2;
            if (SEL == 0) {
                #pragma unroll
                for (int half = 0; half < 2; half++) {
                    int row = r0e + half * 8;
                    if (row < M) {
                        uint32_t hp, lp;
                        split2(acc[mi][nj][2 * half], acc[mi][nj][2 * half + 1], hp, lp);
                        size_t o = (size_t)row * N + col;
                        *(uint32_t*)((char*)g_qkv_hi + o * 2) = hp;
                        *(uint32_t*)((char*)g_qkv_lo + o * 2) = lp;
                    }
                }
            } else {
                float b0 = bias[col], b1 = bias[col + 1];
                if (r0e < M)
                    *(float2*)(Cext + (size_t)r0e * N + col) =
                        make_float2(acc[mi][nj][0] + b0, acc[mi][nj][1] + b1);
                if (r0e + 8 < M)
                    *(float2*)(Cext + (size_t)(r0e + 8) * N + col) =
                        make_float2(acc[mi][nj][2] + b0, acc[mi][nj][3] + b1);
            }
        }
    }
}

// ================= tensor-core flash attention (rows 1..1024) =================
// grid (8, 96), 256 threads (8 warps x m16). Double-buffered K/V smem;
// K via cp.async, V repacked to [dim][key-pair] into the idle stage.
#define ATT_STG_U32 9216u               // 36864 B / 4 per stage
#define ATT_SMEM    (2 * 36864)

__global__ __launch_bounds__(256) void attn_mma_kernel() {
    extern __shared__ uint32_t sh[];
    int qt = blockIdx.x;
    int bh_ = blockIdx.y;
    int b = bh_ / NH, h = bh_ % NH;

    int tid = threadIdx.x, wid = tid >> 5, lane = tid & 31;
    int g = lane >> 2, t = lane & 3;
    size_t base = (size_t)b * NTOK * QKVW;
    uint32_t sbase = smem_u32(sh);

    // ---- Q fragments ----
    int row0 = 1 + qt * 128 + wid * 16;
    const float qsc = SCALE * LOG2E;
    const __nv_bfloat16* Qh0 = g_qkv_hi + base + (size_t)(row0 + g) * QKVW + h * 64;
    const __nv_bfloat16* Ql0 = g_qkv_lo + base + (size_t)(row0 + g) * QKVW + h * 64;
    const __nv_bfloat16* Qh1 = Qh0 + 8 * QKVW;
    const __nv_bfloat16* Ql1 = Ql0 + 8 * QKVW;
    uint32_t qh[4][4], ql[4][4];
    #pragma unroll
    for (int kk = 0; kk < 4; kk++) {
        int k0 = kk * 16 + 2 * t;
        #pragma unroll
        for (int fi = 0; fi < 4; fi++) {
            int ko = k0 + (fi >> 1) * 8;
            const __nv_bfloat16* ph = (fi & 1) ? Qh1 : Qh0;
            const __nv_bfloat16* pl = (fi & 1) ? Ql1 : Ql0;
            __nv_bfloat162 vh = *(const __nv_bfloat162*)(ph + ko);
            __nv_bfloat162 vl = *(const __nv_bfloat162*)(pl + ko);
            float a = (__bfloat162float(vh.x) + __bfloat162float(vl.x)) * qsc;
            float c = (__bfloat162float(vh.y) + __bfloat162float(vl.y)) * qsc;
            split2(a, c, qh[kk][fi], ql[kk][fi]);
        }
    }

    // K loader (cp.async) for chunk c into stage s
    auto load_k = [&](int c, int s) {
        int j0 = c * 64;
        uint32_t sb = sbase + (uint32_t)s * 36864u;
        #pragma unroll
        for (int l = 0; l < 2; l++) {
            int idx = tid + l * 256;
            int r = idx >> 3, c8 = idx & 7;
            int j = j0 + r;
            uint32_t d = (uint32_t)(r * 36 + c8 * 4) * 4u;
            int ok = (j < NTOK) ? 16 : 0;
            size_t o = base + (size_t)j * QKVW + DMODEL + h * 64 + c8 * 8;
            CP_ASYNC16(sb + d,         (const char*)g_qkv_hi + o * 2, ok);
            CP_ASYNC16(sb + 9216u + d, (const char*)g_qkv_lo + o * 2, ok);
        }
    };
    // V loader (LDG + byte_perm + STS) for chunk c into stage s
    auto load_v = [&](int c, int s) {
        int j0 = c * 64;
        uint32_t* VH = sh + s * ATT_STG_U32 + 4608;
        uint32_t* VL = VH + 2304;
        int d0 = (tid >> 4) * 4;
        #pragma unroll
        for (int l = 0; l < 2; l++) {
            int jp = (tid & 15) + 16 * l;
            int j = j0 + 2 * jp;
            uint2 ahv = make_uint2(0, 0), bhv = ahv, alv = ahv, blv = ahv;
            size_t o = base + (size_t)j * QKVW + 2 * DMODEL + h * 64 + d0;
            if (j < NTOK) {
                ahv = *(const uint2*)((const char*)g_qkv_hi + o * 2);
                alv = *(const uint2*)((const char*)g_qkv_lo + o * 2);
            }
            if (j + 1 < NTOK) {
                bhv = *(const uint2*)((const char*)g_qkv_hi + (o + QKVW) * 2);
                blv = *(const uint2*)((const char*)g_qkv_lo + (o + QKVW) * 2);
            }
            VH[(d0 + 0) * 36 + jp] = __byte_perm(ahv.x, bhv.x, 0x5410);
            VH[(d0 + 1) * 36 + jp] = __byte_perm(ahv.x, bhv.x, 0x7632);
            VH[(d0 + 2) * 36 + jp] = __byte_perm(ahv.y, bhv.y, 0x5410);
            VH[(d0 + 3) * 36 + jp] = __byte_perm(ahv.y, bhv.y, 0x7632);
            VL[(d0 + 0) * 36 + jp] = __byte_perm(alv.x, blv.x, 0x5410);
            VL[(d0 + 1) * 36 + jp] = __byte_perm(alv.x, blv.x, 0x7632);
            VL[(d0 + 2) * 36 + jp] = __byte_perm(alv.y, blv.y, 0x5410);
            VL[(d0 + 3) * 36 + jp] = __byte_perm(alv.y, blv.y, 0x7632);
        }
    };

    float O[8][4];
    #pragma unroll
    for (int nj = 0; nj < 8; nj++)
        #pragma unroll
        for (int q = 0; q < 4; q++) O[nj][q] = 0.f;
    float mr0 = -1e30f, mr1 = -1e30f, lr0 = 0.f, lr1 = 0.f;

    load_k(0, 0);
    CP_COMMIT();
    load_v(0, 0);

    for (int c = 0; c < 17; c++) {
        int s = c & 1;
        CP_WAIT0();
        __syncthreads();
        if (c + 1 < 17) {
            load_k(c + 1, s ^ 1);
            CP_COMMIT();
            load_v(c + 1, s ^ 1);
        }
        const uint32_t* KH = sh + s * ATT_STG_U32;
        const uint32_t* KL = KH + 2304;
        const uint32_t* VH = KH + 4608;
        const uint32_t* VL = KH + 6912;
        int j0 = c * 64;

        // ---- S = Q K^T ----
        float S[8][4];
        #pragma unroll
        for (int nj = 0; nj < 8; nj++)
            #pragma unroll
            for (int q = 0; q < 4; q++) S[nj][q] = 0.f;

        #pragma unroll
        for (int kk = 0; kk < 4; kk++) {
            int kc = kk * 8;
            #pragma unroll
            for (int nj = 0; nj < 8; nj++) {
                int nc = 8 * nj + g;
                uint32_t kb[2], kl[2];
                kb[0] = KH[nc * 36 + kc + t]; kb[1] = KH[nc * 36 + kc + t + 4];
                kl[0] = KL[nc * 36 + kc + t]; kl[1] = KL[nc * 36 + kc + t + 4];
                mma_bf16(S[nj], qh[kk], kb);
                mma_bf16(S[nj], ql[kk], kb);
                mma_bf16(S[nj], qh[kk], kl);
            }
        }

        if (j0 + 64 > NTOK) {
            #pragma unroll
            for (int nj = 0; nj < 8; nj++) {
                int col = j0 + 8 * nj + 2 * t;
                if (col >= NTOK)     { S[nj][0] = -1e30f; S[nj][2] = -1e30f; }
                if (col + 1 >= NTOK) { S[nj][1] = -1e30f; S[nj][3] = -1e30f; }
            }
        }

        // ---- online softmax (log2 domain) ----
        float cm0 = -1e30f, cm1 = -1e30f;
        #pragma unroll
        for (int nj = 0; nj < 8; nj++) {
            cm0 = fmaxf(cm0, fmaxf(S[nj][0], S[nj][1]));
            cm1 = fmaxf(cm1, fmaxf(S[nj][2], S[nj][3]));
        }
        cm0 = fmaxf(cm0, __shfl_xor_sync(0xffffffffu, cm0, 1));
        cm0 = fmaxf(cm0, __shfl_xor_sync(0xffffffffu, cm0, 2));
        cm1 = fmaxf(cm1, __shfl_xor_sync(0xffffffffu, cm1, 1));
        cm1 = fmaxf(cm1, __shfl_xor_sync(0xffffffffu, cm1, 2));
        float mn0 = fmaxf(mr0, cm0), mn1 = fmaxf(mr1, cm1);
        float f0 = exp2f(mr0 - mn0), f1 = exp2f(mr1 - mn1);
        float ps0 = 0.f, ps1 = 0.f;
        #pragma unroll
        for (int nj = 0; nj < 8; nj++) {
            S[nj][0] = exp2f(S[nj][0] - mn0);
            S[nj][1] = exp2f(S[nj][1] - mn0);
            S[nj][2] = exp2f(S[nj][2] - mn1);
            S[nj][3] = exp2f(S[nj][3] - mn1);
            ps0 += S[nj][0] + S[nj][1];
            ps1 += S[nj][2] + S[nj][3];
        }
        ps0 += __shfl_xor_sync(0xffffffffu, ps0, 1);
        ps0 += __shfl_xor_sync(0xffffffffu, ps0, 2);
        ps1 += __shfl_xor_sync(0xffffffffu, ps1, 1);
        ps1 += __shfl_xor_sync(0xffffffffu, ps1, 2);
        lr0 = lr0 * f0 + ps0;
        lr1 = lr1 * f1 + ps1;
        mr0 = mn0; mr1 = mn1;
        #pragma unroll
        for (int nj = 0; nj < 8; nj++) {
            O[nj][0] *= f0; O[nj][1] *= f0;
            O[nj][2] *= f1; O[nj][3] *= f1;
        }

        // ---- O += P @ V ----
        #pragma unroll
        for (int kk = 0; kk < 4; kk++) {
            int j2 = 2 * kk;
            uint32_t ph[4], pl[4];
            split2(S[j2][0],     S[j2][1],     ph[0], pl[0]);
            split2(S[j2][2],     S[j2][3],     ph[1], pl[1]);
            split2(S[j2 + 1][0], S[j2 + 1][1], ph[2], pl[2]);
            split2(S[j2 + 1][2], S[j2 + 1][3], ph[3], pl[3]);
            #pragma unroll
            for (int nj = 0; nj < 8; nj++) {
                int n = 8 * nj + g;
                uint32_t vh[2], vl[2];
                vh[0] = VH[n * 36 + 8 * kk + t]; vh[1] = VH[n * 36 + 8 * kk + t + 4];
                vl[0] = VL[n * 36 + 8 * kk + t]; vl[1] = VL[n * 36 + 8 * kk + t + 4];
                mma_bf16(O[nj], ph, vh);
                mma_bf16(O[nj], pl, vh);
                mma_bf16(O[nj], ph, vl);
            }
        }
    }

    // ---- write out ----
    float i0 = 1.f / lr0, i1 = 1.f / lr1;
    size_t o0 = ((size_t)b * NTOK + row0 + g) * DMODEL + h * 64;
    size_t o1 = o0 + (size_t)8 * DMODEL;
    #pragma unroll
    for (int nj = 0; nj < 8; nj++) {
        int col = 8 * nj + 2 * t;
        uint32_t hp, lp;
        split2(O[nj][0] * i0, O[nj][1] * i0, hp, lp);
        *(uint32_t*)((char*)g_ctx_hi + (o0 + col) * 2) = hp;
        *(uint32_t*)((char*)g_ctx_lo + (o0 + col) * 2) = lp;
        split2(O[nj][2] * i1, O[nj][3] * i1, hp, lp);
        *(uint32_t*)((char*)g_ctx_hi + (o1 + col) * 2) = hp;
        *(uint32_t*)((char*)g_ctx_lo + (o1 + col) * 2) = lp;
    }
}

// ---------------- block reduction helpers ----------------
__device__ __forceinline__ float blockReduceSum(float v, float* red) {
    #pragma unroll
    for (int o = 16; o > 0; o >>= 1) v += __shfl_xor_sync(0xffffffffu, v, o);
    int lane = threadIdx.x & 31, w = threadIdx.x >> 5;
    __syncthreads();
    if (lane == 0) red[w] = v;
    __syncthreads();
    if (threadIdx.x == 0) {
        float s = 0.f;
        #pragma unroll
        for (int i = 0; i < 8; i++) s += red[i];
        red[0] = s;
    }
    __syncthreads();
    return red[0];
}

__device__ __forceinline__ float blockReduceMax(float v, float* red) {
    #pragma unroll
    for (int o = 16; o > 0; o >>= 1) v = fmaxf(v, __shfl_xor_sync(0xffffffffu, v, o));
    int lane = threadIdx.x & 31, w = threadIdx.x >> 5;
    __syncthreads();
    if (lane == 0) red[w] = v;
    __syncthreads();
    if (threadIdx.x == 0) {
        float s = -1e30f;
        #pragma unroll
        for (int i = 0; i < 8; i++) s = fmaxf(s, red[i]);
        red[0] = s;
    }
    __syncthreads();
    return red[0];
}

// ---------------- LayerNorm -> split bf16 hi/lo ----------------
__global__ __launch_bounds__(256) void ln_kernel(const float* __restrict__ x,
                                                 const float* __restrict__ w,
                                                 const float* __restrict__ bias) {
    int row = blockIdx.x;
    const float* xr = x + (size_t)row * DMODEL;
    int t = threadIdx.x;
    float v[3];
    float s = 0.f, sq = 0.f;
    #pragma unroll
    for (int i = 0; i < 3; i++) {
        v[i] = xr[t + i * 256];
        s += v[i];
        sq += v[i] * v[i];
    }
    __shared__ float red[32];
    __shared__ float stats[2];
    #pragma unroll
    for (int o = 16; o > 0; o >>= 1) {
        s  += __shfl_xor_sync(0xffffffffu, s, o);
        sq += __shfl_xor_sync(0xffffffffu, sq, o);
    }
    int lane = t & 31, wp = t >> 5;
    if (lane == 0) { red[wp] = s; red[8 + wp] = sq; }
    __syncthreads();
    if (t == 0) {
        float a = 0.f, b2 = 0.f;
        #pragma unroll
        for (int i = 0; i < 8; i++) { a += red[i]; b2 += red[8 + i]; }
        stats[0] = a; stats[1] = b2;
    }
    __syncthreads();
    float mean = stats[0] * (1.f / DMODEL);
    float var  = stats[1] * (1.f / DMODEL) - mean * mean;
    float inv  = rsqrtf(var + EPS);
    #pragma unroll
    for (int i = 0; i < 3; i++) {
        int c = t + i * 256;
        float o = (v[i] - mean) * inv * w[c] + bias[c];
        __nv_bfloat16 h = __float2bfloat16_rn(o);
        size_t idx = (size_t)row * DMODEL + c;
        g_xn_hi[idx] = h;
        g_xn_lo[idx] = __float2bfloat16_rn(o - __bfloat162float(h));
    }
}

// ---------------- CLS row (query row 0) ----------------
__global__ __launch_bounds__(256) void cls_kernel(const float* __restrict__ canny,
                                                  const float* __restrict__ noise) {
    int bh = blockIdx.x;
    int b = bh / NH, h = bh % NH;
    __shared__ float sm[NTOK];
    __shared__ float q0[64];
    __shared__ float red[32];
    __shared__ float part[4][64];
    int tid = threadIdx.x;
    size_t base = (size_t)b * NTOK * QKVW;

    if (tid < 64)
        q0[tid] = __bfloat162float(g_qkv_hi[base + h * 64 + tid])
                + __bfloat162float(g_qkv_lo[base + h * 64 + tid]);
    __syncthreads();

    for (int j = tid; j < NTOK; j += 256) {
        size_t ko = base + (size_t)j * QKVW + DMODEL + h * 64;
        float dot = 0.f;
        #pragma unroll
        for (int d2 = 0; d2 < 32; d2++) {
            __nv_bfloat162 kh = *(const __nv_bfloat162*)(g_qkv_hi + ko + 2 * d2);
            __nv_bfloat162 kl = *(const __nv_bfloat162*)(g_qkv_lo + ko + 2 * d2);
            dot += q0[2 * d2]     * (__bfloat162float(kh.x) + __bfloat162float(kl.x))
                 + q0[2 * d2 + 1] * (__bfloat162float(kh.y) + __bfloat162float(kl.y));
        }
        sm[j] = dot * SCALE;
    }
    __syncthreads();

    float mx = -1e30f, cs = 0.f, ns = 0.f;
    for (int j = tid; j < NPATCH; j += 256) {
        mx = fmaxf(mx, sm[j + 1]);
        cs += canny[(size_t)b * NPATCH + j] + 1.f;
        ns += noise[(size_t)b * NPATCH + j];
    }
    mx = blockReduceMax(mx, red);
    cs = blockReduceSum(cs, red);
    ns = blockReduceSum(ns, red);
    float se = 0.f;
    for (int j = tid; j < NPATCH; j += 256) se += exp2f((sm[j + 1] - mx) * LOG2E);
    se = blockReduceSum(se, red);
    float inv_se = 1.f / se, inv_cs = 1.f / cs, inv_ns = 1.f / ns;
    for (int j = tid; j < NPATCH; j += 256) {
        float a = exp2f((sm[j + 1] - mx) * LOG2E) * inv_se;
        sm[j + 1] = a + (canny[(size_t)b * NPATCH + j] + 1.f) * inv_cs
                      + noise[(size_t)b * NPATCH + j] * inv_ns;
    }
    __syncthreads();

    float mx2 = -1e30f;
    for (int j = tid; j < NTOK; j += 256) mx2 = fmaxf(mx2, sm[j]);
    mx2 = blockReduceMax(mx2, red);
    float se2 = 0.f;
    for (int j = tid; j < NTOK; j += 256) se2 += exp2f((sm[j] - mx2) * LOG2E);
    se2 = blockReduceSum(se2, red);
    float inv2 = 1.f / se2;
    for (int j = tid; j < NTOK; j += 256) sm[j] = exp2f((sm[j] - mx2) * LOG2E) * inv2;
    __syncthreads();

    int d = tid & 63, qp = tid >> 6;
    float acc = 0.f;
    for (int j = qp; j < NTOK; j += 4) {
        size_t vo = base + (size_t)j * QKVW + 2 * DMODEL + h * 64 + d;
        acc += sm[j] * (__bfloat162float(g_qkv_hi[vo]) + __bfloat162float(g_qkv_lo[vo]));
    }
    part[qp][d] = acc;
    __syncthreads();
    if (tid < 64) {
        float o = part[0][tid] + part[1][tid] + part[2][tid] + part[3][tid];
        __nv_bfloat16 hh = __float2bfloat16_rn(o);
        size_t idx = (size_t)b * NTOK * DMODEL + h * 64 + tid;
        g_ctx_hi[idx] = hh;
        g_ctx_lo[idx] = __float2bfloat16_rn(o - __bfloat162float(hh));
    }
}

// ---------------- launch ----------------
extern "C" void kernel_launch(void* const* d_in, const int* in_sizes, int n_in,
                              void* d_out, int out_size) {
    const float* x     = (const float*)d_in[0];
    const float* canny = (const float*)d_in[1];
    const float* noise = (const float*)d_in[2];
    const float* ln_w  = (const float*)d_in[3];
    const float* ln_b  = (const float*)d_in[4];
    const float* w_qkv = (const float*)d_in[5];
    const float* w_out = (const float*)d_in[6];
    const float* b_out = (const float*)d_in[7];
    float* out = (float*)d_out;

    cudaFuncSetAttribute(gemm_mma<0>, cudaFuncAttributeMaxDynamicSharedMemorySize, GEMM_SMEM);
    cudaFuncSetAttribute(gemm_mma<1>, cudaFuncAttributeMaxDynamicSharedMemorySize, GEMM_SMEM);
    cudaFuncSetAttribute(attn_mma_kernel, cudaFuncAttributeMaxDynamicSharedMemorySize, ATT_SMEM);

    __nv_bfloat16 *wqkvTh, *wqkvTl, *woutTh, *woutTl;
    cudaGetSymbolAddress((void**)&wqkvTh, g_wqkvT_hi);
    cudaGetSymbolAddress((void**)&wqkvTl, g_wqkvT_lo);
    cudaGetSymbolAddress((void**)&woutTh, g_woutT_hi);
    cudaGetSymbolAddress((void**)&woutTl, g_woutT_lo);

    // 1. LayerNorm (-> bf16 hi/lo)
    ln_kernel<<<MTOT, 256>>>(x, ln_w, ln_b);

    // 1b. transpose+split weights
    {
        dim3 g1(QKVW / 32, DMODEL / 32);
        transpose_split_kernel<<<g1, 256>>>(w_qkv, wqkvTh, wqkvTl, DMODEL, QKVW);
        dim3 g2(DMODEL / 32, DMODEL / 32);
        transpose_split_kernel<<<g2, 256>>>(w_out, woutTh, woutTl, DMODEL, DMODEL);
    }

    // 2. QKV GEMM -> g_qkv hi/lo
    {
        dim3 grid(QKVW / 128, (MTOT + 127) / 128);
        gemm_mma<0><<<grid, 256, GEMM_SMEM>>>(wqkvTh, wqkvTl, nullptr, nullptr, MTOT, QKVW, DMODEL);
    }

    // 3. attention rows 1..1024
    {
        dim3 g_attn(8, BATCH * NH);
        attn_mma_kernel<<<g_attn, 256, ATT_SMEM>>>();
    }

    // 4. CLS row with prior injection
    cls_kernel<<<BATCH * NH, 256>>>(canny, noise);

    // 5. output projection -> d_out (fp32 + bias)
    {
        dim3 grid(DMODEL / 128, (MTOT + 127) / 128);
        gemm_mma<1><<<grid, 256, GEMM_SMEM>>>(woutTh, woutTl, b_out, out, MTOT, DMODEL, DMODEL);
    }
}

// round 9
// speedup vs baseline: 1.1636x; 1.1636x over previous
#include <cuda_runtime.h>
#include <cuda_bf16.h>
#include <math.h>
#include <stdint.h>

#define BATCH   8
#define NTOK    1025
#define DMODEL  768
#define NH      12
#define HDIM    64
#define NPATCH  1024
#define QKVW    (3*DMODEL)          // 2304
#define EPS     1e-5f
#define LOG2E   1.4426950408889634f
#define SCALE   0.03608439182435161f   // 768^-0.5
#define MTOT    (BATCH*NTOK)        // 8200

// ---------------- scratch (device globals; no allocation) ----------------
__device__ __nv_bfloat16 g_xn_hi [(size_t)MTOT * DMODEL];
__device__ __nv_bfloat16 g_xn_lo [(size_t)MTOT * DMODEL];
__device__ __nv_bfloat16 g_qkv_hi[(size_t)MTOT * QKVW];
__device__ __nv_bfloat16 g_qkv_lo[(size_t)MTOT * QKVW];
__device__ __nv_bfloat16 g_ctx_hi[(size_t)MTOT * DMODEL];
__device__ __nv_bfloat16 g_ctx_lo[(size_t)MTOT * DMODEL];
__device__ __nv_bfloat16 g_wqkvT_hi[(size_t)QKVW * DMODEL];
__device__ __nv_bfloat16 g_wqkvT_lo[(size_t)QKVW * DMODEL];
__device__ __nv_bfloat16 g_woutT_hi[(size_t)DMODEL * DMODEL];
__device__ __nv_bfloat16 g_woutT_lo[(size_t)DMODEL * DMODEL];

// ---------------- helpers ----------------
__device__ __forceinline__ uint32_t smem_u32(const void* p) {
    uint32_t a;
    asm("{ .reg .u64 t; cvta.to.shared.u64 t, %1; cvt.u32.u64 %0, t; }" : "=r"(a) : "l"(p));
    return a;
}

__device__ __forceinline__ void mma_bf16(float* c, const uint32_t* a, const uint32_t* b) {
    asm volatile(
        "mma.sync.aligned.m16n8k16.row.col.f32.bf16.bf16.f32 "
        "{%0,%1,%2,%3}, {%4,%5,%6,%7}, {%8,%9}, {%0,%1,%2,%3};"
        : "+f"(c[0]), "+f"(c[1]), "+f"(c[2]), "+f"(c[3])
        : "r"(a[0]), "r"(a[1]), "r"(a[2]), "r"(a[3]), "r"(b[0]), "r"(b[1]));
}

__device__ __forceinline__ void ldsm_x4(uint32_t* f, uint32_t addr) {
    asm volatile("ldmatrix.sync.aligned.m8n8.x4.shared.b16 {%0,%1,%2,%3}, [%4];"
        : "=r"(f[0]), "=r"(f[1]), "=r"(f[2]), "=r"(f[3]) : "r"(addr));
}
__device__ __forceinline__ void ldsm_x2(uint32_t* f, uint32_t addr) {
    asm volatile("ldmatrix.sync.aligned.m8n8.x2.shared.b16 {%0,%1}, [%2];"
        : "=r"(f[0]), "=r"(f[1]) : "r"(addr));
}

#define CP_ASYNC16(dst, src, nbytes) \
    asm volatile("cp.async.cg.shared.global [%0], [%1], 16, %2;" \
                 :: "r"(dst), "l"(src), "r"(nbytes))
#define CP_COMMIT() asm volatile("cp.async.commit_group;")
#define CP_WAIT1()  asm volatile("cp.async.wait_group 1;")
#define CP_WAIT0()  asm volatile("cp.async.wait_group 0;")

// hi/lo bf16 split of two floats -> packed bf16x2 (hi, lo); a in low half
__device__ __forceinline__ void split2(float a, float b, uint32_t& hp, uint32_t& lp) {
    __nv_bfloat16 ha = __float2bfloat16_rn(a), hb = __float2bfloat16_rn(b);
    float ra = a - __bfloat162float(ha), rb = b - __bfloat162float(hb);
    __nv_bfloat16 la = __float2bfloat16_rn(ra), lb = __float2bfloat16_rn(rb);
    hp = (uint32_t)__bfloat16_as_ushort(ha) | ((uint32_t)__bfloat16_as_ushort(hb) << 16);
    lp = (uint32_t)__bfloat16_as_ushort(la) | ((uint32_t)__bfloat16_as_ushort(lb) << 16);
}

// ---------------- weight transpose + split ----------------
__global__ __launch_bounds__(256) void transpose_split_kernel(const float* __restrict__ src,
                                                              __nv_bfloat16* __restrict__ dh,
                                                              __nv_bfloat16* __restrict__ dl,
                                                              int K, int N) {
    __shared__ float t[32][33];
    int nx = blockIdx.x * 32, kx = blockIdx.y * 32;
    int lx = threadIdx.x & 31, ly = threadIdx.x >> 5;
    #pragma unroll
    for (int i = ly; i < 32; i += 8)
        t[i][lx] = src[(size_t)(kx + i) * N + nx + lx];
    __syncthreads();
    #pragma unroll
    for (int i = ly; i < 32; i += 8) {
        float v = t[lx][i];
        __nv_bfloat16 h = __float2bfloat16_rn(v);
        size_t o = (size_t)(nx + i) * K + kx + lx;
        dh[o] = h;
        dl[o] = __float2bfloat16_rn(v - __bfloat162float(h));
    }
}

// ================= tensor-core GEMM (2-stage cp.async, 1 barrier/chunk, 2 CTA/SM) =================
#define SM_STRIDE 20
#define ARR_BYTES (128 * SM_STRIDE * 4)     // 10240
#define STG_BYTES (4 * ARR_BYTES)           // 40960
#define GEMM_SMEM (2 * STG_BYTES)           // 81920

template<int SEL>
__global__ __launch_bounds__(256, 2) void gemm_mma(const __nv_bfloat16* __restrict__ Bh,
                                                   const __nv_bfloat16* __restrict__ Bl,
                                                   const float* __restrict__ bias,
                                                   float* __restrict__ Cext,
                                                   int M, int N, int K) {
    const __nv_bfloat16* Ah = (SEL == 0) ? g_xn_hi : g_ctx_hi;
    const __nv_bfloat16* Al = (SEL == 0) ? g_xn_lo : g_ctx_lo;

    extern __shared__ char smem[];
    uint32_t sbase = smem_u32(smem);

    int tid = threadIdx.x;
    int wid = tid >> 5, lane = tid & 31;
    int g = lane >> 2, t = lane & 3;
    int wm = wid & 1, wn = wid >> 1;
    int m0 = blockIdx.y * 128, n0 = blockIdx.x * 128;
    int mw = wm * 64, nw = wn * 32;

    int rA = (lane & 7) + ((lane >> 3) & 1) * 8;
    int cA = (lane >> 4) * 4;
    uint32_t aoff = (uint32_t)(rA * SM_STRIDE + cA) * 4u;
    int rB = lane & 7;
    int cB = ((lane >> 3) & 1) * 4;
    uint32_t boff = (uint32_t)(rB * SM_STRIDE + cB) * 4u;

    int lr = tid >> 2, lq = tid & 3;

    float acc[4][4][4];
    #pragma unroll
    for (int i = 0; i < 4; i++)
        #pragma unroll
        for (int j = 0; j < 4; j++)
            #pragma unroll
            for (int q = 0; q < 4; q++) acc[i][j][q] = 0.f;

    int nch = K / 32;

    auto load_stage = [&](int ch, int s) {
        int kb = ch * 32;
        uint32_t so = sbase + (uint32_t)s * STG_BYTES;
        #pragma unroll
        for (int l = 0; l < 2; l++) {
            int r = lr + l * 64;
            uint32_t d = (uint32_t)(r * SM_STRIDE + lq * 4) * 4u;
            int okA = (m0 + r < M) ? 16 : 0;
            size_t ao = (size_t)(m0 + r) * K + kb + lq * 8;
            size_t bo = (size_t)(n0 + r) * K + kb + lq * 8;
            CP_ASYNC16(so + d,                 Ah + ao, okA);
            CP_ASYNC16(so + ARR_BYTES + d,     Al + ao, okA);
            CP_ASYNC16(so + 2 * ARR_BYTES + d, Bh + bo, 16);
            CP_ASYNC16(so + 3 * ARR_BYTES + d, Bl + bo, 16);
        }
    };

    load_stage(0, 0);
    CP_COMMIT();

    for (int ch = 0; ch < nch; ch++) {
        int s = ch & 1;
        CP_WAIT0();
        __syncthreads();
        // load next chunk into the other stage (read last at MMA(ch-1), safe)
        if (ch + 1 < nch) {
            load_stage(ch + 1, s ^ 1);
            CP_COMMIT();
        }

        uint32_t uAH = sbase + (uint32_t)s * STG_BYTES;
        uint32_t uAL = uAH + ARR_BYTES;
        uint32_t uBH = uAH + 2 * ARR_BYTES;
        uint32_t uBL = uAH + 3 * ARR_BYTES;

        uint32_t ah[2][4][4], al[2][4][4], bh[2][4][2], bl[2][4][2];
        #pragma unroll
        for (int kk = 0; kk < 2; kk++) {
            uint32_t kcb = (uint32_t)(kk * 8) * 4u;
            #pragma unroll
            for (int mi = 0; mi < 4; mi++) {
                uint32_t base = (uint32_t)((mw + mi * 16) * SM_STRIDE) * 4u + kcb + aoff;
                ldsm_x4(ah[kk][mi], uAH + base);
                ldsm_x4(al[kk][mi], uAL + base);
            }
            #pragma unroll
            for (int nj = 0; nj < 4; nj++) {
                uint32_t base = (uint32_t)((nw + nj * 8) * SM_STRIDE) * 4u + kcb + boff;
                ldsm_x2(bh[kk][nj], uBH + base);
                ldsm_x2(bl[kk][nj], uBL + base);
            }
        }
        #pragma unroll
        for (int kk = 0; kk < 2; kk++)
            #pragma unroll
            for (int mi = 0; mi < 4; mi++)
                #pragma unroll
                for (int nj = 0; nj < 4; nj++) {
                    mma_bf16(acc[mi][nj], ah[kk][mi], bh[kk][nj]);
                    mma_bf16(acc[mi][nj], al[kk][mi], bh[kk][nj]);
                    mma_bf16(acc[mi][nj], ah[kk][mi], bl[kk][nj]);
                }
    }

    // ---- epilogue ----
    #pragma unroll
    for (int mi = 0; mi < 4; mi++) {
        int r0e = m0 + mw + mi * 16 + g;
        #pragma unroll
        for (int nj = 0; nj < 4; nj++) {
            int col = n0 + nw + nj * 8 + t * 2;
            if (SEL == 0) {
                #pragma unroll
                for (int half = 0; half < 2; half++) {
                    int row = r0e + half * 8;
                    if (row < M) {
                        uint32_t hp, lp;
                        split2(acc[mi][nj][2 * half], acc[mi][nj][2 * half + 1], hp, lp);
                        size_t o = (size_t)row * N + col;
                        *(uint32_t*)((char*)g_qkv_hi + o * 2) = hp;
                        *(uint32_t*)((char*)g_qkv_lo + o * 2) = lp;
                    }
                }
            } else {
                float b0 = bias[col], b1 = bias[col + 1];
                if (r0e < M)
                    *(float2*)(Cext + (size_t)r0e * N + col) =
                        make_float2(acc[mi][nj][0] + b0, acc[mi][nj][1] + b1);
                if (r0e + 8 < M)
                    *(float2*)(Cext + (size_t)(r0e + 8) * N + col) =
                        make_float2(acc[mi][nj][2] + b0, acc[mi][nj][3] + b1);
            }
        }
    }
}

// ================= tensor-core flash attention (rows 1..1024) =================
// grid (8, 96), 256 threads (8 warps x m16). K via cp.async double buffer;
// V LDG-prefetched into registers one chunk ahead, STS-drained before barrier.
#define ATT_STG_U32 9216u               // 36864 B / 4 per stage
#define ATT_SMEM    (2 * 36864)

__global__ __launch_bounds__(256) void attn_mma_kernel() {
    extern __shared__ uint32_t sh[];
    int qt = blockIdx.x;
    int bh_ = blockIdx.y;
    int b = bh_ / NH, h = bh_ % NH;

    int tid = threadIdx.x, wid = tid >> 5, lane = tid & 31;
    int g = lane >> 2, t = lane & 3;
    size_t base = (size_t)b * NTOK * QKVW;
    uint32_t sbase = smem_u32(sh);

    // ---- Q fragments ----
    int row0 = 1 + qt * 128 + wid * 16;
    const float qsc = SCALE * LOG2E;
    const __nv_bfloat16* Qh0 = g_qkv_hi + base + (size_t)(row0 + g) * QKVW + h * 64;
    const __nv_bfloat16* Ql0 = g_qkv_lo + base + (size_t)(row0 + g) * QKVW + h * 64;
    const __nv_bfloat16* Qh1 = Qh0 + 8 * QKVW;
    const __nv_bfloat16* Ql1 = Ql0 + 8 * QKVW;
    uint32_t qh[4][4], ql[4][4];
    #pragma unroll
    for (int kk = 0; kk < 4; kk++) {
        int k0 = kk * 16 + 2 * t;
        #pragma unroll
        for (int fi = 0; fi < 4; fi++) {
            int ko = k0 + (fi >> 1) * 8;
            const __nv_bfloat16* ph = (fi & 1) ? Qh1 : Qh0;
            const __nv_bfloat16* pl = (fi & 1) ? Ql1 : Ql0;
            __nv_bfloat162 vh = *(const __nv_bfloat162*)(ph + ko);
            __nv_bfloat162 vl = *(const __nv_bfloat162*)(pl + ko);
            float a = (__bfloat162float(vh.x) + __bfloat162float(vl.x)) * qsc;
            float c = (__bfloat162float(vh.y) + __bfloat162float(vl.y)) * qsc;
            split2(a, c, qh[kk][fi], ql[kk][fi]);
        }
    }

    // K loader (cp.async) for chunk c into stage s
    auto load_k = [&](int c, int s) {
        int j0 = c * 64;
        uint32_t sb = sbase + (uint32_t)s * 36864u;
        #pragma unroll
        for (int l = 0; l < 2; l++) {
            int idx = tid + l * 256;
            int r = idx >> 3, c8 = idx & 7;
            int j = j0 + r;
            uint32_t d = (uint32_t)(r * 36 + c8 * 4) * 4u;
            int ok = (j < NTOK) ? 16 : 0;
            size_t o = base + (size_t)j * QKVW + DMODEL + h * 64 + c8 * 8;
            CP_ASYNC16(sb + d,         (const char*)g_qkv_hi + o * 2, ok);
            CP_ASYNC16(sb + 9216u + d, (const char*)g_qkv_lo + o * 2, ok);
        }
    };
    int vd0 = (tid >> 4) * 4;
    // V LDG prefetch into registers (4 x uint2 per l-iteration)
    uint2 vr[2][4];     // [l][ahv,bhv,alv,blv]
    auto ldg_v = [&](int c) {
        int j0 = c * 64;
        #pragma unroll
        for (int l = 0; l < 2; l++) {
            int jp = (tid & 15) + 16 * l;
            int j = j0 + 2 * jp;
            uint2 z = make_uint2(0, 0);
            vr[l][0] = z; vr[l][1] = z; vr[l][2] = z; vr[l][3] = z;
            size_t o = base + (size_t)j * QKVW + 2 * DMODEL + h * 64 + vd0;
            if (j < NTOK) {
                vr[l][0] = *(const uint2*)((const char*)g_qkv_hi + o * 2);
                vr[l][2] = *(const uint2*)((const char*)g_qkv_lo + o * 2);
            }
            if (j + 1 < NTOK) {
                vr[l][1] = *(const uint2*)((const char*)g_qkv_hi + (o + QKVW) * 2);
                vr[l][3] = *(const uint2*)((const char*)g_qkv_lo + (o + QKVW) * 2);
            }
        }
    };
    // drain prefetched V registers into stage s
    auto sts_v = [&](int s) {
        uint32_t* VH = sh + s * ATT_STG_U32 + 4608;
        uint32_t* VL = VH + 2304;
        #pragma unroll
        for (int l = 0; l < 2; l++) {
            int jp = (tid & 15) + 16 * l;
            uint2 ahv = vr[l][0], bhv = vr[l][1], alv = vr[l][2], blv = vr[l][3];
            VH[(vd0 + 0) * 36 + jp] = __byte_perm(ahv.x, bhv.x, 0x5410);
            VH[(vd0 + 1) * 36 + jp] = __byte_perm(ahv.x, bhv.x, 0x7632);
            VH[(vd0 + 2) * 36 + jp] = __byte_perm(ahv.y, bhv.y, 0x5410);
            VH[(vd0 + 3) * 36 + jp] = __byte_perm(ahv.y, bhv.y, 0x7632);
            VL[(vd0 + 0) * 36 + jp] = __byte_perm(alv.x, blv.x, 0x5410);
            VL[(vd0 + 1) * 36 + jp] = __byte_perm(alv.x, blv.x, 0x7632);
            VL[(vd0 + 2) * 36 + jp] = __byte_perm(alv.y, blv.y, 0x5410);
            VL[(vd0 + 3) * 36 + jp] = __byte_perm(alv.y, blv.y, 0x7632);
        }
    };

    float O[8][4];
    #pragma unroll
    for (int nj = 0; nj < 8; nj++)
        #pragma unroll
        for (int q = 0; q < 4; q++) O[nj][q] = 0.f;
    float mr0 = -1e30f, mr1 = -1e30f, lr0 = 0.f, lr1 = 0.f;

    load_k(0, 0);
    CP_COMMIT();
    ldg_v(0);

    for (int c = 0; c < 17; c++) {
        int s = c & 1;
        sts_v(s);           // drain V(c) regs (LDG issued one chunk ago)
        CP_WAIT0();         // K(c) landed
        __syncthreads();    // K(c)+V(c) visible to all
        if (c + 1 < 17) {
            load_k(c + 1, s ^ 1);
            CP_COMMIT();
            ldg_v(c + 1);   // V(c+1) LDGs fly during compute below
        }
        const uint32_t* KH = sh + s * ATT_STG_U32;
        const uint32_t* KL = KH + 2304;
        const uint32_t* VH = KH + 4608;
        const uint32_t* VL = KH + 6912;
        int j0 = c * 64;

        // ---- S = Q K^T ----
        float S[8][4];
        #pragma unroll
        for (int nj = 0; nj < 8; nj++)
            #pragma unroll
            for (int q = 0; q < 4; q++) S[nj][q] = 0.f;

        #pragma unroll
        for (int kk = 0; kk < 4; kk++) {
            int kc = kk * 8;
            #pragma unroll
            for (int nj = 0; nj < 8; nj++) {
                int nc = 8 * nj + g;
                uint32_t kb[2], kl[2];
                kb[0] = KH[nc * 36 + kc + t]; kb[1] = KH[nc * 36 + kc + t + 4];
                kl[0] = KL[nc * 36 + kc + t]; kl[1] = KL[nc * 36 + kc + t + 4];
                mma_bf16(S[nj], qh[kk], kb);
                mma_bf16(S[nj], ql[kk], kb);
                mma_bf16(S[nj], qh[kk], kl);
            }
        }

        if (j0 + 64 > NTOK) {
            #pragma unroll
            for (int nj = 0; nj < 8; nj++) {
                int col = j0 + 8 * nj + 2 * t;
                if (col >= NTOK)     { S[nj][0] = -1e30f; S[nj][2] = -1e30f; }
                if (col + 1 >= NTOK) { S[nj][1] = -1e30f; S[nj][3] = -1e30f; }
            }
        }

        // ---- online softmax (log2 domain) ----
        float cm0 = -1e30f, cm1 = -1e30f;
        #pragma unroll
        for (int nj = 0; nj < 8; nj++) {
            cm0 = fmaxf(cm0, fmaxf(S[nj][0], S[nj][1]));
            cm1 = fmaxf(cm1, fmaxf(S[nj][2], S[nj][3]));
        }
        cm0 = fmaxf(cm0, __shfl_xor_sync(0xffffffffu, cm0, 1));
        cm0 = fmaxf(cm0, __shfl_xor_sync(0xffffffffu, cm0, 2));
        cm1 = fmaxf(cm1, __shfl_xor_sync(0xffffffffu, cm1, 1));
        cm1 = fmaxf(cm1, __shfl_xor_sync(0xffffffffu, cm1, 2));
        float mn0 = fmaxf(mr0, cm0), mn1 = fmaxf(mr1, cm1);
        float f0 = exp2f(mr0 - mn0), f1 = exp2f(mr1 - mn1);
        float ps0 = 0.f, ps1 = 0.f;
        #pragma unroll
        for (int nj = 0; nj < 8; nj++) {
            S[nj][0] = exp2f(S[nj][0] - mn0);
            S[nj][1] = exp2f(S[nj][1] - mn0);
            S[nj][2] = exp2f(S[nj][2] - mn1);
            S[nj][3] = exp2f(S[nj][3] - mn1);
            ps0 += S[nj][0] + S[nj][1];
            ps1 += S[nj][2] + S[nj][3];
        }
        ps0 += __shfl_xor_sync(0xffffffffu, ps0, 1);
        ps0 += __shfl_xor_sync(0xffffffffu, ps0, 2);
        ps1 += __shfl_xor_sync(0xffffffffu, ps1, 1);
        ps1 += __shfl_xor_sync(0xffffffffu, ps1, 2);
        lr0 = lr0 * f0 + ps0;
        lr1 = lr1 * f1 + ps1;
        mr0 = mn0; mr1 = mn1;
        #pragma unroll
        for (int nj = 0; nj < 8; nj++) {
            O[nj][0] *= f0; O[nj][1] *= f0;
            O[nj][2] *= f1; O[nj][3] *= f1;
        }

        // ---- O += P @ V ----
        #pragma unroll
        for (int kk = 0; kk < 4; kk++) {
            int j2 = 2 * kk;
            uint32_t ph[4], pl[4];
            split2(S[j2][0],     S[j2][1],     ph[0], pl[0]);
            split2(S[j2][2],     S[j2][3],     ph[1], pl[1]);
            split2(S[j2 + 1][0], S[j2 + 1][1], ph[2], pl[2]);
            split2(S[j2 + 1][2], S[j2 + 1][3], ph[3], pl[3]);
            #pragma unroll
            for (int nj = 0; nj < 8; nj++) {
                int n = 8 * nj + g;
                uint32_t vh[2], vl[2];
                vh[0] = VH[n * 36 + 8 * kk + t]; vh[1] = VH[n * 36 + 8 * kk + t + 4];
                vl[0] = VL[n * 36 + 8 * kk + t]; vl[1] = VL[n * 36 + 8 * kk + t + 4];
                mma_bf16(O[nj], ph, vh);
                mma_bf16(O[nj], pl, vh);
                mma_bf16(O[nj], ph, vl);
            }
        }
    }

    // ---- write out ----
    float i0 = 1.f / lr0, i1 = 1.f / lr1;
    size_t o0 = ((size_t)b * NTOK + row0 + g) * DMODEL + h * 64;
    size_t o1 = o0 + (size_t)8 * DMODEL;
    #pragma unroll
    for (int nj = 0; nj < 8; nj++) {
        int col = 8 * nj + 2 * t;
        uint32_t hp, lp;
        split2(O[nj][0] * i0, O[nj][1] * i0, hp, lp);
        *(uint32_t*)((char*)g_ctx_hi + (o0 + col) * 2) = hp;
        *(uint32_t*)((char*)g_ctx_lo + (o0 + col) * 2) = lp;
        split2(O[nj][2] * i1, O[nj][3] * i1, hp, lp);
        *(uint32_t*)((char*)g_ctx_hi + (o1 + col) * 2) = hp;
        *(uint32_t*)((char*)g_ctx_lo + (o1 + col) * 2) = lp;
    }
}

// ---------------- block reduction helpers ----------------
__device__ __forceinline__ float blockReduceSum(float v, float* red) {
    #pragma unroll
    for (int o = 16; o > 0; o >>= 1) v += __shfl_xor_sync(0xffffffffu, v, o);
    int lane = threadIdx.x & 31, w = threadIdx.x >> 5;
    __syncthreads();
    if (lane == 0) red[w] = v;
    __syncthreads();
    if (threadIdx.x == 0) {
        float s = 0.f;
        #pragma unroll
        for (int i = 0; i < 8; i++) s += red[i];
        red[0] = s;
    }
    __syncthreads();
    return red[0];
}

__device__ __forceinline__ float blockReduceMax(float v, float* red) {
    #pragma unroll
    for (int o = 16; o > 0; o >>= 1) v = fmaxf(v, __shfl_xor_sync(0xffffffffu, v, o));
    int lane = threadIdx.x & 31, w = threadIdx.x >> 5;
    __syncthreads();
    if (lane == 0) red[w] = v;
    __syncthreads();
    if (threadIdx.x == 0) {
        float s = -1e30f;
        #pragma unroll
        for (int i = 0; i < 8; i++) s = fmaxf(s, red[i]);
        red[0] = s;
    }
    __syncthreads();
    return red[0];
}

// ---------------- LayerNorm -> split bf16 hi/lo ----------------
__global__ __launch_bounds__(256) void ln_kernel(const float* __restrict__ x,
                                                 const float* __restrict__ w,
                                                 const float* __restrict__ bias) {
    int row = blockIdx.x;
    const float* xr = x + (size_t)row * DMODEL;
    int t = threadIdx.x;
    float v[3];
    float s = 0.f, sq = 0.f;
    #pragma unroll
    for (int i = 0; i < 3; i++) {
        v[i] = xr[t + i * 256];
        s += v[i];
        sq += v[i] * v[i];
    }
    __shared__ float red[32];
    __shared__ float stats[2];
    #pragma unroll
    for (int o = 16; o > 0; o >>= 1) {
        s  += __shfl_xor_sync(0xffffffffu, s, o);
        sq += __shfl_xor_sync(0xffffffffu, sq, o);
    }
    int lane = t & 31, wp = t >> 5;
    if (lane == 0) { red[wp] = s; red[8 + wp] = sq; }
    __syncthreads();
    if (t == 0) {
        float a = 0.f, b2 = 0.f;
        #pragma unroll
        for (int i = 0; i < 8; i++) { a += red[i]; b2 += red[8 + i]; }
        stats[0] = a; stats[1] = b2;
    }
    __syncthreads();
    float mean = stats[0] * (1.f / DMODEL);
    float var  = stats[1] * (1.f / DMODEL) - mean * mean;
    float inv  = rsqrtf(var + EPS);
    #pragma unroll
    for (int i = 0; i < 3; i++) {
        int c = t + i * 256;
        float o = (v[i] - mean) * inv * w[c] + bias[c];
        __nv_bfloat16 h = __float2bfloat16_rn(o);
        size_t idx = (size_t)row * DMODEL + c;
        g_xn_hi[idx] = h;
        g_xn_lo[idx] = __float2bfloat16_rn(o - __bfloat162float(h));
    }
}

// ---------------- CLS row (query row 0) ----------------
__global__ __launch_bounds__(256) void cls_kernel(const float* __restrict__ canny,
                                                  const float* __restrict__ noise) {
    int bh = blockIdx.x;
    int b = bh / NH, h = bh % NH;
    __shared__ float sm[NTOK];
    __shared__ float q0[64];
    __shared__ float red[32];
    __shared__ float part[4][64];
    int tid = threadIdx.x;
    size_t base = (size_t)b * NTOK * QKVW;

    if (tid < 64)
        q0[tid] = __bfloat162float(g_qkv_hi[base + h * 64 + tid])
                + __bfloat162float(g_qkv_lo[base + h * 64 + tid]);
    __syncthreads();

    for (int j = tid; j < NTOK; j += 256) {
        size_t ko = base + (size_t)j * QKVW + DMODEL + h * 64;
        float dot = 0.f;
        #pragma unroll
        for (int d2 = 0; d2 < 32; d2++) {
            __nv_bfloat162 kh = *(const __nv_bfloat162*)(g_qkv_hi + ko + 2 * d2);
            __nv_bfloat162 kl = *(const __nv_bfloat162*)(g_qkv_lo + ko + 2 * d2);
            dot += q0[2 * d2]     * (__bfloat162float(kh.x) + __bfloat162float(kl.x))
                 + q0[2 * d2 + 1] * (__bfloat162float(kh.y) + __bfloat162float(kl.y));
        }
        sm[j] = dot * SCALE;
    }
    __syncthreads();

    float mx = -1e30f, cs = 0.f, ns = 0.f;
    for (int j = tid; j < NPATCH; j += 256) {
        mx = fmaxf(mx, sm[j + 1]);
        cs += canny[(size_t)b * NPATCH + j] + 1.f;
        ns += noise[(size_t)b * NPATCH + j];
    }
    mx = blockReduceMax(mx, red);
    cs = blockReduceSum(cs, red);
    ns = blockReduceSum(ns, red);
    float se = 0.f;
    for (int j = tid; j < NPATCH; j += 256) se += exp2f((sm[j + 1] - mx) * LOG2E);
    se = blockReduceSum(se, red);
    float inv_se = 1.f / se, inv_cs = 1.f / cs, inv_ns = 1.f / ns;
    for (int j = tid; j < NPATCH; j += 256) {
        float a = exp2f((sm[j + 1] - mx) * LOG2E) * inv_se;
        sm[j + 1] = a + (canny[(size_t)b * NPATCH + j] + 1.f) * inv_cs
                      + noise[(size_t)b * NPATCH + j] * inv_ns;
    }
    __syncthreads();

    float mx2 = -1e30f;
    for (int j = tid; j < NTOK; j += 256) mx2 = fmaxf(mx2, sm[j]);
    mx2 = blockReduceMax(mx2, red);
    float se2 = 0.f;
    for (int j = tid; j < NTOK; j += 256) se2 += exp2f((sm[j] - mx2) * LOG2E);
    se2 = blockReduceSum(se2, red);
    float inv2 = 1.f / se2;
    for (int j = tid; j < NTOK; j += 256) sm[j] = exp2f((sm[j] - mx2) * LOG2E) * inv2;
    __syncthreads();

    int d = tid & 63, qp = tid >> 6;
    float acc = 0.f;
    for (int j = qp; j < NTOK; j += 4) {
        size_t vo = base + (size_t)j * QKVW + 2 * DMODEL + h * 64 + d;
        acc += sm[j] * (__bfloat162float(g_qkv_hi[vo]) + __bfloat162float(g_qkv_lo[vo]));
    }
    part[qp][d] = acc;
    __syncthreads();
    if (tid < 64) {
        float o = part[0][tid] + part[1][tid] + part[2][tid] + part[3][tid];
        __nv_bfloat16 hh = __float2bfloat16_rn(o);
        size_t idx = (size_t)b * NTOK * DMODEL + h * 64 + tid;
        g_ctx_hi[idx] = hh;
        g_ctx_lo[idx] = __float2bfloat16_rn(o - __bfloat162float(hh));
    }
}

// ---------------- launch ----------------
extern "C" void kernel_launch(void* const* d_in, const int* in_sizes, int n_in,
                              void* d_out, int out_size) {
    const float* x     = (const float*)d_in[0];
    const float* canny = (const float*)d_in[1];
    const float* noise = (const float*)d_in[2];
    const float* ln_w  = (const float*)d_in[3];
    const float* ln_b  = (const float*)d_in[4];
    const float* w_qkv = (const float*)d_in[5];
    const float* w_out = (const float*)d_in[6];
    const float* b_out = (const float*)d_in[7];
    float* out = (float*)d_out;

    cudaFuncSetAttribute(gemm_mma<0>, cudaFuncAttributeMaxDynamicSharedMemorySize, GEMM_SMEM);
    cudaFuncSetAttribute(gemm_mma<1>, cudaFuncAttributeMaxDynamicSharedMemorySize, GEMM_SMEM);
    cudaFuncSetAttribute(attn_mma_kernel, cudaFuncAttributeMaxDynamicSharedMemorySize, ATT_SMEM);

    __nv_bfloat16 *wqkvTh, *wqkvTl, *woutTh, *woutTl;
    cudaGetSymbolAddress((void**)&wqkvTh, g_wqkvT_hi);
    cudaGetSymbolAddress((void**)&wqkvTl, g_wqkvT_lo);
    cudaGetSymbolAddress((void**)&woutTh, g_woutT_hi);
    cudaGetSymbolAddress((void**)&woutTl, g_woutT_lo);

    // 1. LayerNorm (-> bf16 hi/lo)
    ln_kernel<<<MTOT, 256>>>(x, ln_w, ln_b);

    // 1b. transpose+split weights
    {
        dim3 g1(QKVW / 32, DMODEL / 32);
        transpose_split_kernel<<<g1, 256>>>(w_qkv, wqkvTh, wqkvTl, DMODEL, QKVW);
        dim3 g2(DMODEL / 32, DMODEL / 32);
        transpose_split_kernel<<<g2, 256>>>(w_out, woutTh, woutTl, DMODEL, DMODEL);
    }

    // 2. QKV GEMM -> g_qkv hi/lo
    {
        dim3 grid(QKVW / 128, (MTOT + 127) / 128);
        gemm_mma<0><<<grid, 256, GEMM_SMEM>>>(wqkvTh, wqkvTl, nullptr, nullptr, MTOT, QKVW, DMODEL);
    }

    // 3. attention rows 1..1024
    {
        dim3 g_attn(8, BATCH * NH);
        attn_mma_kernel<<<g_attn, 256, ATT_SMEM>>>();
    }

    // 4. CLS row with prior injection
    cls_kernel<<<BATCH * NH, 256>>>(canny, noise);

    // 5. output projection -> d_out (fp32 + bias)
    {
        dim3 grid(DMODEL / 128, (MTOT + 127) / 128);
        gemm_mma<1><<<grid, 256, GEMM_SMEM>>>(woutTh, woutTl, b_out, out, MTOT, DMODEL, DMODEL);
    }
}

// round 10
// speedup vs baseline: 1.3600x; 1.1688x over previous
#include <cuda_runtime.h>
#include <cuda_bf16.h>
#include <math.h>
#include <stdint.h>

#define BATCH   8
#define NTOK    1025
#define DMODEL  768
#define NH      12
#define HDIM    64
#define NPATCH  1024
#define QKVW    (3*DMODEL)          // 2304
#define EPS     1e-5f
#define LOG2E   1.4426950408889634f
#define SCALE   0.03608439182435161f   // 768^-0.5
#define MTOT    (BATCH*NTOK)        // 8200

// ---------------- scratch (device globals; no allocation) ----------------
__device__ __nv_bfloat16 g_xn_hi [(size_t)MTOT * DMODEL];
__device__ __nv_bfloat16 g_xn_lo [(size_t)MTOT * DMODEL];
__device__ __nv_bfloat16 g_qkv_hi[(size_t)MTOT * QKVW];
__device__ __nv_bfloat16 g_qkv_lo[(size_t)MTOT * QKVW];
__device__ __nv_bfloat16 g_ctx_hi[(size_t)MTOT * DMODEL];
__device__ __nv_bfloat16 g_ctx_lo[(size_t)MTOT * DMODEL];
__device__ __nv_bfloat16 g_wqkvT_hi[(size_t)QKVW * DMODEL];
__device__ __nv_bfloat16 g_wqkvT_lo[(size_t)QKVW * DMODEL];
__device__ __nv_bfloat16 g_woutT_hi[(size_t)DMODEL * DMODEL];
__device__ __nv_bfloat16 g_woutT_lo[(size_t)DMODEL * DMODEL];

// ---------------- helpers ----------------
__device__ __forceinline__ uint32_t smem_u32(const void* p) {
    uint32_t a;
    asm("{ .reg .u64 t; cvta.to.shared.u64 t, %1; cvt.u32.u64 %0, t; }" : "=r"(a) : "l"(p));
    return a;
}

__device__ __forceinline__ void mma_bf16(float* c, const uint32_t* a, const uint32_t* b) {
    asm volatile(
        "mma.sync.aligned.m16n8k16.row.col.f32.bf16.bf16.f32 "
        "{%0,%1,%2,%3}, {%4,%5,%6,%7}, {%8,%9}, {%0,%1,%2,%3};"
        : "+f"(c[0]), "+f"(c[1]), "+f"(c[2]), "+f"(c[3])
        : "r"(a[0]), "r"(a[1]), "r"(a[2]), "r"(a[3]), "r"(b[0]), "r"(b[1]));
}

__device__ __forceinline__ void ldsm_x4(uint32_t* f, uint32_t addr) {
    asm volatile("ldmatrix.sync.aligned.m8n8.x4.shared.b16 {%0,%1,%2,%3}, [%4];"
        : "=r"(f[0]), "=r"(f[1]), "=r"(f[2]), "=r"(f[3]) : "r"(addr));
}
__device__ __forceinline__ void ldsm_x2(uint32_t* f, uint32_t addr) {
    asm volatile("ldmatrix.sync.aligned.m8n8.x2.shared.b16 {%0,%1}, [%2];"
        : "=r"(f[0]), "=r"(f[1]) : "r"(addr));
}
__device__ __forceinline__ void ldsm_x2_trans(uint32_t* f, uint32_t addr) {
    asm volatile("ldmatrix.sync.aligned.m8n8.x2.trans.shared.b16 {%0,%1}, [%2];"
        : "=r"(f[0]), "=r"(f[1]) : "r"(addr));
}

#define CP_ASYNC16(dst, src, nbytes) \
    asm volatile("cp.async.cg.shared.global [%0], [%1], 16, %2;" \
                 :: "r"(dst), "l"(src), "r"(nbytes))
#define CP_COMMIT() asm volatile("cp.async.commit_group;")
#define CP_WAIT0()  asm volatile("cp.async.wait_group 0;")

// hi/lo bf16 split of two floats -> packed bf16x2 (hi, lo); a in low half
__device__ __forceinline__ void split2(float a, float b, uint32_t& hp, uint32_t& lp) {
    __nv_bfloat16 ha = __float2bfloat16_rn(a), hb = __float2bfloat16_rn(b);
    float ra = a - __bfloat162float(ha), rb = b - __bfloat162float(hb);
    __nv_bfloat16 la = __float2bfloat16_rn(ra), lb = __float2bfloat16_rn(rb);
    hp = (uint32_t)__bfloat16_as_ushort(ha) | ((uint32_t)__bfloat16_as_ushort(hb) << 16);
    lp = (uint32_t)__bfloat16_as_ushort(la) | ((uint32_t)__bfloat16_as_ushort(lb) << 16);
}

// ---------------- weight transpose + split ----------------
__global__ __launch_bounds__(256) void transpose_split_kernel(const float* __restrict__ src,
                                                              __nv_bfloat16* __restrict__ dh,
                                                              __nv_bfloat16* __restrict__ dl,
                                                              int K, int N) {
    __shared__ float t[32][33];
    int nx = blockIdx.x * 32, kx = blockIdx.y * 32;
    int lx = threadIdx.x & 31, ly = threadIdx.x >> 5;
    #pragma unroll
    for (int i = ly; i < 32; i += 8)
        t[i][lx] = src[(size_t)(kx + i) * N + nx + lx];
    __syncthreads();
    #pragma unroll
    for (int i = ly; i < 32; i += 8) {
        float v = t[lx][i];
        __nv_bfloat16 h = __float2bfloat16_rn(v);
        size_t o = (size_t)(nx + i) * K + kx + lx;
        dh[o] = h;
        dl[o] = __float2bfloat16_rn(v - __bfloat162float(h));
    }
}

// ================= tensor-core GEMM (2-stage cp.async, 1 barrier/chunk, 2 CTA/SM) =================
#define SM_STRIDE 20
#define ARR_BYTES (128 * SM_STRIDE * 4)     // 10240
#define STG_BYTES (4 * ARR_BYTES)           // 40960
#define GEMM_SMEM (2 * STG_BYTES)           // 81920

template<int SEL>
__global__ __launch_bounds__(256, 2) void gemm_mma(const __nv_bfloat16* __restrict__ Bh,
                                                   const __nv_bfloat16* __restrict__ Bl,
                                                   const float* __restrict__ bias,
                                                   float* __restrict__ Cext,
                                                   int M, int N, int K) {
    const __nv_bfloat16* Ah = (SEL == 0) ? g_xn_hi : g_ctx_hi;
    const __nv_bfloat16* Al = (SEL == 0) ? g_xn_lo : g_ctx_lo;

    extern __shared__ char smem[];
    uint32_t sbase = smem_u32(smem);

    int tid = threadIdx.x;
    int wid = tid >> 5, lane = tid & 31;
    int g = lane >> 2, t = lane & 3;
    int wm = wid & 1, wn = wid >> 1;
    int m0 = blockIdx.y * 128, n0 = blockIdx.x * 128;
    int mw = wm * 64, nw = wn * 32;

    int rA = (lane & 7) + ((lane >> 3) & 1) * 8;
    int cA = (lane >> 4) * 4;
    uint32_t aoff = (uint32_t)(rA * SM_STRIDE + cA) * 4u;
    int rB = lane & 7;
    int cB = ((lane >> 3) & 1) * 4;
    uint32_t boff = (uint32_t)(rB * SM_STRIDE + cB) * 4u;

    int lr = tid >> 2, lq = tid & 3;

    float acc[4][4][4];
    #pragma unroll
    for (int i = 0; i < 4; i++)
        #pragma unroll
        for (int j = 0; j < 4; j++)
            #pragma unroll
            for (int q = 0; q < 4; q++) acc[i][j][q] = 0.f;

    int nch = K / 32;

    auto load_stage = [&](int ch, int s) {
        int kb = ch * 32;
        uint32_t so = sbase + (uint32_t)s * STG_BYTES;
        #pragma unroll
        for (int l = 0; l < 2; l++) {
            int r = lr + l * 64;
            uint32_t d = (uint32_t)(r * SM_STRIDE + lq * 4) * 4u;
            int okA = (m0 + r < M) ? 16 : 0;
            size_t ao = (size_t)(m0 + r) * K + kb + lq * 8;
            size_t bo = (size_t)(n0 + r) * K + kb + lq * 8;
            CP_ASYNC16(so + d,                 Ah + ao, okA);
            CP_ASYNC16(so + ARR_BYTES + d,     Al + ao, okA);
            CP_ASYNC16(so + 2 * ARR_BYTES + d, Bh + bo, 16);
            CP_ASYNC16(so + 3 * ARR_BYTES + d, Bl + bo, 16);
        }
    };

    load_stage(0, 0);
    CP_COMMIT();

    for (int ch = 0; ch < nch; ch++) {
        int s = ch & 1;
        CP_WAIT0();
        __syncthreads();
        if (ch + 1 < nch) {
            load_stage(ch + 1, s ^ 1);
            CP_COMMIT();
        }

        uint32_t uAH = sbase + (uint32_t)s * STG_BYTES;
        uint32_t uAL = uAH + ARR_BYTES;
        uint32_t uBH = uAH + 2 * ARR_BYTES;
        uint32_t uBL = uAH + 3 * ARR_BYTES;

        uint32_t ah[2][4][4], al[2][4][4], bh[2][4][2], bl[2][4][2];
        #pragma unroll
        for (int kk = 0; kk < 2; kk++) {
            uint32_t kcb = (uint32_t)(kk * 8) * 4u;
            #pragma unroll
            for (int mi = 0; mi < 4; mi++) {
                uint32_t base = (uint32_t)((mw + mi * 16) * SM_STRIDE) * 4u + kcb + aoff;
                ldsm_x4(ah[kk][mi], uAH + base);
                ldsm_x4(al[kk][mi], uAL + base);
            }
            #pragma unroll
            for (int nj = 0; nj < 4; nj++) {
                uint32_t base = (uint32_t)((nw + nj * 8) * SM_STRIDE) * 4u + kcb + boff;
                ldsm_x2(bh[kk][nj], uBH + base);
                ldsm_x2(bl[kk][nj], uBL + base);
            }
        }
        #pragma unroll
        for (int kk = 0; kk < 2; kk++)
            #pragma unroll
            for (int mi = 0; mi < 4; mi++)
                #pragma unroll
                for (int nj = 0; nj < 4; nj++) {
                    mma_bf16(acc[mi][nj], ah[kk][mi], bh[kk][nj]);
                    mma_bf16(acc[mi][nj], al[kk][mi], bh[kk][nj]);
                    mma_bf16(acc[mi][nj], ah[kk][mi], bl[kk][nj]);
                }
    }

    // ---- epilogue ----
    #pragma unroll
    for (int mi = 0; mi < 4; mi++) {
        int r0e = m0 + mw + mi * 16 + g;
        #pragma unroll
        for (int nj = 0; nj < 4; nj++) {
            int col = n0 + nw + nj * 8 + t * 2;
            if (SEL == 0) {
                #pragma unroll
                for (int half = 0; half < 2; half++) {
                    int row = r0e + half * 8;
                    if (row < M) {
                        uint32_t hp, lp;
                        split2(acc[mi][nj][2 * half], acc[mi][nj][2 * half + 1], hp, lp);
                        size_t o = (size_t)row * N + col;
                        *(uint32_t*)((char*)g_qkv_hi + o * 2) = hp;
                        *(uint32_t*)((char*)g_qkv_lo + o * 2) = lp;
                    }
                }
            } else {
                float b0 = bias[col], b1 = bias[col + 1];
                if (r0e < M)
                    *(float2*)(Cext + (size_t)r0e * N + col) =
                        make_float2(acc[mi][nj][0] + b0, acc[mi][nj][1] + b1);
                if (r0e + 8 < M)
                    *(float2*)(Cext + (size_t)(r0e + 8) * N + col) =
                        make_float2(acc[mi][nj][2] + b0, acc[mi][nj][3] + b1);
            }
        }
    }
}

// ================= tensor-core flash attention (rows 1..1024) =================
// grid (8, 96), 256 threads (8 warps x m16), 2 CTA/SM.
// K AND V both plain [key][dim-pair] layout via cp.async double buffer.
// PV B-fragments come from ldmatrix.x2.trans on the [key][dim] V tile.
#define ATT_STG_U32 9216u               // 36864 B / 4 per stage
#define ATT_SMEM    (2 * 36864)

__global__ __launch_bounds__(256, 2) void attn_mma_kernel() {
    extern __shared__ uint32_t sh[];
    int qt = blockIdx.x;
    int bh_ = blockIdx.y;
    int b = bh_ / NH, h = bh_ % NH;

    int tid = threadIdx.x, wid = tid >> 5, lane = tid & 31;
    int g = lane >> 2, t = lane & 3;
    size_t base = (size_t)b * NTOK * QKVW;
    uint32_t sbase = smem_u32(sh);

    // ---- Q fragments ----
    int row0 = 1 + qt * 128 + wid * 16;
    const float qsc = SCALE * LOG2E;
    const __nv_bfloat16* Qh0 = g_qkv_hi + base + (size_t)(row0 + g) * QKVW + h * 64;
    const __nv_bfloat16* Ql0 = g_qkv_lo + base + (size_t)(row0 + g) * QKVW + h * 64;
    const __nv_bfloat16* Qh1 = Qh0 + 8 * QKVW;
    const __nv_bfloat16* Ql1 = Ql0 + 8 * QKVW;
    uint32_t qh[4][4], ql[4][4];
    #pragma unroll
    for (int kk = 0; kk < 4; kk++) {
        int k0 = kk * 16 + 2 * t;
        #pragma unroll
        for (int fi = 0; fi < 4; fi++) {
            int ko = k0 + (fi >> 1) * 8;
            const __nv_bfloat16* ph = (fi & 1) ? Qh1 : Qh0;
            const __nv_bfloat16* pl = (fi & 1) ? Ql1 : Ql0;
            __nv_bfloat162 vh = *(const __nv_bfloat162*)(ph + ko);
            __nv_bfloat162 vl = *(const __nv_bfloat162*)(pl + ko);
            float a = (__bfloat162float(vh.x) + __bfloat162float(vl.x)) * qsc;
            float c = (__bfloat162float(vh.y) + __bfloat162float(vl.y)) * qsc;
            split2(a, c, qh[kk][fi], ql[kk][fi]);
        }
    }

    // K+V loader (cp.async) for chunk c into stage s: all [key][dim-pair], stride 36 u32
    auto load_kv = [&](int c, int s) {
        int j0 = c * 64;
        uint32_t sb = sbase + (uint32_t)s * 36864u;
        #pragma unroll
        for (int l = 0; l < 2; l++) {
            int idx = tid + l * 256;
            int r = idx >> 3, c8 = idx & 7;
            int j = j0 + r;
            uint32_t d = (uint32_t)(r * 36 + c8 * 4) * 4u;
            int ok = (j < NTOK) ? 16 : 0;
            size_t ko = base + (size_t)j * QKVW + DMODEL + h * 64 + c8 * 8;
            size_t vo = ko + DMODEL;
            CP_ASYNC16(sb + d,          (const char*)g_qkv_hi + ko * 2, ok);
            CP_ASYNC16(sb + 9216u + d,  (const char*)g_qkv_lo + ko * 2, ok);
            CP_ASYNC16(sb + 18432u + d, (const char*)g_qkv_hi + vo * 2, ok);
            CP_ASYNC16(sb + 27648u + d, (const char*)g_qkv_lo + vo * 2, ok);
        }
    };

    // ldmatrix.trans per-lane row offset for V fragments (row stride = 144 B)
    int vrow = (lane & 7) + ((lane >> 3) & 1) * 8;
    uint32_t vtoff = (uint32_t)vrow * 144u;

    float O[8][4];
    #pragma unroll
    for (int nj = 0; nj < 8; nj++)
        #pragma unroll
        for (int q = 0; q < 4; q++) O[nj][q] = 0.f;
    float mr0 = -1e30f, mr1 = -1e30f, lr0 = 0.f, lr1 = 0.f;

    load_kv(0, 0);
    CP_COMMIT();

    for (int c = 0; c < 17; c++) {
        int s = c & 1;
        CP_WAIT0();
        __syncthreads();
        if (c + 1 < 17) {
            load_kv(c + 1, s ^ 1);
            CP_COMMIT();
        }
        const uint32_t* KH = sh + s * ATT_STG_U32;
        const uint32_t* KL = KH + 2304;
        uint32_t uVH = sbase + (uint32_t)s * 36864u + 18432u + vtoff;
        uint32_t uVL = uVH + 9216u;
        int j0 = c * 64;

        // ---- S = Q K^T ----
        float S[8][4];
        #pragma unroll
        for (int nj = 0; nj < 8; nj++)
            #pragma unroll
            for (int q = 0; q < 4; q++) S[nj][q] = 0.f;

        #pragma unroll
        for (int kk = 0; kk < 4; kk++) {
            int kc = kk * 8;
            #pragma unroll
            for (int nj = 0; nj < 8; nj++) {
                int nc = 8 * nj + g;
                uint32_t kb[2], kl[2];
                kb[0] = KH[nc * 36 + kc + t]; kb[1] = KH[nc * 36 + kc + t + 4];
                kl[0] = KL[nc * 36 + kc + t]; kl[1] = KL[nc * 36 + kc + t + 4];
                mma_bf16(S[nj], qh[kk], kb);
                mma_bf16(S[nj], ql[kk], kb);
                mma_bf16(S[nj], qh[kk], kl);
            }
        }

        if (j0 + 64 > NTOK) {
            #pragma unroll
            for (int nj = 0; nj < 8; nj++) {
                int col = j0 + 8 * nj + 2 * t;
                if (col >= NTOK)     { S[nj][0] = -1e30f; S[nj][2] = -1e30f; }
                if (col + 1 >= NTOK) { S[nj][1] = -1e30f; S[nj][3] = -1e30f; }
            }
        }

        // ---- online softmax (log2 domain) ----
        float cm0 = -1e30f, cm1 = -1e30f;
        #pragma unroll
        for (int nj = 0; nj < 8; nj++) {
            cm0 = fmaxf(cm0, fmaxf(S[nj][0], S[nj][1]));
            cm1 = fmaxf(cm1, fmaxf(S[nj][2], S[nj][3]));
        }
        cm0 = fmaxf(cm0, __shfl_xor_sync(0xffffffffu, cm0, 1));
        cm0 = fmaxf(cm0, __shfl_xor_sync(0xffffffffu, cm0, 2));
        cm1 = fmaxf(cm1, __shfl_xor_sync(0xffffffffu, cm1, 1));
        cm1 = fmaxf(cm1, __shfl_xor_sync(0xffffffffu, cm1, 2));
        float mn0 = fmaxf(mr0, cm0), mn1 = fmaxf(mr1, cm1);
        float f0 = exp2f(mr0 - mn0), f1 = exp2f(mr1 - mn1);
        float ps0 = 0.f, ps1 = 0.f;
        #pragma unroll
        for (int nj = 0; nj < 8; nj++) {
            S[nj][0] = exp2f(S[nj][0] - mn0);
            S[nj][1] = exp2f(S[nj][1] - mn0);
            S[nj][2] = exp2f(S[nj][2] - mn1);
            S[nj][3] = exp2f(S[nj][3] - mn1);
            ps0 += S[nj][0] + S[nj][1];
            ps1 += S[nj][2] + S[nj][3];
        }
        ps0 += __shfl_xor_sync(0xffffffffu, ps0, 1);
        ps0 += __shfl_xor_sync(0xffffffffu, ps0, 2);
        ps1 += __shfl_xor_sync(0xffffffffu, ps1, 1);
        ps1 += __shfl_xor_sync(0xffffffffu, ps1, 2);
        lr0 = lr0 * f0 + ps0;
        lr1 = lr1 * f1 + ps1;
        mr0 = mn0; mr1 = mn1;
        #pragma unroll
        for (int nj = 0; nj < 8; nj++) {
            O[nj][0] *= f0; O[nj][1] *= f0;
            O[nj][2] *= f1; O[nj][3] *= f1;
        }

        // ---- O += P @ V (B fragments via ldmatrix.trans on [key][dim] tile) ----
        #pragma unroll
        for (int kk = 0; kk < 4; kk++) {
            int j2 = 2 * kk;
            uint32_t ph[4], pl[4];
            split2(S[j2][0],     S[j2][1],     ph[0], pl[0]);
            split2(S[j2][2],     S[j2][3],     ph[1], pl[1]);
            split2(S[j2 + 1][0], S[j2 + 1][1], ph[2], pl[2]);
            split2(S[j2 + 1][2], S[j2 + 1][3], ph[3], pl[3]);
            uint32_t kbase = (uint32_t)(kk * 16) * 144u;
            #pragma unroll
            for (int nj = 0; nj < 8; nj++) {
                uint32_t coff = kbase + (uint32_t)nj * 16u;
                uint32_t vh[2], vl[2];
                ldsm_x2_trans(vh, uVH + coff);
                ldsm_x2_trans(vl, uVL + coff);
                mma_bf16(O[nj], ph, vh);
                mma_bf16(O[nj], pl, vh);
                mma_bf16(O[nj], ph, vl);
            }
        }
    }

    // ---- write out ----
    float i0 = 1.f / lr0, i1 = 1.f / lr1;
    size_t o0 = ((size_t)b * NTOK + row0 + g) * DMODEL + h * 64;
    size_t o1 = o0 + (size_t)8 * DMODEL;
    #pragma unroll
    for (int nj = 0; nj < 8; nj++) {
        int col = 8 * nj + 2 * t;
        uint32_t hp, lp;
        split2(O[nj][0] * i0, O[nj][1] * i0, hp, lp);
        *(uint32_t*)((char*)g_ctx_hi + (o0 + col) * 2) = hp;
        *(uint32_t*)((char*)g_ctx_lo + (o0 + col) * 2) = lp;
        split2(O[nj][2] * i1, O[nj][3] * i1, hp, lp);
        *(uint32_t*)((char*)g_ctx_hi + (o1 + col) * 2) = hp;
        *(uint32_t*)((char*)g_ctx_lo + (o1 + col) * 2) = lp;
    }
}

// ---------------- block reduction helpers ----------------
__device__ __forceinline__ float blockReduceSum(float v, float* red) {
    #pragma unroll
    for (int o = 16; o > 0; o >>= 1) v += __shfl_xor_sync(0xffffffffu, v, o);
    int lane = threadIdx.x & 31, w = threadIdx.x >> 5;
    __syncthreads();
    if (lane == 0) red[w] = v;
    __syncthreads();
    if (threadIdx.x == 0) {
        float s = 0.f;
        #pragma unroll
        for (int i = 0; i < 8; i++) s += red[i];
        red[0] = s;
    }
    __syncthreads();
    return red[0];
}

__device__ __forceinline__ float blockReduceMax(float v, float* red) {
    #pragma unroll
    for (int o = 16; o > 0; o >>= 1) v = fmaxf(v, __shfl_xor_sync(0xffffffffu, v, o));
    int lane = threadIdx.x & 31, w = threadIdx.x >> 5;
    __syncthreads();
    if (lane == 0) red[w] = v;
    __syncthreads();
    if (threadIdx.x == 0) {
        float s = -1e30f;
        #pragma unroll
        for (int i = 0; i < 8; i++) s = fmaxf(s, red[i]);
        red[0] = s;
    }
    __syncthreads();
    return red[0];
}

// ---------------- LayerNorm -> split bf16 hi/lo ----------------
__global__ __launch_bounds__(256) void ln_kernel(const float* __restrict__ x,
                                                 const float* __restrict__ w,
                                                 const float* __restrict__ bias) {
    int row = blockIdx.x;
    const float* xr = x + (size_t)row * DMODEL;
    int t = threadIdx.x;
    float v[3];
    float s = 0.f, sq = 0.f;
    #pragma unroll
    for (int i = 0; i < 3; i++) {
        v[i] = xr[t + i * 256];
        s += v[i];
        sq += v[i] * v[i];
    }
    __shared__ float red[32];
    __shared__ float stats[2];
    #pragma unroll
    for (int o = 16; o > 0; o >>= 1) {
        s  += __shfl_xor_sync(0xffffffffu, s, o);
        sq += __shfl_xor_sync(0xffffffffu, sq, o);
    }
    int lane = t & 31, wp = t >> 5;
    if (lane == 0) { red[wp] = s; red[8 + wp] = sq; }
    __syncthreads();
    if (t == 0) {
        float a = 0.f, b2 = 0.f;
        #pragma unroll
        for (int i = 0; i < 8; i++) { a += red[i]; b2 += red[8 + i]; }
        stats[0] = a; stats[1] = b2;
    }
    __syncthreads();
    float mean = stats[0] * (1.f / DMODEL);
    float var  = stats[1] * (1.f / DMODEL) - mean * mean;
    float inv  = rsqrtf(var + EPS);
    #pragma unroll
    for (int i = 0; i < 3; i++) {
        int c = t + i * 256;
        float o = (v[i] - mean) * inv * w[c] + bias[c];
        __nv_bfloat16 h = __float2bfloat16_rn(o);
        size_t idx = (size_t)row * DMODEL + c;
        g_xn_hi[idx] = h;
        g_xn_lo[idx] = __float2bfloat16_rn(o - __bfloat162float(h));
    }
}

// ---------------- CLS row (query row 0) ----------------
__global__ __launch_bounds__(256) void cls_kernel(const float* __restrict__ canny,
                                                  const float* __restrict__ noise) {
    int bh = blockIdx.x;
    int b = bh / NH, h = bh % NH;
    __shared__ float sm[NTOK];
    __shared__ float q0[64];
    __shared__ float red[32];
    __shared__ float part[4][64];
    int tid = threadIdx.x;
    size_t base = (size_t)b * NTOK * QKVW;

    if (tid < 64)
        q0[tid] = __bfloat162float(g_qkv_hi[base + h * 64 + tid])
                + __bfloat162float(g_qkv_lo[base + h * 64 + tid]);
    __syncthreads();

    for (int j = tid; j < NTOK; j += 256) {
        size_t ko = base + (size_t)j * QKVW + DMODEL + h * 64;
        float dot = 0.f;
        #pragma unroll
        for (int d2 = 0; d2 < 32; d2++) {
            __nv_bfloat162 kh = *(const __nv_bfloat162*)(g_qkv_hi + ko + 2 * d2);
            __nv_bfloat162 kl = *(const __nv_bfloat162*)(g_qkv_lo + ko + 2 * d2);
            dot += q0[2 * d2]     * (__bfloat162float(kh.x) + __bfloat162float(kl.x))
                 + q0[2 * d2 + 1] * (__bfloat162float(kh.y) + __bfloat162float(kl.y));
        }
        sm[j] = dot * SCALE;
    }
    __syncthreads();

    float mx = -1e30f, cs = 0.f, ns = 0.f;
    for (int j = tid; j < NPATCH; j += 256) {
        mx = fmaxf(mx, sm[j + 1]);
        cs += canny[(size_t)b * NPATCH + j] + 1.f;
        ns += noise[(size_t)b * NPATCH + j];
    }
    mx = blockReduceMax(mx, red);
    cs = blockReduceSum(cs, red);
    ns = blockReduceSum(ns, red);
    float se = 0.f;
    for (int j = tid; j < NPATCH; j += 256) se += exp2f((sm[j + 1] - mx) * LOG2E);
    se = blockReduceSum(se, red);
    float inv_se = 1.f / se, inv_cs = 1.f / cs, inv_ns = 1.f / ns;
    for (int j = tid; j < NPATCH; j += 256) {
        float a = exp2f((sm[j + 1] - mx) * LOG2E) * inv_se;
        sm[j + 1] = a + (canny[(size_t)b * NPATCH + j] + 1.f) * inv_cs
                      + noise[(size_t)b * NPATCH + j] * inv_ns;
    }
    __syncthreads();

    float mx2 = -1e30f;
    for (int j = tid; j < NTOK; j += 256) mx2 = fmaxf(mx2, sm[j]);
    mx2 = blockReduceMax(mx2, red);
    float se2 = 0.f;
    for (int j = tid; j < NTOK; j += 256) se2 += exp2f((sm[j] - mx2) * LOG2E);
    se2 = blockReduceSum(se2, red);
    float inv2 = 1.f / se2;
    for (int j = tid; j < NTOK; j += 256) sm[j] = exp2f((sm[j] - mx2) * LOG2E) * inv2;
    __syncthreads();

    int d = tid & 63, qp = tid >> 6;
    float acc = 0.f;
    for (int j = qp; j < NTOK; j += 4) {
        size_t vo = base + (size_t)j * QKVW + 2 * DMODEL + h * 64 + d;
        acc += sm[j] * (__bfloat162float(g_qkv_hi[vo]) + __bfloat162float(g_qkv_lo[vo]));
    }
    part[qp][d] = acc;
    __syncthreads();
    if (tid < 64) {
        float o = part[0][tid] + part[1][tid] + part[2][tid] + part[3][tid];
        __nv_bfloat16 hh = __float2bfloat16_rn(o);
        size_t idx = (size_t)b * NTOK * DMODEL + h * 64 + tid;
        g_ctx_hi[idx] = hh;
        g_ctx_lo[idx] = __float2bfloat16_rn(o - __bfloat162float(hh));
    }
}

// ---------------- launch ----------------
extern "C" void kernel_launch(void* const* d_in, const int* in_sizes, int n_in,
                              void* d_out, int out_size) {
    const float* x     = (const float*)d_in[0];
    const float* canny = (const float*)d_in[1];
    const float* noise = (const float*)d_in[2];
    const float* ln_w  = (const float*)d_in[3];
    const float* ln_b  = (const float*)d_in[4];
    const float* w_qkv = (const float*)d_in[5];
    const float* w_out = (const float*)d_in[6];
    const float* b_out = (const float*)d_in[7];
    float* out = (float*)d_out;

    cudaFuncSetAttribute(gemm_mma<0>, cudaFuncAttributeMaxDynamicSharedMemorySize, GEMM_SMEM);
    cudaFuncSetAttribute(gemm_mma<1>, cudaFuncAttributeMaxDynamicSharedMemorySize, GEMM_SMEM);
    cudaFuncSetAttribute(attn_mma_kernel, cudaFuncAttributeMaxDynamicSharedMemorySize, ATT_SMEM / 2 * 2);
    cudaFuncSetAttribute(attn_mma_kernel, cudaFuncAttributeMaxDynamicSharedMemorySize, 2 * 36864);

    __nv_bfloat16 *wqkvTh, *wqkvTl, *woutTh, *woutTl;
    cudaGetSymbolAddress((void**)&wqkvTh, g_wqkvT_hi);
    cudaGetSymbolAddress((void**)&wqkvTl, g_wqkvT_lo);
    cudaGetSymbolAddress((void**)&woutTh, g_woutT_hi);
    cudaGetSymbolAddress((void**)&woutTl, g_woutT_lo);

    // 1. LayerNorm (-> bf16 hi/lo)
    ln_kernel<<<MTOT, 256>>>(x, ln_w, ln_b);

    // 1b. transpose+split weights
    {
        dim3 g1(QKVW / 32, DMODEL / 32);
        transpose_split_kernel<<<g1, 256>>>(w_qkv, wqkvTh, wqkvTl, DMODEL, QKVW);
        dim3 g2(DMODEL / 32, DMODEL / 32);
        transpose_split_kernel<<<g2, 256>>>(w_out, woutTh, woutTl, DMODEL, DMODEL);
    }

    // 2. QKV GEMM -> g_qkv hi/lo
    {
        dim3 grid(QKVW / 128, (MTOT + 127) / 128);
        gemm_mma<0><<<grid, 256, GEMM_SMEM>>>(wqkvTh, wqkvTl, nullptr, nullptr, MTOT, QKVW, DMODEL);
    }

    // 3. attention rows 1..1024 (2 CTA/SM)
    {
        dim3 g_attn(8, BATCH * NH);
        attn_mma_kernel<<<g_attn, 256, 2 * 36864>>>();
    }

    // 4. CLS row with prior injection
    cls_kernel<<<BATCH * NH, 256>>>(canny, noise);

    // 5. output projection -> d_out (fp32 + bias)
    {
        dim3 grid(DMODEL / 128, (MTOT + 127) / 128);
        gemm_mma<1><<<grid, 256, GEMM_SMEM>>>(woutTh, woutTl, b_out, out, MTOT, DMODEL, DMODEL);
    }
}

// round 11
// speedup vs baseline: 1.7870x; 1.3139x over previous
#include <cuda_runtime.h>
#include <cuda_fp16.h>
#include <math.h>
#include <stdint.h>

#define BATCH   8
#define NTOK    1025
#define DMODEL  768
#define NH      12
#define HDIM    64
#define NPATCH  1024
#define QKVW    (3*DMODEL)          // 2304
#define EPS     1e-5f
#define LOG2E   1.4426950408889634f
#define SCALE   0.03608439182435161f   // 768^-0.5
#define MTOT    (BATCH*NTOK)        // 8200

// ---------------- scratch (device globals; no allocation) ----------------
__device__ __half g_xn_hi [(size_t)MTOT * DMODEL];
__device__ __half g_xn_lo [(size_t)MTOT * DMODEL];
__device__ __half g_qkv_hi[(size_t)MTOT * QKVW];
__device__ __half g_qkv_lo[(size_t)MTOT * QKVW];
__device__ __half g_ctx_hi[(size_t)MTOT * DMODEL];
__device__ __half g_ctx_lo[(size_t)MTOT * DMODEL];
__device__ __half g_wqkvT [(size_t)QKVW * DMODEL];
__device__ __half g_woutT [(size_t)DMODEL * DMODEL];

// ---------------- helpers ----------------
__device__ __forceinline__ uint32_t smem_u32(const void* p) {
    uint32_t a;
    asm("{ .reg .u64 t; cvta.to.shared.u64 t, %1; cvt.u32.u64 %0, t; }" : "=r"(a) : "l"(p));
    return a;
}

__device__ __forceinline__ void mma_f16(float* c, const uint32_t* a, const uint32_t* b) {
    asm volatile(
        "mma.sync.aligned.m16n8k16.row.col.f32.f16.f16.f32 "
        "{%0,%1,%2,%3}, {%4,%5,%6,%7}, {%8,%9}, {%0,%1,%2,%3};"
        : "+f"(c[0]), "+f"(c[1]), "+f"(c[2]), "+f"(c[3])
        : "r"(a[0]), "r"(a[1]), "r"(a[2]), "r"(a[3]), "r"(b[0]), "r"(b[1]));
}

__device__ __forceinline__ void ldsm_x4(uint32_t* f, uint32_t addr) {
    asm volatile("ldmatrix.sync.aligned.m8n8.x4.shared.b16 {%0,%1,%2,%3}, [%4];"
        : "=r"(f[0]), "=r"(f[1]), "=r"(f[2]), "=r"(f[3]) : "r"(addr));
}
__device__ __forceinline__ void ldsm_x2(uint32_t* f, uint32_t addr) {
    asm volatile("ldmatrix.sync.aligned.m8n8.x2.shared.b16 {%0,%1}, [%2];"
        : "=r"(f[0]), "=r"(f[1]) : "r"(addr));
}
__device__ __forceinline__ void ldsm_x2_trans(uint32_t* f, uint32_t addr) {
    asm volatile("ldmatrix.sync.aligned.m8n8.x2.trans.shared.b16 {%0,%1}, [%2];"
        : "=r"(f[0]), "=r"(f[1]) : "r"(addr));
}

#define CP_ASYNC16(dst, src, nbytes) \
    asm volatile("cp.async.cg.shared.global [%0], [%1], 16, %2;" \
                 :: "r"(dst), "l"(src), "r"(nbytes))
#define CP_COMMIT() asm volatile("cp.async.commit_group;")
#define CP_WAIT0()  asm volatile("cp.async.wait_group 0;")

// hi/lo fp16 split of two floats -> packed half2 (hi, lo); a in low half
__device__ __forceinline__ void split2h(float a, float b, uint32_t& hp, uint32_t& lp) {
    __half ha = __float2half_rn(a), hb = __float2half_rn(b);
    float ra = a - __half2float(ha), rb = b - __half2float(hb);
    __half la = __float2half_rn(ra), lb = __float2half_rn(rb);
    hp = (uint32_t)__half_as_ushort(ha) | ((uint32_t)__half_as_ushort(hb) << 16);
    lp = (uint32_t)__half_as_ushort(la) | ((uint32_t)__half_as_ushort(lb) << 16);
}

// ---------------- weight transpose (fp16 hi only): dst[N,K] = fp16(src[K,N]) ----------------
__global__ __launch_bounds__(256) void transpose_h_kernel(const float* __restrict__ src,
                                                          __half* __restrict__ dh,
                                                          int K, int N) {
    __shared__ float t[32][33];
    int nx = blockIdx.x * 32, kx = blockIdx.y * 32;
    int lx = threadIdx.x & 31, ly = threadIdx.x >> 5;
    #pragma unroll
    for (int i = ly; i < 32; i += 8)
        t[i][lx] = src[(size_t)(kx + i) * N + nx + lx];
    __syncthreads();
    #pragma unroll
    for (int i = ly; i < 32; i += 8)
        dh[(size_t)(nx + i) * K + kx + lx] = __float2half_rn(t[lx][i]);
}

// ================= tensor-core GEMM (fp16 2-pass, 2-stage cp.async, 2 CTA/SM) =================
// C = (Ah+Al) @ Bh^T : A 22-bit effective, B 11-bit.
#define SM_STRIDE 20
#define ARR_BYTES (128 * SM_STRIDE * 4)     // 10240
#define STG_BYTES (3 * ARR_BYTES)           // 30720
#define GEMM_SMEM (2 * STG_BYTES)           // 61440

template<int SEL>
__global__ __launch_bounds__(256, 2) void gemm_mma(const __half* __restrict__ Bh,
                                                   const float* __restrict__ bias,
                                                   float* __restrict__ Cext,
                                                   int M, int N, int K) {
    const __half* Ah = (SEL == 0) ? g_xn_hi : g_ctx_hi;
    const __half* Al = (SEL == 0) ? g_xn_lo : g_ctx_lo;

    extern __shared__ char smem[];
    uint32_t sbase = smem_u32(smem);

    int tid = threadIdx.x;
    int wid = tid >> 5, lane = tid & 31;
    int g = lane >> 2, t = lane & 3;
    int wm = wid & 1, wn = wid >> 1;
    int m0 = blockIdx.y * 128, n0 = blockIdx.x * 128;
    int mw = wm * 64, nw = wn * 32;

    int rA = (lane & 7) + ((lane >> 3) & 1) * 8;
    int cA = (lane >> 4) * 4;
    uint32_t aoff = (uint32_t)(rA * SM_STRIDE + cA) * 4u;
    int rB = lane & 7;
    int cB = ((lane >> 3) & 1) * 4;
    uint32_t boff = (uint32_t)(rB * SM_STRIDE + cB) * 4u;

    int lr = tid >> 2, lq = tid & 3;

    float acc[4][4][4];
    #pragma unroll
    for (int i = 0; i < 4; i++)
        #pragma unroll
        for (int j = 0; j < 4; j++)
            #pragma unroll
            for (int q = 0; q < 4; q++) acc[i][j][q] = 0.f;

    int nch = K / 32;

    auto load_stage = [&](int ch, int s) {
        int kb = ch * 32;
        uint32_t so = sbase + (uint32_t)s * STG_BYTES;
        #pragma unroll
        for (int l = 0; l < 2; l++) {
            int r = lr + l * 64;
            uint32_t d = (uint32_t)(r * SM_STRIDE + lq * 4) * 4u;
            int okA = (m0 + r < M) ? 16 : 0;
            size_t ao = (size_t)(m0 + r) * K + kb + lq * 8;
            size_t bo = (size_t)(n0 + r) * K + kb + lq * 8;
            CP_ASYNC16(so + d,                 Ah + ao, okA);
            CP_ASYNC16(so + ARR_BYTES + d,     Al + ao, okA);
            CP_ASYNC16(so + 2 * ARR_BYTES + d, Bh + bo, 16);
        }
    };

    load_stage(0, 0);
    CP_COMMIT();

    for (int ch = 0; ch < nch; ch++) {
        int s = ch & 1;
        CP_WAIT0();
        __syncthreads();
        if (ch + 1 < nch) {
            load_stage(ch + 1, s ^ 1);
            CP_COMMIT();
        }

        uint32_t uAH = sbase + (uint32_t)s * STG_BYTES;
        uint32_t uAL = uAH + ARR_BYTES;
        uint32_t uBH = uAH + 2 * ARR_BYTES;

        uint32_t ah[2][4][4], al[2][4][4], bh[2][4][2];
        #pragma unroll
        for (int kk = 0; kk < 2; kk++) {
            uint32_t kcb = (uint32_t)(kk * 8) * 4u;
            #pragma unroll
            for (int mi = 0; mi < 4; mi++) {
                uint32_t base = (uint32_t)((mw + mi * 16) * SM_STRIDE) * 4u + kcb + aoff;
                ldsm_x4(ah[kk][mi], uAH + base);
                ldsm_x4(al[kk][mi], uAL + base);
            }
            #pragma unroll
            for (int nj = 0; nj < 4; nj++) {
                uint32_t base = (uint32_t)((nw + nj * 8) * SM_STRIDE) * 4u + kcb + boff;
                ldsm_x2(bh[kk][nj], uBH + base);
            }
        }
        #pragma unroll
        for (int kk = 0; kk < 2; kk++)
            #pragma unroll
            for (int mi = 0; mi < 4; mi++)
                #pragma unroll
                for (int nj = 0; nj < 4; nj++) {
                    mma_f16(acc[mi][nj], ah[kk][mi], bh[kk][nj]);
                    mma_f16(acc[mi][nj], al[kk][mi], bh[kk][nj]);
                }
    }

    // ---- epilogue ----
    #pragma unroll
    for (int mi = 0; mi < 4; mi++) {
        int r0e = m0 + mw + mi * 16 + g;
        #pragma unroll
        for (int nj = 0; nj < 4; nj++) {
            int col = n0 + nw + nj * 8 + t * 2;
            if (SEL == 0) {
                #pragma unroll
                for (int half = 0; half < 2; half++) {
                    int row = r0e + half * 8;
                    if (row < M) {
                        uint32_t hp, lp;
                        split2h(acc[mi][nj][2 * half], acc[mi][nj][2 * half + 1], hp, lp);
                        size_t o = (size_t)row * N + col;
                        *(uint32_t*)((char*)g_qkv_hi + o * 2) = hp;
                        *(uint32_t*)((char*)g_qkv_lo + o * 2) = lp;
                    }
                }
            } else {
                float b0 = bias[col], b1 = bias[col + 1];
                if (r0e < M)
                    *(float2*)(Cext + (size_t)r0e * N + col) =
                        make_float2(acc[mi][nj][0] + b0, acc[mi][nj][1] + b1);
                if (r0e + 8 < M)
                    *(float2*)(Cext + (size_t)(r0e + 8) * N + col) =
                        make_float2(acc[mi][nj][2] + b0, acc[mi][nj][3] + b1);
            }
        }
    }
}

// ================= tensor-core flash attention (rows 1..1024), fp16 2-pass =================
// grid (8, 96), 256 threads (8 warps x m16), 2 CTA/SM.
// K, V stored hi-only [key][dim-pair] via cp.async double buffer (stride 36 u32).
// Q and P carry 22-bit hi/lo. QK B-frags via ldsm_x2; PV B-frags via ldsm_x2.trans.
#define ATT_STG_BYTES 18432u
#define ATT_SMEM      (2 * 18432)

__global__ __launch_bounds__(256, 2) void attn_mma_kernel() {
    extern __shared__ uint32_t sh[];
    int qt = blockIdx.x;
    int bh_ = blockIdx.y;
    int b = bh_ / NH, h = bh_ % NH;

    int tid = threadIdx.x, wid = tid >> 5, lane = tid & 31;
    int g = lane >> 2, t = lane & 3;
    size_t base = (size_t)b * NTOK * QKVW;
    uint32_t sbase = smem_u32(sh);

    // ---- Q fragments: reconstruct fp32 from hi/lo, scale, re-split ----
    int row0 = 1 + qt * 128 + wid * 16;
    const float qsc = SCALE * LOG2E;
    const __half* Qh0 = g_qkv_hi + base + (size_t)(row0 + g) * QKVW + h * 64;
    const __half* Ql0 = g_qkv_lo + base + (size_t)(row0 + g) * QKVW + h * 64;
    const __half* Qh1 = Qh0 + 8 * QKVW;
    const __half* Ql1 = Ql0 + 8 * QKVW;
    uint32_t qh[4][4], ql[4][4];
    #pragma unroll
    for (int kk = 0; kk < 4; kk++) {
        int k0 = kk * 16 + 2 * t;
        #pragma unroll
        for (int fi = 0; fi < 4; fi++) {
            int ko = k0 + (fi >> 1) * 8;
            const __half* ph = (fi & 1) ? Qh1 : Qh0;
            const __half* pl = (fi & 1) ? Ql1 : Ql0;
            __half2 vh = *(const __half2*)(ph + ko);
            __half2 vl = *(const __half2*)(pl + ko);
            float a = (__half2float(vh.x) + __half2float(vl.x)) * qsc;
            float c = (__half2float(vh.y) + __half2float(vl.y)) * qsc;
            split2h(a, c, qh[kk][fi], ql[kk][fi]);
        }
    }

    // K+V loader (cp.async, hi only)
    auto load_kv = [&](int c, int s) {
        int j0 = c * 64;
        uint32_t sb = sbase + (uint32_t)s * ATT_STG_BYTES;
        #pragma unroll
        for (int l = 0; l < 2; l++) {
            int idx = tid + l * 256;
            int r = idx >> 3, c8 = idx & 7;
            int j = j0 + r;
            uint32_t d = (uint32_t)(r * 36 + c8 * 4) * 4u;
            int ok = (j < NTOK) ? 16 : 0;
            size_t ko = base + (size_t)j * QKVW + DMODEL + h * 64 + c8 * 8;
            size_t vo = ko + DMODEL;
            CP_ASYNC16(sb + d,         (const char*)g_qkv_hi + ko * 2, ok);
            CP_ASYNC16(sb + 9216u + d, (const char*)g_qkv_hi + vo * 2, ok);
        }
    };

    // per-lane ldsm offsets
    int kfr = lane & 7, kfc = ((lane >> 3) & 1) * 4;
    uint32_t kfoff = (uint32_t)(kfr * 36 + kfc) * 4u;
    int vrow = (lane & 7) + ((lane >> 3) & 1) * 8;
    uint32_t vtoff = (uint32_t)vrow * 144u;

    float O[8][4];
    #pragma unroll
    for (int nj = 0; nj < 8; nj++)
        #pragma unroll
        for (int q = 0; q < 4; q++) O[nj][q] = 0.f;
    float mr0 = -1e30f, mr1 = -1e30f, lr0 = 0.f, lr1 = 0.f;

    load_kv(0, 0);
    CP_COMMIT();

    for (int c = 0; c < 17; c++) {
        int s = c & 1;
        CP_WAIT0();
        __syncthreads();
        if (c + 1 < 17) {
            load_kv(c + 1, s ^ 1);
            CP_COMMIT();
        }
        uint32_t uKH = sbase + (uint32_t)s * ATT_STG_BYTES;
        uint32_t uVH = uKH + 9216u + vtoff;
        int j0 = c * 64;

        // ---- S = Q K^T (2-pass: qh, ql vs Kh) ----
        float S[8][4];
        #pragma unroll
        for (int nj = 0; nj < 8; nj++)
            #pragma unroll
            for (int q = 0; q < 4; q++) S[nj][q] = 0.f;

        #pragma unroll
        for (int kk = 0; kk < 4; kk++) {
            uint32_t kcb = (uint32_t)(kk * 8) * 4u;
            #pragma unroll
            for (int nj = 0; nj < 8; nj++) {
                uint32_t kb[2];
                ldsm_x2(kb, uKH + (uint32_t)(nj * 8 * 36) * 4u + kcb + kfoff);
                mma_f16(S[nj], qh[kk], kb);
                mma_f16(S[nj], ql[kk], kb);
            }
        }

        if (j0 + 64 > NTOK) {
            #pragma unroll
            for (int nj = 0; nj < 8; nj++) {
                int col = j0 + 8 * nj + 2 * t;
                if (col >= NTOK)     { S[nj][0] = -1e30f; S[nj][2] = -1e30f; }
                if (col + 1 >= NTOK) { S[nj][1] = -1e30f; S[nj][3] = -1e30f; }
            }
        }

        // ---- online softmax (log2 domain) ----
        float cm0 = -1e30f, cm1 = -1e30f;
        #pragma unroll
        for (int nj = 0; nj < 8; nj++) {
            cm0 = fmaxf(cm0, fmaxf(S[nj][0], S[nj][1]));
            cm1 = fmaxf(cm1, fmaxf(S[nj][2], S[nj][3]));
        }
        cm0 = fmaxf(cm0, __shfl_xor_sync(0xffffffffu, cm0, 1));
        cm0 = fmaxf(cm0, __shfl_xor_sync(0xffffffffu, cm0, 2));
        cm1 = fmaxf(cm1, __shfl_xor_sync(0xffffffffu, cm1, 1));
        cm1 = fmaxf(cm1, __shfl_xor_sync(0xffffffffu, cm1, 2));
        float mn0 = fmaxf(mr0, cm0), mn1 = fmaxf(mr1, cm1);
        float f0 = exp2f(mr0 - mn0), f1 = exp2f(mr1 - mn1);
        float ps0 = 0.f, ps1 = 0.f;
        #pragma unroll
        for (int nj = 0; nj < 8; nj++) {
            S[nj][0] = exp2f(S[nj][0] - mn0);
            S[nj][1] = exp2f(S[nj][1] - mn0);
            S[nj][2] = exp2f(S[nj][2] - mn1);
            S[nj][3] = exp2f(S[nj][3] - mn1);
            ps0 += S[nj][0] + S[nj][1];
            ps1 += S[nj][2] + S[nj][3];
        }
        ps0 += __shfl_xor_sync(0xffffffffu, ps0, 1);
        ps0 += __shfl_xor_sync(0xffffffffu, ps0, 2);
        ps1 += __shfl_xor_sync(0xffffffffu, ps1, 1);
        ps1 += __shfl_xor_sync(0xffffffffu, ps1, 2);
        lr0 = lr0 * f0 + ps0;
        lr1 = lr1 * f1 + ps1;
        mr0 = mn0; mr1 = mn1;
        #pragma unroll
        for (int nj = 0; nj < 8; nj++) {
            O[nj][0] *= f0; O[nj][1] *= f0;
            O[nj][2] *= f1; O[nj][3] *= f1;
        }

        // ---- O += P @ V (P hi/lo 2-pass vs Vh) ----
        #pragma unroll
        for (int kk = 0; kk < 4; kk++) {
            int j2 = 2 * kk;
            uint32_t ph[4], pl[4];
            split2h(S[j2][0],     S[j2][1],     ph[0], pl[0]);
            split2h(S[j2][2],     S[j2][3],     ph[1], pl[1]);
            split2h(S[j2 + 1][0], S[j2 + 1][1], ph[2], pl[2]);
            split2h(S[j2 + 1][2], S[j2 + 1][3], ph[3], pl[3]);
            uint32_t kbase = (uint32_t)(kk * 16) * 144u;
            #pragma unroll
            for (int nj = 0; nj < 8; nj++) {
                uint32_t vh[2];
                ldsm_x2_trans(vh, uVH + kbase + (uint32_t)nj * 16u);
                mma_f16(O[nj], ph, vh);
                mma_f16(O[nj], pl, vh);
            }
        }
    }

    // ---- write out (split to g_ctx hi/lo) ----
    float i0 = 1.f / lr0, i1 = 1.f / lr1;
    size_t o0 = ((size_t)b * NTOK + row0 + g) * DMODEL + h * 64;
    size_t o1 = o0 + (size_t)8 * DMODEL;
    #pragma unroll
    for (int nj = 0; nj < 8; nj++) {
        int col = 8 * nj + 2 * t;
        uint32_t hp, lp;
        split2h(O[nj][0] * i0, O[nj][1] * i0, hp, lp);
        *(uint32_t*)((char*)g_ctx_hi + (o0 + col) * 2) = hp;
        *(uint32_t*)((char*)g_ctx_lo + (o0 + col) * 2) = lp;
        split2h(O[nj][2] * i1, O[nj][3] * i1, hp, lp);
        *(uint32_t*)((char*)g_ctx_hi + (o1 + col) * 2) = hp;
        *(uint32_t*)((char*)g_ctx_lo + (o1 + col) * 2) = lp;
    }
}

// ---------------- block reduction helpers ----------------
__device__ __forceinline__ float blockReduceSum(float v, float* red) {
    #pragma unroll
    for (int o = 16; o > 0; o >>= 1) v += __shfl_xor_sync(0xffffffffu, v, o);
    int lane = threadIdx.x & 31, w = threadIdx.x >> 5;
    __syncthreads();
    if (lane == 0) red[w] = v;
    __syncthreads();
    if (threadIdx.x == 0) {
        float s = 0.f;
        #pragma unroll
        for (int i = 0; i < 8; i++) s += red[i];
        red[0] = s;
    }
    __syncthreads();
    return red[0];
}

__device__ __forceinline__ float blockReduceMax(float v, float* red) {
    #pragma unroll
    for (int o = 16; o > 0; o >>= 1) v = fmaxf(v, __shfl_xor_sync(0xffffffffu, v, o));
    int lane = threadIdx.x & 31, w = threadIdx.x >> 5;
    __syncthreads();
    if (lane == 0) red[w] = v;
    __syncthreads();
    if (threadIdx.x == 0) {
        float s = -1e30f;
        #pragma unroll
        for (int i = 0; i < 8; i++) s = fmaxf(s, red[i]);
        red[0] = s;
    }
    __syncthreads();
    return red[0];
}

// ---------------- LayerNorm -> split fp16 hi/lo ----------------
__global__ __launch_bounds__(256) void ln_kernel(const float* __restrict__ x,
                                                 const float* __restrict__ w,
                                                 const float* __restrict__ bias) {
    int row = blockIdx.x;
    const float* xr = x + (size_t)row * DMODEL;
    int t = threadIdx.x;
    float v[3];
    float s = 0.f, sq = 0.f;
    #pragma unroll
    for (int i = 0; i < 3; i++) {
        v[i] = xr[t + i * 256];
        s += v[i];
        sq += v[i] * v[i];
    }
    __shared__ float red[32];
    __shared__ float stats[2];
    #pragma unroll
    for (int o = 16; o > 0; o >>= 1) {
        s  += __shfl_xor_sync(0xffffffffu, s, o);
        sq += __shfl_xor_sync(0xffffffffu, sq, o);
    }
    int lane = t & 31, wp = t >> 5;
    if (lane == 0) { red[wp] = s; red[8 + wp] = sq; }
    __syncthreads();
    if (t == 0) {
        float a = 0.f, b2 = 0.f;
        #pragma unroll
        for (int i = 0; i < 8; i++) { a += red[i]; b2 += red[8 + i]; }
        stats[0] = a; stats[1] = b2;
    }
    __syncthreads();
    float mean = stats[0] * (1.f / DMODEL);
    float var  = stats[1] * (1.f / DMODEL) - mean * mean;
    float inv  = rsqrtf(var + EPS);
    #pragma unroll
    for (int i = 0; i < 3; i++) {
        int c = t + i * 256;
        float o = (v[i] - mean) * inv * w[c] + bias[c];
        __half hh = __float2half_rn(o);
        size_t idx = (size_t)row * DMODEL + c;
        g_xn_hi[idx] = hh;
        g_xn_lo[idx] = __float2half_rn(o - __half2float(hh));
    }
}

// ---------------- CLS row (query row 0) ----------------
__global__ __launch_bounds__(256) void cls_kernel(const float* __restrict__ canny,
                                                  const float* __restrict__ noise) {
    int bh = blockIdx.x;
    int b = bh / NH, h = bh % NH;
    __shared__ float sm[NTOK];
    __shared__ float q0[64];
    __shared__ float red[32];
    __shared__ float part[4][64];
    int tid = threadIdx.x;
    size_t base = (size_t)b * NTOK * QKVW;

    if (tid < 64)
        q0[tid] = __half2float(g_qkv_hi[base + h * 64 + tid])
                + __half2float(g_qkv_lo[base + h * 64 + tid]);
    __syncthreads();

    for (int j = tid; j < NTOK; j += 256) {
        size_t ko = base + (size_t)j * QKVW + DMODEL + h * 64;
        float dot = 0.f;
        #pragma unroll
        for (int d2 = 0; d2 < 32; d2++) {
            __half2 kh = *(const __half2*)(g_qkv_hi + ko + 2 * d2);
            __half2 kl = *(const __half2*)(g_qkv_lo + ko + 2 * d2);
            dot += q0[2 * d2]     * (__half2float(kh.x) + __half2float(kl.x))
                 + q0[2 * d2 + 1] * (__half2float(kh.y) + __half2float(kl.y));
        }
        sm[j] = dot * SCALE;
    }
    __syncthreads();

    float mx = -1e30f, cs = 0.f, ns = 0.f;
    for (int j = tid; j < NPATCH; j += 256) {
        mx = fmaxf(mx, sm[j + 1]);
        cs += canny[(size_t)b * NPATCH + j] + 1.f;
        ns += noise[(size_t)b * NPATCH + j];
    }
    mx = blockReduceMax(mx, red);
    cs = blockReduceSum(cs, red);
    ns = blockReduceSum(ns, red);
    float se = 0.f;
    for (int j = tid; j < NPATCH; j += 256) se += exp2f((sm[j + 1] - mx) * LOG2E);
    se = blockReduceSum(se, red);
    float inv_se = 1.f / se, inv_cs = 1.f / cs, inv_ns = 1.f / ns;
    for (int j = tid; j < NPATCH; j += 256) {
        float a = exp2f((sm[j + 1] - mx) * LOG2E) * inv_se;
        sm[j + 1] = a + (canny[(size_t)b * NPATCH + j] + 1.f) * inv_cs
                      + noise[(size_t)b * NPATCH + j] * inv_ns;
    }
    __syncthreads();

    float mx2 = -1e30f;
    for (int j = tid; j < NTOK; j += 256) mx2 = fmaxf(mx2, sm[j]);
    mx2 = blockReduceMax(mx2, red);
    float se2 = 0.f;
    for (int j = tid; j < NTOK; j += 256) se2 += exp2f((sm[j] - mx2) * LOG2E);
    se2 = blockReduceSum(se2, red);
    float inv2 = 1.f / se2;
    for (int j = tid; j < NTOK; j += 256) sm[j] = exp2f((sm[j] - mx2) * LOG2E) * inv2;
    __syncthreads();

    int d = tid & 63, qp = tid >> 6;
    float acc = 0.f;
    for (int j = qp; j < NTOK; j += 4) {
        size_t vo = base + (size_t)j * QKVW + 2 * DMODEL + h * 64 + d;
        acc += sm[j] * (__half2float(g_qkv_hi[vo]) + __half2float(g_qkv_lo[vo]));
    }
    part[qp][d] = acc;
    __syncthreads();
    if (tid < 64) {
        float o = part[0][tid] + part[1][tid] + part[2][tid] + part[3][tid];
        __half hh = __float2half_rn(o);
        size_t idx = (size_t)b * NTOK * DMODEL + h * 64 + tid;
        g_ctx_hi[idx] = hh;
        g_ctx_lo[idx] = __float2half_rn(o - __half2float(hh));
    }
}

// ---------------- launch ----------------
extern "C" void kernel_launch(void* const* d_in, const int* in_sizes, int n_in,
                              void* d_out, int out_size) {
    const float* x     = (const float*)d_in[0];
    const float* canny = (const float*)d_in[1];
    const float* noise = (const float*)d_in[2];
    const float* ln_w  = (const float*)d_in[3];
    const float* ln_b  = (const float*)d_in[4];
    const float* w_qkv = (const float*)d_in[5];
    const float* w_out = (const float*)d_in[6];
    const float* b_out = (const float*)d_in[7];
    float* out = (float*)d_out;

    cudaFuncSetAttribute(gemm_mma<0>, cudaFuncAttributeMaxDynamicSharedMemorySize, GEMM_SMEM);
    cudaFuncSetAttribute(gemm_mma<1>, cudaFuncAttributeMaxDynamicSharedMemorySize, GEMM_SMEM);
    cudaFuncSetAttribute(attn_mma_kernel, cudaFuncAttributeMaxDynamicSharedMemorySize, ATT_SMEM);

    __half *wqkvT, *woutT;
    cudaGetSymbolAddress((void**)&wqkvT, g_wqkvT);
    cudaGetSymbolAddress((void**)&woutT, g_woutT);

    // 1. LayerNorm (-> fp16 hi/lo)
    ln_kernel<<<MTOT, 256>>>(x, ln_w, ln_b);

    // 1b. transpose weights to [N, K] fp16
    {
        dim3 g1(QKVW / 32, DMODEL / 32);
        transpose_h_kernel<<<g1, 256>>>(w_qkv, wqkvT, DMODEL, QKVW);
        dim3 g2(DMODEL / 32, DMODEL / 32);
        transpose_h_kernel<<<g2, 256>>>(w_out, woutT, DMODEL, DMODEL);
    }

    // 2. QKV GEMM -> g_qkv hi/lo
    {
        dim3 grid(QKVW / 128, (MTOT + 127) / 128);
        gemm_mma<0><<<grid, 256, GEMM_SMEM>>>(wqkvT, nullptr, nullptr, MTOT, QKVW, DMODEL);
    }

    // 3. attention rows 1..1024 (2 CTA/SM)
    {
        dim3 g_attn(8, BATCH * NH);
        attn_mma_kernel<<<g_attn, 256, ATT_SMEM>>>();
    }

    // 4. CLS row with prior injection
    cls_kernel<<<BATCH * NH, 256>>>(canny, noise);

    // 5. output projection -> d_out (fp32 + bias)
    {
        dim3 grid(DMODEL / 128, (MTOT + 127) / 128);
        gemm_mma<1><<<grid, 256, GEMM_SMEM>>>(woutT, b_out, out, MTOT, DMODEL, DMODEL);
    }
}

// round 12
// speedup vs baseline: 2.0670x; 1.1567x over previous
#include <cuda_runtime.h>
#include <cuda_fp16.h>
#include <math.h>
#include <stdint.h>

#define BATCH   8
#define NTOK    1025
#define DMODEL  768
#define NH      12
#define HDIM    64
#define NPATCH  1024
#define QKVW    (3*DMODEL)          // 2304
#define EPS     1e-5f
#define LOG2E   1.4426950408889634f
#define SCALE   0.03608439182435161f   // 768^-0.5
#define MTOT    (BATCH*NTOK)        // 8200

// ---------------- scratch (device globals; no allocation) ----------------
__device__ __half g_xn_hi [(size_t)MTOT * DMODEL];
__device__ __half g_xn_lo [(size_t)MTOT * DMODEL];
__device__ __half g_qkv_hi[(size_t)MTOT * QKVW];
__device__ __half g_qkv_lo[(size_t)MTOT * QKVW];
__device__ __half g_ctx_hi[(size_t)MTOT * DMODEL];
__device__ __half g_ctx_lo[(size_t)MTOT * DMODEL];
__device__ __half g_wqkvT [(size_t)QKVW * DMODEL];
__device__ __half g_woutT [(size_t)DMODEL * DMODEL];

// ---------------- helpers ----------------
__device__ __forceinline__ uint32_t smem_u32(const void* p) {
    uint32_t a;
    asm("{ .reg .u64 t; cvta.to.shared.u64 t, %1; cvt.u32.u64 %0, t; }" : "=r"(a) : "l"(p));
    return a;
}

__device__ __forceinline__ void mma_f16(float* c, const uint32_t* a, const uint32_t* b) {
    asm volatile(
        "mma.sync.aligned.m16n8k16.row.col.f32.f16.f16.f32 "
        "{%0,%1,%2,%3}, {%4,%5,%6,%7}, {%8,%9}, {%0,%1,%2,%3};"
        : "+f"(c[0]), "+f"(c[1]), "+f"(c[2]), "+f"(c[3])
        : "r"(a[0]), "r"(a[1]), "r"(a[2]), "r"(a[3]), "r"(b[0]), "r"(b[1]));
}

__device__ __forceinline__ void ldsm_x4(uint32_t* f, uint32_t addr) {
    asm volatile("ldmatrix.sync.aligned.m8n8.x4.shared.b16 {%0,%1,%2,%3}, [%4];"
        : "=r"(f[0]), "=r"(f[1]), "=r"(f[2]), "=r"(f[3]) : "r"(addr));
}
__device__ __forceinline__ void ldsm_x2(uint32_t* f, uint32_t addr) {
    asm volatile("ldmatrix.sync.aligned.m8n8.x2.shared.b16 {%0,%1}, [%2];"
        : "=r"(f[0]), "=r"(f[1]) : "r"(addr));
}
__device__ __forceinline__ void ldsm_x2_trans(uint32_t* f, uint32_t addr) {
    asm volatile("ldmatrix.sync.aligned.m8n8.x2.trans.shared.b16 {%0,%1}, [%2];"
        : "=r"(f[0]), "=r"(f[1]) : "r"(addr));
}

#define CP_ASYNC16(dst, src, nbytes) \
    asm volatile("cp.async.cg.shared.global [%0], [%1], 16, %2;" \
                 :: "r"(dst), "l"(src), "r"(nbytes))
#define CP_COMMIT() asm volatile("cp.async.commit_group;")
#define CP_WAIT0()  asm volatile("cp.async.wait_group 0;")

// hi/lo fp16 split of two floats -> packed half2 (hi, lo); a in low half
__device__ __forceinline__ void split2h(float a, float b, uint32_t& hp, uint32_t& lp) {
    __half ha = __float2half_rn(a), hb = __float2half_rn(b);
    float ra = a - __half2float(ha), rb = b - __half2float(hb);
    __half la = __float2half_rn(ra), lb = __float2half_rn(rb);
    hp = (uint32_t)__half_as_ushort(ha) | ((uint32_t)__half_as_ushort(hb) << 16);
    lp = (uint32_t)__half_as_ushort(la) | ((uint32_t)__half_as_ushort(lb) << 16);
}
// plain fp16 pack of two floats
__device__ __forceinline__ uint32_t pack2h(float a, float b) {
    __half ha = __float2half_rn(a), hb = __float2half_rn(b);
    return (uint32_t)__half_as_ushort(ha) | ((uint32_t)__half_as_ushort(hb) << 16);
}

// ---------------- weight transpose (fp16): dst[N,K] = fp16(src[K,N]) ----------------
__global__ __launch_bounds__(256) void transpose_h_kernel(const float* __restrict__ src,
                                                          __half* __restrict__ dh,
                                                          int K, int N) {
    __shared__ float t[32][33];
    int nx = blockIdx.x * 32, kx = blockIdx.y * 32;
    int lx = threadIdx.x & 31, ly = threadIdx.x >> 5;
    #pragma unroll
    for (int i = ly; i < 32; i += 8)
        t[i][lx] = src[(size_t)(kx + i) * N + nx + lx];
    __syncthreads();
    #pragma unroll
    for (int i = ly; i < 32; i += 8)
        dh[(size_t)(nx + i) * K + kx + lx] = __float2half_rn(t[lx][i]);
}

// ================= tensor-core GEMM (fp16 2-pass, 2-stage cp.async, 2 CTA/SM) =================
#define SM_STRIDE 20
#define ARR_BYTES (128 * SM_STRIDE * 4)     // 10240
#define STG_BYTES (3 * ARR_BYTES)           // 30720
#define GEMM_SMEM (2 * STG_BYTES)           // 61440

template<int SEL>
__global__ __launch_bounds__(256, 2) void gemm_mma(const __half* __restrict__ Bh,
                                                   const float* __restrict__ bias,
                                                   float* __restrict__ Cext,
                                                   int M, int N, int K) {
    const __half* Ah = (SEL == 0) ? g_xn_hi : g_ctx_hi;
    const __half* Al = (SEL == 0) ? g_xn_lo : g_ctx_lo;

    extern __shared__ char smem[];
    uint32_t sbase = smem_u32(smem);

    int tid = threadIdx.x;
    int wid = tid >> 5, lane = tid & 31;
    int g = lane >> 2, t = lane & 3;
    int wm = wid & 1, wn = wid >> 1;
    int m0 = blockIdx.y * 128, n0 = blockIdx.x * 128;
    int mw = wm * 64, nw = wn * 32;

    int rA = (lane & 7) + ((lane >> 3) & 1) * 8;
    int cA = (lane >> 4) * 4;
    uint32_t aoff = (uint32_t)(rA * SM_STRIDE + cA) * 4u;
    int rB = lane & 7;
    int cB = ((lane >> 3) & 1) * 4;
    uint32_t boff = (uint32_t)(rB * SM_STRIDE + cB) * 4u;

    int lr = tid >> 2, lq = tid & 3;

    float acc[4][4][4];
    #pragma unroll
    for (int i = 0; i < 4; i++)
        #pragma unroll
        for (int j = 0; j < 4; j++)
            #pragma unroll
            for (int q = 0; q < 4; q++) acc[i][j][q] = 0.f;

    int nch = K / 32;

    auto load_stage = [&](int ch, int s) {
        int kb = ch * 32;
        uint32_t so = sbase + (uint32_t)s * STG_BYTES;
        #pragma unroll
        for (int l = 0; l < 2; l++) {
            int r = lr + l * 64;
            uint32_t d = (uint32_t)(r * SM_STRIDE + lq * 4) * 4u;
            int okA = (m0 + r < M) ? 16 : 0;
            size_t ao = (size_t)(m0 + r) * K + kb + lq * 8;
            size_t bo = (size_t)(n0 + r) * K + kb + lq * 8;
            CP_ASYNC16(so + d,                 Ah + ao, okA);
            CP_ASYNC16(so + ARR_BYTES + d,     Al + ao, okA);
            CP_ASYNC16(so + 2 * ARR_BYTES + d, Bh + bo, 16);
        }
    };

    load_stage(0, 0);
    CP_COMMIT();

    for (int ch = 0; ch < nch; ch++) {
        int s = ch & 1;
        CP_WAIT0();
        __syncthreads();
        if (ch + 1 < nch) {
            load_stage(ch + 1, s ^ 1);
            CP_COMMIT();
        }

        uint32_t uAH = sbase + (uint32_t)s * STG_BYTES;
        uint32_t uAL = uAH + ARR_BYTES;
        uint32_t uBH = uAH + 2 * ARR_BYTES;

        uint32_t ah[2][4][4], al[2][4][4], bh[2][4][2];
        #pragma unroll
        for (int kk = 0; kk < 2; kk++) {
            uint32_t kcb = (uint32_t)(kk * 8) * 4u;
            #pragma unroll
            for (int mi = 0; mi < 4; mi++) {
                uint32_t base = (uint32_t)((mw + mi * 16) * SM_STRIDE) * 4u + kcb + aoff;
                ldsm_x4(ah[kk][mi], uAH + base);
                ldsm_x4(al[kk][mi], uAL + base);
            }
            #pragma unroll
            for (int nj = 0; nj < 4; nj++) {
                uint32_t base = (uint32_t)((nw + nj * 8) * SM_STRIDE) * 4u + kcb + boff;
                ldsm_x2(bh[kk][nj], uBH + base);
            }
        }
        #pragma unroll
        for (int kk = 0; kk < 2; kk++)
            #pragma unroll
            for (int mi = 0; mi < 4; mi++)
                #pragma unroll
                for (int nj = 0; nj < 4; nj++) {
                    mma_f16(acc[mi][nj], ah[kk][mi], bh[kk][nj]);
                    mma_f16(acc[mi][nj], al[kk][mi], bh[kk][nj]);
                }
    }

    // ---- epilogue ----
    #pragma unroll
    for (int mi = 0; mi < 4; mi++) {
        int r0e = m0 + mw + mi * 16 + g;
        #pragma unroll
        for (int nj = 0; nj < 4; nj++) {
            int col = n0 + nw + nj * 8 + t * 2;
            if (SEL == 0) {
                #pragma unroll
                for (int half = 0; half < 2; half++) {
                    int row = r0e + half * 8;
                    if (row < M) {
                        uint32_t hp, lp;
                        split2h(acc[mi][nj][2 * half], acc[mi][nj][2 * half + 1], hp, lp);
                        size_t o = (size_t)row * N + col;
                        *(uint32_t*)((char*)g_qkv_hi + o * 2) = hp;
                        *(uint32_t*)((char*)g_qkv_lo + o * 2) = lp;
                    }
                }
            } else {
                float b0 = bias[col], b1 = bias[col + 1];
                if (r0e < M)
                    *(float2*)(Cext + (size_t)r0e * N + col) =
                        make_float2(acc[mi][nj][0] + b0, acc[mi][nj][1] + b1);
                if (r0e + 8 < M)
                    *(float2*)(Cext + (size_t)(r0e + 8) * N + col) =
                        make_float2(acc[mi][nj][2] + b0, acc[mi][nj][3] + b1);
            }
        }
    }
}

// ================= tensor-core flash attention (rows 1..1024), fp16 single-pass =================
// grid (8, 96), 256 threads (8 warps x m16), 2 CTA/SM.
// K, V hi-only [key][dim-pair] via cp.async double buffer (stride 36 u32).
// Q and P rounded to fp16 (single-pass QK and PV).
#define ATT_STG_BYTES 18432u
#define ATT_SMEM      (2 * 18432)

__global__ __launch_bounds__(256, 2) void attn_mma_kernel() {
    extern __shared__ uint32_t sh[];
    int qt = blockIdx.x;
    int bh_ = blockIdx.y;
    int b = bh_ / NH, h = bh_ % NH;

    int tid = threadIdx.x, wid = tid >> 5, lane = tid & 31;
    int g = lane >> 2, t = lane & 3;
    size_t base = (size_t)b * NTOK * QKVW;
    uint32_t sbase = smem_u32(sh);

    // ---- Q fragments: reconstruct fp32 from hi/lo, scale, round to fp16 ----
    int row0 = 1 + qt * 128 + wid * 16;
    const float qsc = SCALE * LOG2E;
    const __half* Qh0 = g_qkv_hi + base + (size_t)(row0 + g) * QKVW + h * 64;
    const __half* Ql0 = g_qkv_lo + base + (size_t)(row0 + g) * QKVW + h * 64;
    const __half* Qh1 = Qh0 + 8 * QKVW;
    const __half* Ql1 = Ql0 + 8 * QKVW;
    uint32_t qh[4][4];
    #pragma unroll
    for (int kk = 0; kk < 4; kk++) {
        int k0 = kk * 16 + 2 * t;
        #pragma unroll
        for (int fi = 0; fi < 4; fi++) {
            int ko = k0 + (fi >> 1) * 8;
            const __half* ph = (fi & 1) ? Qh1 : Qh0;
            const __half* pl = (fi & 1) ? Ql1 : Ql0;
            __half2 vh = *(const __half2*)(ph + ko);
            __half2 vl = *(const __half2*)(pl + ko);
            float a = (__half2float(vh.x) + __half2float(vl.x)) * qsc;
            float c = (__half2float(vh.y) + __half2float(vl.y)) * qsc;
            qh[kk][fi] = pack2h(a, c);
        }
    }

    // K+V loader (cp.async, hi only)
    auto load_kv = [&](int c, int s) {
        int j0 = c * 64;
        uint32_t sb = sbase + (uint32_t)s * ATT_STG_BYTES;
        #pragma unroll
        for (int l = 0; l < 2; l++) {
            int idx = tid + l * 256;
            int r = idx >> 3, c8 = idx & 7;
            int j = j0 + r;
            uint32_t d = (uint32_t)(r * 36 + c8 * 4) * 4u;
            int ok = (j < NTOK) ? 16 : 0;
            size_t ko = base + (size_t)j * QKVW + DMODEL + h * 64 + c8 * 8;
            size_t vo = ko + DMODEL;
            CP_ASYNC16(sb + d,         (const char*)g_qkv_hi + ko * 2, ok);
            CP_ASYNC16(sb + 9216u + d, (const char*)g_qkv_hi + vo * 2, ok);
        }
    };

    // per-lane ldsm offsets
    int kfr = lane & 7, kfc = ((lane >> 3) & 1) * 4;
    uint32_t kfoff = (uint32_t)(kfr * 36 + kfc) * 4u;
    int vrow = (lane & 7) + ((lane >> 3) & 1) * 8;
    uint32_t vtoff = (uint32_t)vrow * 144u;

    float O[8][4];
    #pragma unroll
    for (int nj = 0; nj < 8; nj++)
        #pragma unroll
        for (int q = 0; q < 4; q++) O[nj][q] = 0.f;
    float mr0 = -1e30f, mr1 = -1e30f, lr0 = 0.f, lr1 = 0.f;

    load_kv(0, 0);
    CP_COMMIT();

    for (int c = 0; c < 17; c++) {
        int s = c & 1;
        CP_WAIT0();
        __syncthreads();
        if (c + 1 < 17) {
            load_kv(c + 1, s ^ 1);
            CP_COMMIT();
        }
        uint32_t uKH = sbase + (uint32_t)s * ATT_STG_BYTES;
        uint32_t uVH = uKH + 9216u + vtoff;
        int j0 = c * 64;

        // ---- S = Q K^T (single pass) ----
        float S[8][4];
        #pragma unroll
        for (int nj = 0; nj < 8; nj++)
            #pragma unroll
            for (int q = 0; q < 4; q++) S[nj][q] = 0.f;

        #pragma unroll
        for (int kk = 0; kk < 4; kk++) {
            uint32_t kcb = (uint32_t)(kk * 8) * 4u;
            #pragma unroll
            for (int nj = 0; nj < 8; nj++) {
                uint32_t kb[2];
                ldsm_x2(kb, uKH + (uint32_t)(nj * 8 * 36) * 4u + kcb + kfoff);
                mma_f16(S[nj], qh[kk], kb);
            }
        }

        if (j0 + 64 > NTOK) {
            #pragma unroll
            for (int nj = 0; nj < 8; nj++) {
                int col = j0 + 8 * nj + 2 * t;
                if (col >= NTOK)     { S[nj][0] = -1e30f; S[nj][2] = -1e30f; }
                if (col + 1 >= NTOK) { S[nj][1] = -1e30f; S[nj][3] = -1e30f; }
            }
        }

        // ---- online softmax (log2 domain) ----
        float cm0 = -1e30f, cm1 = -1e30f;
        #pragma unroll
        for (int nj = 0; nj < 8; nj++) {
            cm0 = fmaxf(cm0, fmaxf(S[nj][0], S[nj][1]));
            cm1 = fmaxf(cm1, fmaxf(S[nj][2], S[nj][3]));
        }
        cm0 = fmaxf(cm0, __shfl_xor_sync(0xffffffffu, cm0, 1));
        cm0 = fmaxf(cm0, __shfl_xor_sync(0xffffffffu, cm0, 2));
        cm1 = fmaxf(cm1, __shfl_xor_sync(0xffffffffu, cm1, 1));
        cm1 = fmaxf(cm1, __shfl_xor_sync(0xffffffffu, cm1, 2));
        float mn0 = fmaxf(mr0, cm0), mn1 = fmaxf(mr1, cm1);
        float f0 = exp2f(mr0 - mn0), f1 = exp2f(mr1 - mn1);
        float ps0 = 0.f, ps1 = 0.f;
        #pragma unroll
        for (int nj = 0; nj < 8; nj++) {
            S[nj][0] = exp2f(S[nj][0] - mn0);
            S[nj][1] = exp2f(S[nj][1] - mn0);
            S[nj][2] = exp2f(S[nj][2] - mn1);
            S[nj][3] = exp2f(S[nj][3] - mn1);
            ps0 += S[nj][0] + S[nj][1];
            ps1 += S[nj][2] + S[nj][3];
        }
        ps0 += __shfl_xor_sync(0xffffffffu, ps0, 1);
        ps0 += __shfl_xor_sync(0xffffffffu, ps0, 2);
        ps1 += __shfl_xor_sync(0xffffffffu, ps1, 1);
        ps1 += __shfl_xor_sync(0xffffffffu, ps1, 2);
        lr0 = lr0 * f0 + ps0;
        lr1 = lr1 * f1 + ps1;
        mr0 = mn0; mr1 = mn1;
        #pragma unroll
        for (int nj = 0; nj < 8; nj++) {
            O[nj][0] *= f0; O[nj][1] *= f0;
            O[nj][2] *= f1; O[nj][3] *= f1;
        }

        // ---- O += P @ V (single pass, P rounded to fp16) ----
        #pragma unroll
        for (int kk = 0; kk < 4; kk++) {
            int j2 = 2 * kk;
            uint32_t ph[4];
            ph[0] = pack2h(S[j2][0],     S[j2][1]);
            ph[1] = pack2h(S[j2][2],     S[j2][3]);
            ph[2] = pack2h(S[j2 + 1][0], S[j2 + 1][1]);
            ph[3] = pack2h(S[j2 + 1][2], S[j2 + 1][3]);
            uint32_t kbase = (uint32_t)(kk * 16) * 144u;
            #pragma unroll
            for (int nj = 0; nj < 8; nj++) {
                uint32_t vh[2];
                ldsm_x2_trans(vh, uVH + kbase + (uint32_t)nj * 16u);
                mma_f16(O[nj], ph, vh);
            }
        }
    }

    // ---- write out (split to g_ctx hi/lo) ----
    float i0 = 1.f / lr0, i1 = 1.f / lr1;
    size_t o0 = ((size_t)b * NTOK + row0 + g) * DMODEL + h * 64;
    size_t o1 = o0 + (size_t)8 * DMODEL;
    #pragma unroll
    for (int nj = 0; nj < 8; nj++) {
        int col = 8 * nj + 2 * t;
        uint32_t hp, lp;
        split2h(O[nj][0] * i0, O[nj][1] * i0, hp, lp);
        *(uint32_t*)((char*)g_ctx_hi + (o0 + col) * 2) = hp;
        *(uint32_t*)((char*)g_ctx_lo + (o0 + col) * 2) = lp;
        split2h(O[nj][2] * i1, O[nj][3] * i1, hp, lp);
        *(uint32_t*)((char*)g_ctx_hi + (o1 + col) * 2) = hp;
        *(uint32_t*)((char*)g_ctx_lo + (o1 + col) * 2) = lp;
    }
}

// ---------------- block reduction helpers ----------------
__device__ __forceinline__ float blockReduceSum(float v, float* red) {
    #pragma unroll
    for (int o = 16; o > 0; o >>= 1) v += __shfl_xor_sync(0xffffffffu, v, o);
    int lane = threadIdx.x & 31, w = threadIdx.x >> 5;
    __syncthreads();
    if (lane == 0) red[w] = v;
    __syncthreads();
    if (threadIdx.x == 0) {
        float s = 0.f;
        #pragma unroll
        for (int i = 0; i < 8; i++) s += red[i];
        red[0] = s;
    }
    __syncthreads();
    return red[0];
}

__device__ __forceinline__ float blockReduceMax(float v, float* red) {
    #pragma unroll
    for (int o = 16; o > 0; o >>= 1) v = fmaxf(v, __shfl_xor_sync(0xffffffffu, v, o));
    int lane = threadIdx.x & 31, w = threadIdx.x >> 5;
    __syncthreads();
    if (lane == 0) red[w] = v;
    __syncthreads();
    if (threadIdx.x == 0) {
        float s = -1e30f;
        #pragma unroll
        for (int i = 0; i < 8; i++) s = fmaxf(s, red[i]);
        red[0] = s;
    }
    __syncthreads();
    return red[0];
}

// ---------------- LayerNorm -> split fp16 hi/lo ----------------
__global__ __launch_bounds__(256) void ln_kernel(const float* __restrict__ x,
                                                 const float* __restrict__ w,
                                                 const float* __restrict__ bias) {
    int row = blockIdx.x;
    const float* xr = x + (size_t)row * DMODEL;
    int t = threadIdx.x;
    float v[3];
    float s = 0.f, sq = 0.f;
    #pragma unroll
    for (int i = 0; i < 3; i++) {
        v[i] = xr[t + i * 256];
        s += v[i];
        sq += v[i] * v[i];
    }
    __shared__ float red[32];
    __shared__ float stats[2];
    #pragma unroll
    for (int o = 16; o > 0; o >>= 1) {
        s  += __shfl_xor_sync(0xffffffffu, s, o);
        sq += __shfl_xor_sync(0xffffffffu, sq, o);
    }
    int lane = t & 31, wp = t >> 5;
    if (lane == 0) { red[wp] = s; red[8 + wp] = sq; }
    __syncthreads();
    if (t == 0) {
        float a = 0.f, b2 = 0.f;
        #pragma unroll
        for (int i = 0; i < 8; i++) { a += red[i]; b2 += red[8 + i]; }
        stats[0] = a; stats[1] = b2;
    }
    __syncthreads();
    float mean = stats[0] * (1.f / DMODEL);
    float var  = stats[1] * (1.f / DMODEL) - mean * mean;
    float inv  = rsqrtf(var + EPS);
    #pragma unroll
    for (int i = 0; i < 3; i++) {
        int c = t + i * 256;
        float o = (v[i] - mean) * inv * w[c] + bias[c];
        __half hh = __float2half_rn(o);
        size_t idx = (size_t)row * DMODEL + c;
        g_xn_hi[idx] = hh;
        g_xn_lo[idx] = __float2half_rn(o - __half2float(hh));
    }
}

// ---------------- CLS row (query row 0) ----------------
__global__ __launch_bounds__(256) void cls_kernel(const float* __restrict__ canny,
                                                  const float* __restrict__ noise) {
    int bh = blockIdx.x;
    int b = bh / NH, h = bh % NH;
    __shared__ float sm[NTOK];
    __shared__ float q0[64];
    __shared__ float red[32];
    __shared__ float part[4][64];
    int tid = threadIdx.x;
    size_t base = (size_t)b * NTOK * QKVW;

    if (tid < 64)
        q0[tid] = __half2float(g_qkv_hi[base + h * 64 + tid])
                + __half2float(g_qkv_lo[base + h * 64 + tid]);
    __syncthreads();

    for (int j = tid; j < NTOK; j += 256) {
        size_t ko = base + (size_t)j * QKVW + DMODEL + h * 64;
        float dot = 0.f;
        #pragma unroll
        for (int d2 = 0; d2 < 32; d2++) {
            __half2 kh = *(const __half2*)(g_qkv_hi + ko + 2 * d2);
            __half2 kl = *(const __half2*)(g_qkv_lo + ko + 2 * d2);
            dot += q0[2 * d2]     * (__half2float(kh.x) + __half2float(kl.x))
                 + q0[2 * d2 + 1] * (__half2float(kh.y) + __half2float(kl.y));
        }
        sm[j] = dot * SCALE;
    }
    __syncthreads();

    float mx = -1e30f, cs = 0.f, ns = 0.f;
    for (int j = tid; j < NPATCH; j += 256) {
        mx = fmaxf(mx, sm[j + 1]);
        cs += canny[(size_t)b * NPATCH + j] + 1.f;
        ns += noise[(size_t)b * NPATCH + j];
    }
    mx = blockReduceMax(mx, red);
    cs = blockReduceSum(cs, red);
    ns = blockReduceSum(ns, red);
    float se = 0.f;
    for (int j = tid; j < NPATCH; j += 256) se += exp2f((sm[j + 1] - mx) * LOG2E);
    se = blockReduceSum(se, red);
    float inv_se = 1.f / se, inv_cs = 1.f / cs, inv_ns = 1.f / ns;
    for (int j = tid; j < NPATCH; j += 256) {
        float a = exp2f((sm[j + 1] - mx) * LOG2E) * inv_se;
        sm[j + 1] = a + (canny[(size_t)b * NPATCH + j] + 1.f) * inv_cs
                      + noise[(size_t)b * NPATCH + j] * inv_ns;
    }
    __syncthreads();

    float mx2 = -1e30f;
    for (int j = tid; j < NTOK; j += 256) mx2 = fmaxf(mx2, sm[j]);
    mx2 = blockReduceMax(mx2, red);
    float se2 = 0.f;
    for (int j = tid; j < NTOK; j += 256) se2 += exp2f((sm[j] - mx2) * LOG2E);
    se2 = blockReduceSum(se2, red);
    float inv2 = 1.f / se2;
    for (int j = tid; j < NTOK; j += 256) sm[j] = exp2f((sm[j] - mx2) * LOG2E) * inv2;
    __syncthreads();

    int d = tid & 63, qp = tid >> 6;
    float acc = 0.f;
    for (int j = qp; j < NTOK; j += 4) {
        size_t vo = base + (size_t)j * QKVW + 2 * DMODEL + h * 64 + d;
        acc += sm[j] * (__half2float(g_qkv_hi[vo]) + __half2float(g_qkv_lo[vo]));
    }
    part[qp][d] = acc;
    __syncthreads();
    if (tid < 64) {
        float o = part[0][tid] + part[1][tid] + part[2][tid] + part[3][tid];
        __half hh = __float2half_rn(o);
        size_t idx = (size_t)b * NTOK * DMODEL + h * 64 + tid;
        g_ctx_hi[idx] = hh;
        g_ctx_lo[idx] = __float2half_rn(o - __half2float(hh));
    }
}

// ---------------- launch ----------------
extern "C" void kernel_launch(void* const* d_in, const int* in_sizes, int n_in,
                              void* d_out, int out_size) {
    const float* x     = (const float*)d_in[0];
    const float* canny = (const float*)d_in[1];
    const float* noise = (const float*)d_in[2];
    const float* ln_w  = (const float*)d_in[3];
    const float* ln_b  = (const float*)d_in[4];
    const float* w_qkv = (const float*)d_in[5];
    const float* w_out = (const float*)d_in[6];
    const float* b_out = (const float*)d_in[7];
    float* out = (float*)d_out;

    cudaFuncSetAttribute(gemm_mma<0>, cudaFuncAttributeMaxDynamicSharedMemorySize, GEMM_SMEM);
    cudaFuncSetAttribute(gemm_mma<1>, cudaFuncAttributeMaxDynamicSharedMemorySize, GEMM_SMEM);
    cudaFuncSetAttribute(attn_mma_kernel, cudaFuncAttributeMaxDynamicSharedMemorySize, ATT_SMEM);

    __half *wqkvT, *woutT;
    cudaGetSymbolAddress((void**)&wqkvT, g_wqkvT);
    cudaGetSymbolAddress((void**)&woutT, g_woutT);

    // 1. LayerNorm (-> fp16 hi/lo)
    ln_kernel<<<MTOT, 256>>>(x, ln_w, ln_b);

    // 1b. transpose weights to [N, K] fp16
    {
        dim3 g1(QKVW / 32, DMODEL / 32);
        transpose_h_kernel<<<g1, 256>>>(w_qkv, wqkvT, DMODEL, QKVW);
        dim3 g2(DMODEL / 32, DMODEL / 32);
        transpose_h_kernel<<<g2, 256>>>(w_out, woutT, DMODEL, DMODEL);
    }

    // 2. QKV GEMM -> g_qkv hi/lo
    {
        dim3 grid(QKVW / 128, (MTOT + 127) / 128);
        gemm_mma<0><<<grid, 256, GEMM_SMEM>>>(wqkvT, nullptr, nullptr, MTOT, QKVW, DMODEL);
    }

    // 3. attention rows 1..1024 (2 CTA/SM, single-pass QK/PV)
    {
        dim3 g_attn(8, BATCH * NH);
        attn_mma_kernel<<<g_attn, 256, ATT_SMEM>>>();
    }

    // 4. CLS row with prior injection
    cls_kernel<<<BATCH * NH, 256>>>(canny, noise);

    // 5. output projection -> d_out (fp32 + bias)
    {
        dim3 grid(DMODEL / 128, (MTOT + 127) / 128);
        gemm_mma<1><<<grid, 256, GEMM_SMEM>>>(woutT, b_out, out, MTOT, DMODEL, DMODEL);
    }
}

// round 13
// speedup vs baseline: 2.6943x; 1.3035x over previous
#include <cuda_runtime.h>
#include <cuda_fp16.h>
#include <math.h>
#include <stdint.h>

#define BATCH   8
#define NTOK    1025
#define DMODEL  768
#define NH      12
#define HDIM    64
#define NPATCH  1024
#define QKVW    (3*DMODEL)          // 2304
#define EPS     1e-5f
#define LOG2E   1.4426950408889634f
#define SCALE   0.03608439182435161f   // 768^-0.5
#define MTOT    (BATCH*NTOK)        // 8200

// ---------------- scratch (device globals; no allocation) ----------------
__device__ __half g_xn    [(size_t)MTOT * DMODEL];
__device__ __half g_qkv   [(size_t)MTOT * QKVW];
__device__ __half g_ctx_hi[(size_t)MTOT * DMODEL];
__device__ __half g_ctx_lo[(size_t)MTOT * DMODEL];
__device__ __half g_wqkvT [(size_t)QKVW * DMODEL];
__device__ __half g_woutT [(size_t)DMODEL * DMODEL];

// ---------------- helpers ----------------
__device__ __forceinline__ uint32_t smem_u32(const void* p) {
    uint32_t a;
    asm("{ .reg .u64 t; cvta.to.shared.u64 t, %1; cvt.u32.u64 %0, t; }" : "=r"(a) : "l"(p));
    return a;
}

__device__ __forceinline__ void mma_f16(float* c, const uint32_t* a, const uint32_t* b) {
    asm volatile(
        "mma.sync.aligned.m16n8k16.row.col.f32.f16.f16.f32 "
        "{%0,%1,%2,%3}, {%4,%5,%6,%7}, {%8,%9}, {%0,%1,%2,%3};"
        : "+f"(c[0]), "+f"(c[1]), "+f"(c[2]), "+f"(c[3])
        : "r"(a[0]), "r"(a[1]), "r"(a[2]), "r"(a[3]), "r"(b[0]), "r"(b[1]));
}

__device__ __forceinline__ void ldsm_x4(uint32_t* f, uint32_t addr) {
    asm volatile("ldmatrix.sync.aligned.m8n8.x4.shared.b16 {%0,%1,%2,%3}, [%4];"
        : "=r"(f[0]), "=r"(f[1]), "=r"(f[2]), "=r"(f[3]) : "r"(addr));
}
__device__ __forceinline__ void ldsm_x2(uint32_t* f, uint32_t addr) {
    asm volatile("ldmatrix.sync.aligned.m8n8.x2.shared.b16 {%0,%1}, [%2];"
        : "=r"(f[0]), "=r"(f[1]) : "r"(addr));
}
__device__ __forceinline__ void ldsm_x2_trans(uint32_t* f, uint32_t addr) {
    asm volatile("ldmatrix.sync.aligned.m8n8.x2.trans.shared.b16 {%0,%1}, [%2];"
        : "=r"(f[0]), "=r"(f[1]) : "r"(addr));
}

#define CP_ASYNC16(dst, src, nbytes) \
    asm volatile("cp.async.cg.shared.global [%0], [%1], 16, %2;" \
                 :: "r"(dst), "l"(src), "r"(nbytes))
#define CP_COMMIT() asm volatile("cp.async.commit_group;")
#define CP_WAIT0()  asm volatile("cp.async.wait_group 0;")

// hi/lo fp16 split of two floats -> packed half2 (hi, lo); a in low half
__device__ __forceinline__ void split2h(float a, float b, uint32_t& hp, uint32_t& lp) {
    __half ha = __float2half_rn(a), hb = __float2half_rn(b);
    float ra = a - __half2float(ha), rb = b - __half2float(hb);
    __half la = __float2half_rn(ra), lb = __float2half_rn(rb);
    hp = (uint32_t)__half_as_ushort(ha) | ((uint32_t)__half_as_ushort(hb) << 16);
    lp = (uint32_t)__half_as_ushort(la) | ((uint32_t)__half_as_ushort(lb) << 16);
}
// plain fp16 pack of two floats
__device__ __forceinline__ uint32_t pack2h(float a, float b) {
    __half ha = __float2half_rn(a), hb = __float2half_rn(b);
    return (uint32_t)__half_as_ushort(ha) | ((uint32_t)__half_as_ushort(hb) << 16);
}

// ---------------- weight transpose (fp16): dst[N,K] = fp16(src[K,N]) ----------------
__global__ __launch_bounds__(256) void transpose_h_kernel(const float* __restrict__ src,
                                                          __half* __restrict__ dh,
                                                          int K, int N) {
    __shared__ float t[32][33];
    int nx = blockIdx.x * 32, kx = blockIdx.y * 32;
    int lx = threadIdx.x & 31, ly = threadIdx.x >> 5;
    #pragma unroll
    for (int i = ly; i < 32; i += 8)
        t[i][lx] = src[(size_t)(kx + i) * N + nx + lx];
    __syncthreads();
    #pragma unroll
    for (int i = ly; i < 32; i += 8)
        dh[(size_t)(nx + i) * K + kx + lx] = __float2half_rn(t[lx][i]);
}

// ================= tensor-core GEMM (2-stage cp.async, 2 CTA/SM) =================
// SEL=0: single-pass fp16 (A=g_xn), epilogue -> g_qkv fp16.
// SEL=1: 2-pass (A=g_ctx hi/lo 22-bit), epilogue -> fp32 + bias.
#define SM_STRIDE 20
#define ARR_BYTES (128 * SM_STRIDE * 4)     // 10240

template<int SEL>
__global__ __launch_bounds__(256, 2) void gemm_mma(const __half* __restrict__ Bmat,
                                                   const float* __restrict__ bias,
                                                   float* __restrict__ Cext,
                                                   int M, int N, int K) {
    constexpr uint32_t STG = (SEL == 0) ? 2u * ARR_BYTES : 3u * ARR_BYTES;
    const __half* Ah = (SEL == 0) ? g_xn : g_ctx_hi;
    const __half* Al = g_ctx_lo;   // used only when SEL==1

    extern __shared__ char smem[];
    uint32_t sbase = smem_u32(smem);

    int tid = threadIdx.x;
    int wid = tid >> 5, lane = tid & 31;
    int g = lane >> 2, t = lane & 3;
    int wm = wid & 1, wn = wid >> 1;
    int m0 = blockIdx.y * 128, n0 = blockIdx.x * 128;
    int mw = wm * 64, nw = wn * 32;

    int rA = (lane & 7) + ((lane >> 3) & 1) * 8;
    int cA = (lane >> 4) * 4;
    uint32_t aoff = (uint32_t)(rA * SM_STRIDE + cA) * 4u;
    int rB = lane & 7;
    int cB = ((lane >> 3) & 1) * 4;
    uint32_t boff = (uint32_t)(rB * SM_STRIDE + cB) * 4u;

    int lr = tid >> 2, lq = tid & 3;
    const uint32_t B_OFF = (SEL == 0) ? ARR_BYTES : 2u * ARR_BYTES;

    float acc[4][4][4];
    #pragma unroll
    for (int i = 0; i < 4; i++)
        #pragma unroll
        for (int j = 0; j < 4; j++)
            #pragma unroll
            for (int q = 0; q < 4; q++) acc[i][j][q] = 0.f;

    int nch = K / 32;

    auto load_stage = [&](int ch, int s) {
        int kb = ch * 32;
        uint32_t so = sbase + (uint32_t)s * STG;
        #pragma unroll
        for (int l = 0; l < 2; l++) {
            int r = lr + l * 64;
            uint32_t d = (uint32_t)(r * SM_STRIDE + lq * 4) * 4u;
            int okA = (m0 + r < M) ? 16 : 0;
            size_t ao = (size_t)(m0 + r) * K + kb + lq * 8;
            size_t bo = (size_t)(n0 + r) * K + kb + lq * 8;
            CP_ASYNC16(so + d, Ah + ao, okA);
            if (SEL == 1) CP_ASYNC16(so + ARR_BYTES + d, Al + ao, okA);
            CP_ASYNC16(so + B_OFF + d, Bmat + bo, 16);
        }
    };

    load_stage(0, 0);
    CP_COMMIT();

    for (int ch = 0; ch < nch; ch++) {
        int s = ch & 1;
        CP_WAIT0();
        __syncthreads();
        if (ch + 1 < nch) {
            load_stage(ch + 1, s ^ 1);
            CP_COMMIT();
        }

        uint32_t uAH = sbase + (uint32_t)s * STG;
        uint32_t uAL = uAH + ARR_BYTES;
        uint32_t uB  = uAH + B_OFF;

        uint32_t ah[2][4][4], al[2][4][4], bh[2][4][2];
        #pragma unroll
        for (int kk = 0; kk < 2; kk++) {
            uint32_t kcb = (uint32_t)(kk * 8) * 4u;
            #pragma unroll
            for (int mi = 0; mi < 4; mi++) {
                uint32_t base = (uint32_t)((mw + mi * 16) * SM_STRIDE) * 4u + kcb + aoff;
                ldsm_x4(ah[kk][mi], uAH + base);
                if (SEL == 1) ldsm_x4(al[kk][mi], uAL + base);
            }
            #pragma unroll
            for (int nj = 0; nj < 4; nj++) {
                uint32_t base = (uint32_t)((nw + nj * 8) * SM_STRIDE) * 4u + kcb + boff;
                ldsm_x2(bh[kk][nj], uB + base);
            }
        }
        #pragma unroll
        for (int kk = 0; kk < 2; kk++)
            #pragma unroll
            for (int mi = 0; mi < 4; mi++)
                #pragma unroll
                for (int nj = 0; nj < 4; nj++) {
                    mma_f16(acc[mi][nj], ah[kk][mi], bh[kk][nj]);
                    if (SEL == 1) mma_f16(acc[mi][nj], al[kk][mi], bh[kk][nj]);
                }
    }

    // ---- epilogue ----
    #pragma unroll
    for (int mi = 0; mi < 4; mi++) {
        int r0e = m0 + mw + mi * 16 + g;
        #pragma unroll
        for (int nj = 0; nj < 4; nj++) {
            int col = n0 + nw + nj * 8 + t * 2;
            if (SEL == 0) {
                #pragma unroll
                for (int half = 0; half < 2; half++) {
                    int row = r0e + half * 8;
                    if (row < M) {
                        uint32_t hp = pack2h(acc[mi][nj][2 * half], acc[mi][nj][2 * half + 1]);
                        *(uint32_t*)((char*)g_qkv + ((size_t)row * N + col) * 2) = hp;
                    }
                }
            } else {
                float b0 = bias[col], b1 = bias[col + 1];
                if (r0e < M)
                    *(float2*)(Cext + (size_t)r0e * N + col) =
                        make_float2(acc[mi][nj][0] + b0, acc[mi][nj][1] + b1);
                if (r0e + 8 < M)
                    *(float2*)(Cext + (size_t)(r0e + 8) * N + col) =
                        make_float2(acc[mi][nj][2] + b0, acc[mi][nj][3] + b1);
            }
        }
    }
}

// ================= tensor-core flash attention (rows 1..1024), fp16 single-pass =================
#define ATT_STG_BYTES 18432u
#define ATT_SMEM      (2 * 18432)

__global__ __launch_bounds__(256, 2) void attn_mma_kernel() {
    extern __shared__ uint32_t sh[];
    int qt = blockIdx.x;
    int bh_ = blockIdx.y;
    int b = bh_ / NH, h = bh_ % NH;

    int tid = threadIdx.x, wid = tid >> 5, lane = tid & 31;
    int g = lane >> 2, t = lane & 3;
    size_t base = (size_t)b * NTOK * QKVW;
    uint32_t sbase = smem_u32(sh);

    // ---- Q fragments: load fp16, scale, re-pack ----
    int row0 = 1 + qt * 128 + wid * 16;
    const float qsc = SCALE * LOG2E;
    const __half* Qp0 = g_qkv + base + (size_t)(row0 + g) * QKVW + h * 64;
    const __half* Qp1 = Qp0 + 8 * QKVW;
    uint32_t qh[4][4];
    #pragma unroll
    for (int kk = 0; kk < 4; kk++) {
        int k0 = kk * 16 + 2 * t;
        #pragma unroll
        for (int fi = 0; fi < 4; fi++) {
            int ko = k0 + (fi >> 1) * 8;
            const __half* p = (fi & 1) ? Qp1 : Qp0;
            __half2 v = *(const __half2*)(p + ko);
            qh[kk][fi] = pack2h(__half2float(v.x) * qsc, __half2float(v.y) * qsc);
        }
    }

    // K+V loader (cp.async)
    auto load_kv = [&](int c, int s) {
        int j0 = c * 64;
        uint32_t sb = sbase + (uint32_t)s * ATT_STG_BYTES;
        #pragma unroll
        for (int l = 0; l < 2; l++) {
            int idx = tid + l * 256;
            int r = idx >> 3, c8 = idx & 7;
            int j = j0 + r;
            uint32_t d = (uint32_t)(r * 36 + c8 * 4) * 4u;
            int ok = (j < NTOK) ? 16 : 0;
            size_t ko = base + (size_t)j * QKVW + DMODEL + h * 64 + c8 * 8;
            size_t vo = ko + DMODEL;
            CP_ASYNC16(sb + d,         (const char*)g_qkv + ko * 2, ok);
            CP_ASYNC16(sb + 9216u + d, (const char*)g_qkv + vo * 2, ok);
        }
    };

    int kfr = lane & 7, kfc = ((lane >> 3) & 1) * 4;
    uint32_t kfoff = (uint32_t)(kfr * 36 + kfc) * 4u;
    int vrow = (lane & 7) + ((lane >> 3) & 1) * 8;
    uint32_t vtoff = (uint32_t)vrow * 144u;

    float O[8][4];
    #pragma unroll
    for (int nj = 0; nj < 8; nj++)
        #pragma unroll
        for (int q = 0; q < 4; q++) O[nj][q] = 0.f;
    float mr0 = -1e30f, mr1 = -1e30f, lr0 = 0.f, lr1 = 0.f;

    load_kv(0, 0);
    CP_COMMIT();

    for (int c = 0; c < 17; c++) {
        int s = c & 1;
        CP_WAIT0();
        __syncthreads();
        if (c + 1 < 17) {
            load_kv(c + 1, s ^ 1);
            CP_COMMIT();
        }
        uint32_t uKH = sbase + (uint32_t)s * ATT_STG_BYTES;
        uint32_t uVH = uKH + 9216u + vtoff;
        int j0 = c * 64;

        // ---- S = Q K^T ----
        float S[8][4];
        #pragma unroll
        for (int nj = 0; nj < 8; nj++)
            #pragma unroll
            for (int q = 0; q < 4; q++) S[nj][q] = 0.f;

        #pragma unroll
        for (int kk = 0; kk < 4; kk++) {
            uint32_t kcb = (uint32_t)(kk * 8) * 4u;
            #pragma unroll
            for (int nj = 0; nj < 8; nj++) {
                uint32_t kb[2];
                ldsm_x2(kb, uKH + (uint32_t)(nj * 8 * 36) * 4u + kcb + kfoff);
                mma_f16(S[nj], qh[kk], kb);
            }
        }

        if (j0 + 64 > NTOK) {
            #pragma unroll
            for (int nj = 0; nj < 8; nj++) {
                int col = j0 + 8 * nj + 2 * t;
                if (col >= NTOK)     { S[nj][0] = -1e30f; S[nj][2] = -1e30f; }
                if (col + 1 >= NTOK) { S[nj][1] = -1e30f; S[nj][3] = -1e30f; }
            }
        }

        // ---- online softmax (log2 domain) ----
        float cm0 = -1e30f, cm1 = -1e30f;
        #pragma unroll
        for (int nj = 0; nj < 8; nj++) {
            cm0 = fmaxf(cm0, fmaxf(S[nj][0], S[nj][1]));
            cm1 = fmaxf(cm1, fmaxf(S[nj][2], S[nj][3]));
        }
        cm0 = fmaxf(cm0, __shfl_xor_sync(0xffffffffu, cm0, 1));
        cm0 = fmaxf(cm0, __shfl_xor_sync(0xffffffffu, cm0, 2));
        cm1 = fmaxf(cm1, __shfl_xor_sync(0xffffffffu, cm1, 1));
        cm1 = fmaxf(cm1, __shfl_xor_sync(0xffffffffu, cm1, 2));
        float mn0 = fmaxf(mr0, cm0), mn1 = fmaxf(mr1, cm1);
        float f0 = exp2f(mr0 - mn0), f1 = exp2f(mr1 - mn1);
        float ps0 = 0.f, ps1 = 0.f;
        #pragma unroll
        for (int nj = 0; nj < 8; nj++) {
            S[nj][0] = exp2f(S[nj][0] - mn0);
            S[nj][1] = exp2f(S[nj][1] - mn0);
            S[nj][2] = exp2f(S[nj][2] - mn1);
            S[nj][3] = exp2f(S[nj][3] - mn1);
            ps0 += S[nj][0] + S[nj][1];
            ps1 += S[nj][2] + S[nj][3];
        }
        ps0 += __shfl_xor_sync(0xffffffffu, ps0, 1);
        ps0 += __shfl_xor_sync(0xffffffffu, ps0, 2);
        ps1 += __shfl_xor_sync(0xffffffffu, ps1, 1);
        ps1 += __shfl_xor_sync(0xffffffffu, ps1, 2);
        lr0 = lr0 * f0 + ps0;
        lr1 = lr1 * f1 + ps1;
        mr0 = mn0; mr1 = mn1;
        #pragma unroll
        for (int nj = 0; nj < 8; nj++) {
            O[nj][0] *= f0; O[nj][1] *= f0;
            O[nj][2] *= f1; O[nj][3] *= f1;
        }

        // ---- O += P @ V ----
        #pragma unroll
        for (int kk = 0; kk < 4; kk++) {
            int j2 = 2 * kk;
            uint32_t ph[4];
            ph[0] = pack2h(S[j2][0],     S[j2][1]);
            ph[1] = pack2h(S[j2][2],     S[j2][3]);
            ph[2] = pack2h(S[j2 + 1][0], S[j2 + 1][1]);
            ph[3] = pack2h(S[j2 + 1][2], S[j2 + 1][3]);
            uint32_t kbase = (uint32_t)(kk * 16) * 144u;
            #pragma unroll
            for (int nj = 0; nj < 8; nj++) {
                uint32_t vh[2];
                ldsm_x2_trans(vh, uVH + kbase + (uint32_t)nj * 16u);
                mma_f16(O[nj], ph, vh);
            }
        }
    }

    // ---- write out (split to g_ctx hi/lo for 22-bit out-proj A) ----
    float i0 = 1.f / lr0, i1 = 1.f / lr1;
    size_t o0 = ((size_t)b * NTOK + row0 + g) * DMODEL + h * 64;
    size_t o1 = o0 + (size_t)8 * DMODEL;
    #pragma unroll
    for (int nj = 0; nj < 8; nj++) {
        int col = 8 * nj + 2 * t;
        uint32_t hp, lp;
        split2h(O[nj][0] * i0, O[nj][1] * i0, hp, lp);
        *(uint32_t*)((char*)g_ctx_hi + (o0 + col) * 2) = hp;
        *(uint32_t*)((char*)g_ctx_lo + (o0 + col) * 2) = lp;
        split2h(O[nj][2] * i1, O[nj][3] * i1, hp, lp);
        *(uint32_t*)((char*)g_ctx_hi + (o1 + col) * 2) = hp;
        *(uint32_t*)((char*)g_ctx_lo + (o1 + col) * 2) = lp;
    }
}

// ---------------- block reduction helpers ----------------
__device__ __forceinline__ float blockReduceSum(float v, float* red) {
    #pragma unroll
    for (int o = 16; o > 0; o >>= 1) v += __shfl_xor_sync(0xffffffffu, v, o);
    int lane = threadIdx.x & 31, w = threadIdx.x >> 5;
    __syncthreads();
    if (lane == 0) red[w] = v;
    __syncthreads();
    if (threadIdx.x == 0) {
        float s = 0.f;
        #pragma unroll
        for (int i = 0; i < 8; i++) s += red[i];
        red[0] = s;
    }
    __syncthreads();
    return red[0];
}

__device__ __forceinline__ float blockReduceMax(float v, float* red) {
    #pragma unroll
    for (int o = 16; o > 0; o >>= 1) v = fmaxf(v, __shfl_xor_sync(0xffffffffu, v, o));
    int lane = threadIdx.x & 31, w = threadIdx.x >> 5;
    __syncthreads();
    if (lane == 0) red[w] = v;
    __syncthreads();
    if (threadIdx.x == 0) {
        float s = -1e30f;
        #pragma unroll
        for (int i = 0; i < 8; i++) s = fmaxf(s, red[i]);
        red[0] = s;
    }
    __syncthreads();
    return red[0];
}

// ---------------- LayerNorm -> fp16 ----------------
__global__ __launch_bounds__(256) void ln_kernel(const float* __restrict__ x,
                                                 const float* __restrict__ w,
                                                 const float* __restrict__ bias) {
    int row = blockIdx.x;
    const float* xr = x + (size_t)row * DMODEL;
    int t = threadIdx.x;
    float v[3];
    float s = 0.f, sq = 0.f;
    #pragma unroll
    for (int i = 0; i < 3; i++) {
        v[i] = xr[t + i * 256];
        s += v[i];
        sq += v[i] * v[i];
    }
    __shared__ float red[32];
    __shared__ float stats[2];
    #pragma unroll
    for (int o = 16; o > 0; o >>= 1) {
        s  += __shfl_xor_sync(0xffffffffu, s, o);
        sq += __shfl_xor_sync(0xffffffffu, sq, o);
    }
    int lane = t & 31, wp = t >> 5;
    if (lane == 0) { red[wp] = s; red[8 + wp] = sq; }
    __syncthreads();
    if (t == 0) {
        float a = 0.f, b2 = 0.f;
        #pragma unroll
        for (int i = 0; i < 8; i++) { a += red[i]; b2 += red[8 + i]; }
        stats[0] = a; stats[1] = b2;
    }
    __syncthreads();
    float mean = stats[0] * (1.f / DMODEL);
    float var  = stats[1] * (1.f / DMODEL) - mean * mean;
    float inv  = rsqrtf(var + EPS);
    #pragma unroll
    for (int i = 0; i < 3; i++) {
        int c = t + i * 256;
        float o = (v[i] - mean) * inv * w[c] + bias[c];
        g_xn[(size_t)row * DMODEL + c] = __float2half_rn(o);
    }
}

// ---------------- CLS row (query row 0) ----------------
__global__ __launch_bounds__(256) void cls_kernel(const float* __restrict__ canny,
                                                  const float* __restrict__ noise) {
    int bh = blockIdx.x;
    int b = bh / NH, h = bh % NH;
    __shared__ float sm[NTOK];
    __shared__ float q0[64];
    __shared__ float red[32];
    __shared__ float part[4][64];
    int tid = threadIdx.x;
    size_t base = (size_t)b * NTOK * QKVW;

    if (tid < 64)
        q0[tid] = __half2float(g_qkv[base + h * 64 + tid]);
    __syncthreads();

    for (int j = tid; j < NTOK; j += 256) {
        size_t ko = base + (size_t)j * QKVW + DMODEL + h * 64;
        float dot = 0.f;
        #pragma unroll
        for (int d2 = 0; d2 < 32; d2++) {
            __half2 kh = *(const __half2*)(g_qkv + ko + 2 * d2);
            dot += q0[2 * d2] * __half2float(kh.x) + q0[2 * d2 + 1] * __half2float(kh.y);
        }
        sm[j] = dot * SCALE;
    }
    __syncthreads();

    float mx = -1e30f, cs = 0.f, ns = 0.f;
    for (int j = tid; j < NPATCH; j += 256) {
        mx = fmaxf(mx, sm[j + 1]);
        cs += canny[(size_t)b * NPATCH + j] + 1.f;
        ns += noise[(size_t)b * NPATCH + j];
    }
    mx = blockReduceMax(mx, red);
    cs = blockReduceSum(cs, red);
    ns = blockReduceSum(ns, red);
    float se = 0.f;
    for (int j = tid; j < NPATCH; j += 256) se += exp2f((sm[j + 1] - mx) * LOG2E);
    se = blockReduceSum(se, red);
    float inv_se = 1.f / se, inv_cs = 1.f / cs, inv_ns = 1.f / ns;
    for (int j = tid; j < NPATCH; j += 256) {
        float a = exp2f((sm[j + 1] - mx) * LOG2E) * inv_se;
        sm[j + 1] = a + (canny[(size_t)b * NPATCH + j] + 1.f) * inv_cs
                      + noise[(size_t)b * NPATCH + j] * inv_ns;
    }
    __syncthreads();

    float mx2 = -1e30f;
    for (int j = tid; j < NTOK; j += 256) mx2 = fmaxf(mx2, sm[j]);
    mx2 = blockReduceMax(mx2, red);
    float se2 = 0.f;
    for (int j = tid; j < NTOK; j += 256) se2 += exp2f((sm[j] - mx2) * LOG2E);
    se2 = blockReduceSum(se2, red);
    float inv2 = 1.f / se2;
    for (int j = tid; j < NTOK; j += 256) sm[j] = exp2f((sm[j] - mx2) * LOG2E) * inv2;
    __syncthreads();

    int d = tid & 63, qp = tid >> 6;
    float acc = 0.f;
    for (int j = qp; j < NTOK; j += 4) {
        size_t vo = base + (size_t)j * QKVW + 2 * DMODEL + h * 64 + d;
        acc += sm[j] * __half2float(g_qkv[vo]);
    }
    part[qp][d] = acc;
    __syncthreads();
    if (tid < 64) {
        float o = part[0][tid] + part[1][tid] + part[2][tid] + part[3][tid];
        __half hh = __float2half_rn(o);
        size_t idx = (size_t)b * NTOK * DMODEL + h * 64 + tid;
        g_ctx_hi[idx] = hh;
        g_ctx_lo[idx] = __float2half_rn(o - __half2float(hh));
    }
}

// ---------------- launch ----------------
extern "C" void kernel_launch(void* const* d_in, const int* in_sizes, int n_in,
                              void* d_out, int out_size) {
    const float* x     = (const float*)d_in[0];
    const float* canny = (const float*)d_in[1];
    const float* noise = (const float*)d_in[2];
    const float* ln_w  = (const float*)d_in[3];
    const float* ln_b  = (const float*)d_in[4];
    const float* w_qkv = (const float*)d_in[5];
    const float* w_out = (const float*)d_in[6];
    const float* b_out = (const float*)d_in[7];
    float* out = (float*)d_out;

    cudaFuncSetAttribute(gemm_mma<0>, cudaFuncAttributeMaxDynamicSharedMemorySize, 2 * 2 * ARR_BYTES);
    cudaFuncSetAttribute(gemm_mma<1>, cudaFuncAttributeMaxDynamicSharedMemorySize, 2 * 3 * ARR_BYTES);
    cudaFuncSetAttribute(attn_mma_kernel, cudaFuncAttributeMaxDynamicSharedMemorySize, ATT_SMEM);

    __half *wqkvT, *woutT;
    cudaGetSymbolAddress((void**)&wqkvT, g_wqkvT);
    cudaGetSymbolAddress((void**)&woutT, g_woutT);

    // 1. LayerNorm (-> fp16)
    ln_kernel<<<MTOT, 256>>>(x, ln_w, ln_b);

    // 1b. transpose weights to [N, K] fp16
    {
        dim3 g1(QKVW / 32, DMODEL / 32);
        transpose_h_kernel<<<g1, 256>>>(w_qkv, wqkvT, DMODEL, QKVW);
        dim3 g2(DMODEL / 32, DMODEL / 32);
        transpose_h_kernel<<<g2, 256>>>(w_out, woutT, DMODEL, DMODEL);
    }

    // 2. QKV GEMM (single-pass fp16) -> g_qkv
    {
        dim3 grid(QKVW / 128, (MTOT + 127) / 128);
        gemm_mma<0><<<grid, 256, 2 * 2 * ARR_BYTES>>>(wqkvT, nullptr, nullptr, MTOT, QKVW, DMODEL);
    }

    // 3. attention rows 1..1024 (2 CTA/SM, single-pass QK/PV)
    {
        dim3 g_attn(8, BATCH * NH);
        attn_mma_kernel<<<g_attn, 256, ATT_SMEM>>>();
    }

    // 4. CLS row with prior injection
    cls_kernel<<<BATCH * NH, 256>>>(canny, noise);

    // 5. output projection (2-pass, ctx 22-bit) -> d_out (fp32 + bias)
    {
        dim3 grid(DMODEL / 128, (MTOT + 127) / 128);
        gemm_mma<1><<<grid, 256, 2 * 3 * ARR_BYTES>>>(woutT, b_out, out, MTOT, DMODEL, DMODEL);
    }
}

// round 14
// speedup vs baseline: 3.0461x; 1.1306x over previous
#include <cuda_runtime.h>
#include <cuda_fp16.h>
#include <math.h>
#include <stdint.h>

#define BATCH   8
#define NTOK    1025
#define DMODEL  768
#define NH      12
#define HDIM    64
#define NPATCH  1024
#define QKVW    (3*DMODEL)          // 2304
#define EPS     1e-5f
#define LOG2E   1.4426950408889634f
#define SCALE   0.03608439182435161f   // 768^-0.5
#define MTOT    (BATCH*NTOK)        // 8200

// ---------------- scratch (device globals; no allocation) ----------------
__device__ __half g_xn   [(size_t)MTOT * DMODEL];
__device__ __half g_qkv  [(size_t)MTOT * QKVW];
__device__ __half g_ctx  [(size_t)MTOT * DMODEL];
__device__ __half g_wqkvT[(size_t)QKVW * DMODEL];
__device__ __half g_woutT[(size_t)DMODEL * DMODEL];

// ---------------- helpers ----------------
__device__ __forceinline__ uint32_t smem_u32(const void* p) {
    uint32_t a;
    asm("{ .reg .u64 t; cvta.to.shared.u64 t, %1; cvt.u32.u64 %0, t; }" : "=r"(a) : "l"(p));
    return a;
}

__device__ __forceinline__ void mma_f16(float* c, const uint32_t* a, const uint32_t* b) {
    asm volatile(
        "mma.sync.aligned.m16n8k16.row.col.f32.f16.f16.f32 "
        "{%0,%1,%2,%3}, {%4,%5,%6,%7}, {%8,%9}, {%0,%1,%2,%3};"
        : "+f"(c[0]), "+f"(c[1]), "+f"(c[2]), "+f"(c[3])
        : "r"(a[0]), "r"(a[1]), "r"(a[2]), "r"(a[3]), "r"(b[0]), "r"(b[1]));
}

__device__ __forceinline__ void ldsm_x4(uint32_t* f, uint32_t addr) {
    asm volatile("ldmatrix.sync.aligned.m8n8.x4.shared.b16 {%0,%1,%2,%3}, [%4];"
        : "=r"(f[0]), "=r"(f[1]), "=r"(f[2]), "=r"(f[3]) : "r"(addr));
}
__device__ __forceinline__ void ldsm_x2(uint32_t* f, uint32_t addr) {
    asm volatile("ldmatrix.sync.aligned.m8n8.x2.shared.b16 {%0,%1}, [%2];"
        : "=r"(f[0]), "=r"(f[1]) : "r"(addr));
}
__device__ __forceinline__ void ldsm_x2_trans(uint32_t* f, uint32_t addr) {
    asm volatile("ldmatrix.sync.aligned.m8n8.x2.trans.shared.b16 {%0,%1}, [%2];"
        : "=r"(f[0]), "=r"(f[1]) : "r"(addr));
}

#define CP_ASYNC16(dst, src, nbytes) \
    asm volatile("cp.async.cg.shared.global [%0], [%1], 16, %2;" \
                 :: "r"(dst), "l"(src), "r"(nbytes))
#define CP_COMMIT() asm volatile("cp.async.commit_group;")
#define CP_WAIT1()  asm volatile("cp.async.wait_group 1;")
#define CP_WAIT0()  asm volatile("cp.async.wait_group 0;")

// plain fp16 pack of two floats
__device__ __forceinline__ uint32_t pack2h(float a, float b) {
    __half ha = __float2half_rn(a), hb = __float2half_rn(b);
    return (uint32_t)__half_as_ushort(ha) | ((uint32_t)__half_as_ushort(hb) << 16);
}

// ---------------- weight transpose (fp16): dst[N,K] = fp16(src[K,N]) ----------------
__global__ __launch_bounds__(256) void transpose_h_kernel(const float* __restrict__ src,
                                                          __half* __restrict__ dh,
                                                          int K, int N) {
    __shared__ float t[32][33];
    int nx = blockIdx.x * 32, kx = blockIdx.y * 32;
    int lx = threadIdx.x & 31, ly = threadIdx.x >> 5;
    #pragma unroll
    for (int i = ly; i < 32; i += 8)
        t[i][lx] = src[(size_t)(kx + i) * N + nx + lx];
    __syncthreads();
    #pragma unroll
    for (int i = ly; i < 32; i += 8)
        dh[(size_t)(nx + i) * K + kx + lx] = __float2half_rn(t[lx][i]);
}

// ================= tensor-core GEMM (single-pass fp16, 3-stage cp.async, 2 CTA/SM) =================
// SEL=0: A=g_xn -> g_qkv fp16. SEL=1: A=g_ctx -> fp32 + bias.
#define SM_STRIDE 20
#define ARR_BYTES (128 * SM_STRIDE * 4)     // 10240
#define STG_BYTES (2 * ARR_BYTES)           // 20480
#define GEMM_SMEM (3 * STG_BYTES)           // 61440

template<int SEL>
__global__ __launch_bounds__(256, 2) void gemm_mma(const __half* __restrict__ Bmat,
                                                   const float* __restrict__ bias,
                                                   float* __restrict__ Cext,
                                                   int M, int N, int K) {
    const __half* A = (SEL == 0) ? g_xn : g_ctx;

    extern __shared__ char smem[];
    uint32_t sbase = smem_u32(smem);

    int tid = threadIdx.x;
    int wid = tid >> 5, lane = tid & 31;
    int g = lane >> 2, t = lane & 3;
    int wm = wid & 1, wn = wid >> 1;
    int m0 = blockIdx.y * 128, n0 = blockIdx.x * 128;
    int mw = wm * 64, nw = wn * 32;

    int rA = (lane & 7) + ((lane >> 3) & 1) * 8;
    int cA = (lane >> 4) * 4;
    uint32_t aoff = (uint32_t)(rA * SM_STRIDE + cA) * 4u;
    int rB = lane & 7;
    int cB = ((lane >> 3) & 1) * 4;
    uint32_t boff = (uint32_t)(rB * SM_STRIDE + cB) * 4u;

    int lr = tid >> 2, lq = tid & 3;

    float acc[4][4][4];
    #pragma unroll
    for (int i = 0; i < 4; i++)
        #pragma unroll
        for (int j = 0; j < 4; j++)
            #pragma unroll
            for (int q = 0; q < 4; q++) acc[i][j][q] = 0.f;

    int nch = K / 32;   // 24

    auto load_stage = [&](int ch, int s) {
        int kb = ch * 32;
        uint32_t so = sbase + (uint32_t)s * STG_BYTES;
        #pragma unroll
        for (int l = 0; l < 2; l++) {
            int r = lr + l * 64;
            uint32_t d = (uint32_t)(r * SM_STRIDE + lq * 4) * 4u;
            int okA = (m0 + r < M) ? 16 : 0;
            size_t ao = (size_t)(m0 + r) * K + kb + lq * 8;
            size_t bo = (size_t)(n0 + r) * K + kb + lq * 8;
            CP_ASYNC16(so + d,             A    + ao, okA);
            CP_ASYNC16(so + ARR_BYTES + d, Bmat + bo, 16);
        }
    };

    load_stage(0, 0);
    CP_COMMIT();
    load_stage(1, 1);
    CP_COMMIT();

    for (int ch = 0; ch < nch; ch++) {
        int s = ch % 3;
        if (ch + 1 < nch) CP_WAIT1(); else CP_WAIT0();
        __syncthreads();
        if (ch + 2 < nch) {
            load_stage(ch + 2, (ch + 2) % 3);
            CP_COMMIT();
        }

        uint32_t uA = sbase + (uint32_t)s * STG_BYTES;
        uint32_t uB = uA + ARR_BYTES;

        uint32_t ah[2][4][4], bh[2][4][2];
        #pragma unroll
        for (int kk = 0; kk < 2; kk++) {
            uint32_t kcb = (uint32_t)(kk * 8) * 4u;
            #pragma unroll
            for (int mi = 0; mi < 4; mi++) {
                uint32_t base = (uint32_t)((mw + mi * 16) * SM_STRIDE) * 4u + kcb + aoff;
                ldsm_x4(ah[kk][mi], uA + base);
            }
            #pragma unroll
            for (int nj = 0; nj < 4; nj++) {
                uint32_t base = (uint32_t)((nw + nj * 8) * SM_STRIDE) * 4u + kcb + boff;
                ldsm_x2(bh[kk][nj], uB + base);
            }
        }
        #pragma unroll
        for (int kk = 0; kk < 2; kk++)
            #pragma unroll
            for (int mi = 0; mi < 4; mi++)
                #pragma unroll
                for (int nj = 0; nj < 4; nj++)
                    mma_f16(acc[mi][nj], ah[kk][mi], bh[kk][nj]);
    }

    // ---- epilogue ----
    #pragma unroll
    for (int mi = 0; mi < 4; mi++) {
        int r0e = m0 + mw + mi * 16 + g;
        #pragma unroll
        for (int nj = 0; nj < 4; nj++) {
            int col = n0 + nw + nj * 8 + t * 2;
            if (SEL == 0) {
                #pragma unroll
                for (int half = 0; half < 2; half++) {
                    int row = r0e + half * 8;
                    if (row < M) {
                        uint32_t hp = pack2h(acc[mi][nj][2 * half], acc[mi][nj][2 * half + 1]);
                        *(uint32_t*)((char*)g_qkv + ((size_t)row * N + col) * 2) = hp;
                    }
                }
            } else {
                float b0 = bias[col], b1 = bias[col + 1];
                if (r0e < M)
                    *(float2*)(Cext + (size_t)r0e * N + col) =
                        make_float2(acc[mi][nj][0] + b0, acc[mi][nj][1] + b1);
                if (r0e + 8 < M)
                    *(float2*)(Cext + (size_t)(r0e + 8) * N + col) =
                        make_float2(acc[mi][nj][2] + b0, acc[mi][nj][3] + b1);
            }
        }
    }
}

// ================= tensor-core flash attention (rows 1..1024), fp16, 3-stage =================
#define ATT_STG_BYTES 18432u
#define ATT_SMEM      (3 * 18432)

__global__ __launch_bounds__(256, 2) void attn_mma_kernel() {
    extern __shared__ uint32_t sh[];
    int qt = blockIdx.x;
    int bh_ = blockIdx.y;
    int b = bh_ / NH, h = bh_ % NH;

    int tid = threadIdx.x, wid = tid >> 5, lane = tid & 31;
    int g = lane >> 2, t = lane & 3;
    size_t base = (size_t)b * NTOK * QKVW;
    uint32_t sbase = smem_u32(sh);

    // ---- Q fragments: load fp16, scale, re-pack ----
    int row0 = 1 + qt * 128 + wid * 16;
    const float qsc = SCALE * LOG2E;
    const __half* Qp0 = g_qkv + base + (size_t)(row0 + g) * QKVW + h * 64;
    const __half* Qp1 = Qp0 + 8 * QKVW;
    uint32_t qh[4][4];
    #pragma unroll
    for (int kk = 0; kk < 4; kk++) {
        int k0 = kk * 16 + 2 * t;
        #pragma unroll
        for (int fi = 0; fi < 4; fi++) {
            int ko = k0 + (fi >> 1) * 8;
            const __half* p = (fi & 1) ? Qp1 : Qp0;
            __half2 v = *(const __half2*)(p + ko);
            qh[kk][fi] = pack2h(__half2float(v.x) * qsc, __half2float(v.y) * qsc);
        }
    }

    // K+V loader (cp.async)
    auto load_kv = [&](int c, int s) {
        int j0 = c * 64;
        uint32_t sb = sbase + (uint32_t)s * ATT_STG_BYTES;
        #pragma unroll
        for (int l = 0; l < 2; l++) {
            int idx = tid + l * 256;
            int r = idx >> 3, c8 = idx & 7;
            int j = j0 + r;
            uint32_t d = (uint32_t)(r * 36 + c8 * 4) * 4u;
            int ok = (j < NTOK) ? 16 : 0;
            size_t ko = base + (size_t)j * QKVW + DMODEL + h * 64 + c8 * 8;
            size_t vo = ko + DMODEL;
            CP_ASYNC16(sb + d,         (const char*)g_qkv + ko * 2, ok);
            CP_ASYNC16(sb + 9216u + d, (const char*)g_qkv + vo * 2, ok);
        }
    };

    int kfr = lane & 7, kfc = ((lane >> 3) & 1) * 4;
    uint32_t kfoff = (uint32_t)(kfr * 36 + kfc) * 4u;
    int vrow = (lane & 7) + ((lane >> 3) & 1) * 8;
    uint32_t vtoff = (uint32_t)vrow * 144u;

    float O[8][4];
    #pragma unroll
    for (int nj = 0; nj < 8; nj++)
        #pragma unroll
        for (int q = 0; q < 4; q++) O[nj][q] = 0.f;
    float mr0 = -1e30f, mr1 = -1e30f, lr0 = 0.f, lr1 = 0.f;

    load_kv(0, 0);
    CP_COMMIT();
    load_kv(1, 1);
    CP_COMMIT();

    for (int c = 0; c < 17; c++) {
        int s = c % 3;
        if (c + 1 < 17) CP_WAIT1(); else CP_WAIT0();
        __syncthreads();
        if (c + 2 < 17) {
            load_kv(c + 2, (c + 2) % 3);
            CP_COMMIT();
        }
        uint32_t uKH = sbase + (uint32_t)s * ATT_STG_BYTES;
        uint32_t uVH = uKH + 9216u + vtoff;
        int j0 = c * 64;

        // ---- S = Q K^T ----
        float S[8][4];
        #pragma unroll
        for (int nj = 0; nj < 8; nj++)
            #pragma unroll
            for (int q = 0; q < 4; q++) S[nj][q] = 0.f;

        #pragma unroll
        for (int kk = 0; kk < 4; kk++) {
            uint32_t kcb = (uint32_t)(kk * 8) * 4u;
            #pragma unroll
            for (int nj = 0; nj < 8; nj++) {
                uint32_t kb[2];
                ldsm_x2(kb, uKH + (uint32_t)(nj * 8 * 36) * 4u + kcb + kfoff);
                mma_f16(S[nj], qh[kk], kb);
            }
        }

        if (j0 + 64 > NTOK) {
            #pragma unroll
            for (int nj = 0; nj < 8; nj++) {
                int col = j0 + 8 * nj + 2 * t;
                if (col >= NTOK)     { S[nj][0] = -1e30f; S[nj][2] = -1e30f; }
                if (col + 1 >= NTOK) { S[nj][1] = -1e30f; S[nj][3] = -1e30f; }
            }
        }

        // ---- online softmax (log2 domain) ----
        float cm0 = -1e30f, cm1 = -1e30f;
        #pragma unroll
        for (int nj = 0; nj < 8; nj++) {
            cm0 = fmaxf(cm0, fmaxf(S[nj][0], S[nj][1]));
            cm1 = fmaxf(cm1, fmaxf(S[nj][2], S[nj][3]));
        }
        cm0 = fmaxf(cm0, __shfl_xor_sync(0xffffffffu, cm0, 1));
        cm0 = fmaxf(cm0, __shfl_xor_sync(0xffffffffu, cm0, 2));
        cm1 = fmaxf(cm1, __shfl_xor_sync(0xffffffffu, cm1, 1));
        cm1 = fmaxf(cm1, __shfl_xor_sync(0xffffffffu, cm1, 2));
        float mn0 = fmaxf(mr0, cm0), mn1 = fmaxf(mr1, cm1);
        float f0 = exp2f(mr0 - mn0), f1 = exp2f(mr1 - mn1);
        float ps0 = 0.f, ps1 = 0.f;
        #pragma unroll
        for (int nj = 0; nj < 8; nj++) {
            S[nj][0] = exp2f(S[nj][0] - mn0);
            S[nj][1] = exp2f(S[nj][1] - mn0);
            S[nj][2] = exp2f(S[nj][2] - mn1);
            S[nj][3] = exp2f(S[nj][3] - mn1);
            ps0 += S[nj][0] + S[nj][1];
            ps1 += S[nj][2] + S[nj][3];
        }
        ps0 += __shfl_xor_sync(0xffffffffu, ps0, 1);
        ps0 += __shfl_xor_sync(0xffffffffu, ps0, 2);
        ps1 += __shfl_xor_sync(0xffffffffu, ps1, 1);
        ps1 += __shfl_xor_sync(0xffffffffu, ps1, 2);
        lr0 = lr0 * f0 + ps0;
        lr1 = lr1 * f1 + ps1;
        mr0 = mn0; mr1 = mn1;
        #pragma unroll
        for (int nj = 0; nj < 8; nj++) {
            O[nj][0] *= f0; O[nj][1] *= f0;
            O[nj][2] *= f1; O[nj][3] *= f1;
        }

        // ---- O += P @ V ----
        #pragma unroll
        for (int kk = 0; kk < 4; kk++) {
            int j2 = 2 * kk;
            uint32_t ph[4];
            ph[0] = pack2h(S[j2][0],     S[j2][1]);
            ph[1] = pack2h(S[j2][2],     S[j2][3]);
            ph[2] = pack2h(S[j2 + 1][0], S[j2 + 1][1]);
            ph[3] = pack2h(S[j2 + 1][2], S[j2 + 1][3]);
            uint32_t kbase = (uint32_t)(kk * 16) * 144u;
            #pragma unroll
            for (int nj = 0; nj < 8; nj++) {
                uint32_t vh[2];
                ldsm_x2_trans(vh, uVH + kbase + (uint32_t)nj * 16u);
                mma_f16(O[nj], ph, vh);
            }
        }
    }

    // ---- write out (fp16 ctx) ----
    float i0 = 1.f / lr0, i1 = 1.f / lr1;
    size_t o0 = ((size_t)b * NTOK + row0 + g) * DMODEL + h * 64;
    size_t o1 = o0 + (size_t)8 * DMODEL;
    #pragma unroll
    for (int nj = 0; nj < 8; nj++) {
        int col = 8 * nj + 2 * t;
        *(uint32_t*)((char*)g_ctx + (o0 + col) * 2) = pack2h(O[nj][0] * i0, O[nj][1] * i0);
        *(uint32_t*)((char*)g_ctx + (o1 + col) * 2) = pack2h(O[nj][2] * i1, O[nj][3] * i1);
    }
}

// ---------------- block reduction helpers ----------------
__device__ __forceinline__ float blockReduceSum(float v, float* red) {
    #pragma unroll
    for (int o = 16; o > 0; o >>= 1) v += __shfl_xor_sync(0xffffffffu, v, o);
    int lane = threadIdx.x & 31, w = threadIdx.x >> 5;
    __syncthreads();
    if (lane == 0) red[w] = v;
    __syncthreads();
    if (threadIdx.x == 0) {
        float s = 0.f;
        #pragma unroll
        for (int i = 0; i < 8; i++) s += red[i];
        red[0] = s;
    }
    __syncthreads();
    return red[0];
}

__device__ __forceinline__ float blockReduceMax(float v, float* red) {
    #pragma unroll
    for (int o = 16; o > 0; o >>= 1) v = fmaxf(v, __shfl_xor_sync(0xffffffffu, v, o));
    int lane = threadIdx.x & 31, w = threadIdx.x >> 5;
    __syncthreads();
    if (lane == 0) red[w] = v;
    __syncthreads();
    if (threadIdx.x == 0) {
        float s = -1e30f;
        #pragma unroll
        for (int i = 0; i < 8; i++) s = fmaxf(s, red[i]);
        red[0] = s;
    }
    __syncthreads();
    return red[0];
}

// ---------------- LayerNorm -> fp16 ----------------
__global__ __launch_bounds__(256) void ln_kernel(const float* __restrict__ x,
                                                 const float* __restrict__ w,
                                                 const float* __restrict__ bias) {
    int row = blockIdx.x;
    const float* xr = x + (size_t)row * DMODEL;
    int t = threadIdx.x;
    float v[3];
    float s = 0.f, sq = 0.f;
    #pragma unroll
    for (int i = 0; i < 3; i++) {
        v[i] = xr[t + i * 256];
        s += v[i];
        sq += v[i] * v[i];
    }
    __shared__ float red[32];
    __shared__ float stats[2];
    #pragma unroll
    for (int o = 16; o > 0; o >>= 1) {
        s  += __shfl_xor_sync(0xffffffffu, s, o);
        sq += __shfl_xor_sync(0xffffffffu, sq, o);
    }
    int lane = t & 31, wp = t >> 5;
    if (lane == 0) { red[wp] = s; red[8 + wp] = sq; }
    __syncthreads();
    if (t == 0) {
        float a = 0.f, b2 = 0.f;
        #pragma unroll
        for (int i = 0; i < 8; i++) { a += red[i]; b2 += red[8 + i]; }
        stats[0] = a; stats[1] = b2;
    }
    __syncthreads();
    float mean = stats[0] * (1.f / DMODEL);
    float var  = stats[1] * (1.f / DMODEL) - mean * mean;
    float inv  = rsqrtf(var + EPS);
    #pragma unroll
    for (int i = 0; i < 3; i++) {
        int c = t + i * 256;
        float o = (v[i] - mean) * inv * w[c] + bias[c];
        g_xn[(size_t)row * DMODEL + c] = __float2half_rn(o);
    }
}

// ---------------- CLS row (query row 0) ----------------
__global__ __launch_bounds__(256) void cls_kernel(const float* __restrict__ canny,
                                                  const float* __restrict__ noise) {
    int bh = blockIdx.x;
    int b = bh / NH, h = bh % NH;
    __shared__ float sm[NTOK];
    __shared__ float q0[64];
    __shared__ float red[32];
    __shared__ float part[4][64];
    int tid = threadIdx.x;
    size_t base = (size_t)b * NTOK * QKVW;

    if (tid < 64)
        q0[tid] = __half2float(g_qkv[base + h * 64 + tid]);
    __syncthreads();

    for (int j = tid; j < NTOK; j += 256) {
        size_t ko = base + (size_t)j * QKVW + DMODEL + h * 64;
        float dot = 0.f;
        #pragma unroll
        for (int d2 = 0; d2 < 32; d2++) {
            __half2 kh = *(const __half2*)(g_qkv + ko + 2 * d2);
            dot += q0[2 * d2] * __half2float(kh.x) + q0[2 * d2 + 1] * __half2float(kh.y);
        }
        sm[j] = dot * SCALE;
    }
    __syncthreads();

    float mx = -1e30f, cs = 0.f, ns = 0.f;
    for (int j = tid; j < NPATCH; j += 256) {
        mx = fmaxf(mx, sm[j + 1]);
        cs += canny[(size_t)b * NPATCH + j] + 1.f;
        ns += noise[(size_t)b * NPATCH + j];
    }
    mx = blockReduceMax(mx, red);
    cs = blockReduceSum(cs, red);
    ns = blockReduceSum(ns, red);
    float se = 0.f;
    for (int j = tid; j < NPATCH; j += 256) se += exp2f((sm[j + 1] - mx) * LOG2E);
    se = blockReduceSum(se, red);
    float inv_se = 1.f / se, inv_cs = 1.f / cs, inv_ns = 1.f / ns;
    for (int j = tid; j < NPATCH; j += 256) {
        float a = exp2f((sm[j + 1] - mx) * LOG2E) * inv_se;
        sm[j + 1] = a + (canny[(size_t)b * NPATCH + j] + 1.f) * inv_cs
                      + noise[(size_t)b * NPATCH + j] * inv_ns;
    }
    __syncthreads();

    float mx2 = -1e30f;
    for (int j = tid; j < NTOK; j += 256) mx2 = fmaxf(mx2, sm[j]);
    mx2 = blockReduceMax(mx2, red);
    float se2 = 0.f;
    for (int j = tid; j < NTOK; j += 256) se2 += exp2f((sm[j] - mx2) * LOG2E);
    se2 = blockReduceSum(se2, red);
    float inv2 = 1.f / se2;
    for (int j = tid; j < NTOK; j += 256) sm[j] = exp2f((sm[j] - mx2) * LOG2E) * inv2;
    __syncthreads();

    int d = tid & 63, qp = tid >> 6;
    float acc = 0.f;
    for (int j = qp; j < NTOK; j += 4) {
        size_t vo = base + (size_t)j * QKVW + 2 * DMODEL + h * 64 + d;
        acc += sm[j] * __half2float(g_qkv[vo]);
    }
    part[qp][d] = acc;
    __syncthreads();
    if (tid < 64) {
        float o = part[0][tid] + part[1][tid] + part[2][tid] + part[3][tid];
        g_ctx[(size_t)b * NTOK * DMODEL + h * 64 + tid] = __float2half_rn(o);
    }
}

// ---------------- launch ----------------
extern "C" void kernel_launch(void* const* d_in, const int* in_sizes, int n_in,
                              void* d_out, int out_size) {
    const float* x     = (const float*)d_in[0];
    const float* canny = (const float*)d_in[1];
    const float* noise = (const float*)d_in[2];
    const float* ln_w  = (const float*)d_in[3];
    const float* ln_b  = (const float*)d_in[4];
    const float* w_qkv = (const float*)d_in[5];
    const float* w_out = (const float*)d_in[6];
    const float* b_out = (const float*)d_in[7];
    float* out = (float*)d_out;

    cudaFuncSetAttribute(gemm_mma<0>, cudaFuncAttributeMaxDynamicSharedMemorySize, GEMM_SMEM);
    cudaFuncSetAttribute(gemm_mma<1>, cudaFuncAttributeMaxDynamicSharedMemorySize, GEMM_SMEM);
    cudaFuncSetAttribute(attn_mma_kernel, cudaFuncAttributeMaxDynamicSharedMemorySize, ATT_SMEM);

    __half *wqkvT, *woutT;
    cudaGetSymbolAddress((void**)&wqkvT, g_wqkvT);
    cudaGetSymbolAddress((void**)&woutT, g_woutT);

    // 1. LayerNorm (-> fp16)
    ln_kernel<<<MTOT, 256>>>(x, ln_w, ln_b);

    // 1b. transpose weights to [N, K] fp16
    {
        dim3 g1(QKVW / 32, DMODEL / 32);
        transpose_h_kernel<<<g1, 256>>>(w_qkv, wqkvT, DMODEL, QKVW);
        dim3 g2(DMODEL / 32, DMODEL / 32);
        transpose_h_kernel<<<g2, 256>>>(w_out, woutT, DMODEL, DMODEL);
    }

    // 2. QKV GEMM (single-pass fp16, 3-stage) -> g_qkv
    {
        dim3 grid(QKVW / 128, (MTOT + 127) / 128);
        gemm_mma<0><<<grid, 256, GEMM_SMEM>>>(wqkvT, nullptr, nullptr, MTOT, QKVW, DMODEL);
    }

    // 3. attention rows 1..1024 (2 CTA/SM, 3-stage)
    {
        dim3 g_attn(8, BATCH * NH);
        attn_mma_kernel<<<g_attn, 256, ATT_SMEM>>>();
    }

    // 4. CLS row with prior injection
    cls_kernel<<<BATCH * NH, 256>>>(canny, noise);

    // 5. output projection (single-pass fp16, 3-stage) -> d_out (fp32 + bias)
    {
        dim3 grid(DMODEL / 128, (MTOT + 127) / 128);
        gemm_mma<1><<<grid, 256, GEMM_SMEM>>>(woutT, b_out, out, MTOT, DMODEL, DMODEL);
    }
}

// round 15
// speedup vs baseline: 3.1791x; 1.0436x over previous
#include <cuda_runtime.h>
#include <cuda_fp16.h>
#include <math.h>
#include <stdint.h>

#define BATCH   8
#define NTOK    1025
#define DMODEL  768
#define NH      12
#define HDIM    64
#define NPATCH  1024
#define QKVW    (3*DMODEL)          // 2304
#define EPS     1e-5f
#define LOG2E   1.4426950408889634f
#define SCALE   0.03608439182435161f   // 768^-0.5
#define MTOT    (BATCH*NTOK)        // 8200

// ---------------- scratch (device globals; no allocation) ----------------
__device__ __half g_xn   [(size_t)MTOT * DMODEL];
__device__ __half g_qkv  [(size_t)MTOT * QKVW];
__device__ __half g_ctx  [(size_t)MTOT * DMODEL];
__device__ __half g_wqkvT[(size_t)QKVW * DMODEL];
__device__ __half g_woutT[(size_t)DMODEL * DMODEL];

// ---------------- helpers ----------------
__device__ __forceinline__ uint32_t smem_u32(const void* p) {
    uint32_t a;
    asm("{ .reg .u64 t; cvta.to.shared.u64 t, %1; cvt.u32.u64 %0, t; }" : "=r"(a) : "l"(p));
    return a;
}

__device__ __forceinline__ void mma_f16(float* c, const uint32_t* a, const uint32_t* b) {
    asm volatile(
        "mma.sync.aligned.m16n8k16.row.col.f32.f16.f16.f32 "
        "{%0,%1,%2,%3}, {%4,%5,%6,%7}, {%8,%9}, {%0,%1,%2,%3};"
        : "+f"(c[0]), "+f"(c[1]), "+f"(c[2]), "+f"(c[3])
        : "r"(a[0]), "r"(a[1]), "r"(a[2]), "r"(a[3]), "r"(b[0]), "r"(b[1]));
}

__device__ __forceinline__ void ldsm_x4(uint32_t* f, uint32_t addr) {
    asm volatile("ldmatrix.sync.aligned.m8n8.x4.shared.b16 {%0,%1,%2,%3}, [%4];"
        : "=r"(f[0]), "=r"(f[1]), "=r"(f[2]), "=r"(f[3]) : "r"(addr));
}
__device__ __forceinline__ void ldsm_x2(uint32_t* f, uint32_t addr) {
    asm volatile("ldmatrix.sync.aligned.m8n8.x2.shared.b16 {%0,%1}, [%2];"
        : "=r"(f[0]), "=r"(f[1]) : "r"(addr));
}
__device__ __forceinline__ void ldsm_x2_trans(uint32_t* f, uint32_t addr) {
    asm volatile("ldmatrix.sync.aligned.m8n8.x2.trans.shared.b16 {%0,%1}, [%2];"
        : "=r"(f[0]), "=r"(f[1]) : "r"(addr));
}

#define CP_ASYNC16(dst, src, nbytes) \
    asm volatile("cp.async.cg.shared.global [%0], [%1], 16, %2;" \
                 :: "r"(dst), "l"(src), "r"(nbytes))
#define CP_COMMIT() asm volatile("cp.async.commit_group;")
#define CP_WAIT1()  asm volatile("cp.async.wait_group 1;")
#define CP_WAIT0()  asm volatile("cp.async.wait_group 0;")

// plain fp16 pack of two floats
__device__ __forceinline__ uint32_t pack2h(float a, float b) {
    __half ha = __float2half_rn(a), hb = __float2half_rn(b);
    return (uint32_t)__half_as_ushort(ha) | ((uint32_t)__half_as_ushort(hb) << 16);
}

// ---------------- weight transpose (fp16): dst[N,K] = fp16(src[K,N]) ----------------
__global__ __launch_bounds__(256) void transpose_h_kernel(const float* __restrict__ src,
                                                          __half* __restrict__ dh,
                                                          int K, int N) {
    __shared__ float t[32][33];
    int nx = blockIdx.x * 32, kx = blockIdx.y * 32;
    int lx = threadIdx.x & 31, ly = threadIdx.x >> 5;
    #pragma unroll
    for (int i = ly; i < 32; i += 8)
        t[i][lx] = src[(size_t)(kx + i) * N + nx + lx];
    __syncthreads();
    #pragma unroll
    for (int i = ly; i < 32; i += 8)
        dh[(size_t)(nx + i) * K + kx + lx] = __float2half_rn(t[lx][i]);
}

// ================= tensor-core GEMM (fp16, BK=64, 3-stage cp.async, 2 CTA/SM) =================
// SEL=0: A=g_xn -> g_qkv fp16. SEL=1: A=g_ctx -> fp32 + bias.
#define SM_STRIDE 36
#define ARR_BYTES (128 * SM_STRIDE * 4)     // 18432
#define STG_BYTES (2 * ARR_BYTES)           // 36864
#define GEMM_SMEM (3 * STG_BYTES)           // 110592

template<int SEL>
__global__ __launch_bounds__(256, 2) void gemm_mma(const __half* __restrict__ Bmat,
                                                   const float* __restrict__ bias,
                                                   float* __restrict__ Cext,
                                                   int M, int N, int K) {
    const __half* A = (SEL == 0) ? g_xn : g_ctx;

    extern __shared__ char smem[];
    uint32_t sbase = smem_u32(smem);

    int tid = threadIdx.x;
    int wid = tid >> 5, lane = tid & 31;
    int g = lane >> 2, t = lane & 3;
    int wm = wid & 1, wn = wid >> 1;
    int m0 = blockIdx.y * 128, n0 = blockIdx.x * 128;
    int mw = wm * 64, nw = wn * 32;

    int rA = (lane & 7) + ((lane >> 3) & 1) * 8;
    int cA = (lane >> 4) * 4;
    uint32_t aoff = (uint32_t)(rA * SM_STRIDE + cA) * 4u;
    int rB = lane & 7;
    int cB = ((lane >> 3) & 1) * 4;
    uint32_t boff = (uint32_t)(rB * SM_STRIDE + cB) * 4u;

    float acc[4][4][4];
    #pragma unroll
    for (int i = 0; i < 4; i++)
        #pragma unroll
        for (int j = 0; j < 4; j++)
            #pragma unroll
            for (int q = 0; q < 4; q++) acc[i][j][q] = 0.f;

    int nch = K / 64;   // 12

    // stage loader: 128 rows x 64 halfs per array -> 8 x 16B per row
    auto load_stage = [&](int ch, int s) {
        int kb = ch * 64;
        uint32_t so = sbase + (uint32_t)s * STG_BYTES;
        #pragma unroll
        for (int l = 0; l < 4; l++) {
            int idx = tid + l * 256;
            int r = idx >> 3, c8 = idx & 7;
            uint32_t d = (uint32_t)(r * SM_STRIDE + c8 * 4) * 4u;
            int okA = (m0 + r < M) ? 16 : 0;
            size_t ao = (size_t)(m0 + r) * K + kb + c8 * 8;
            size_t bo = (size_t)(n0 + r) * K + kb + c8 * 8;
            CP_ASYNC16(so + d,             A    + ao, okA);
            CP_ASYNC16(so + ARR_BYTES + d, Bmat + bo, 16);
        }
    };

    load_stage(0, 0);
    CP_COMMIT();
    load_stage(1, 1);
    CP_COMMIT();

    for (int ch = 0; ch < nch; ch++) {
        int s = ch % 3;
        if (ch + 1 < nch) CP_WAIT1(); else CP_WAIT0();
        __syncthreads();
        if (ch + 2 < nch) {
            load_stage(ch + 2, (ch + 2) % 3);
            CP_COMMIT();
        }

        uint32_t uA = sbase + (uint32_t)s * STG_BYTES;
        uint32_t uB = uA + ARR_BYTES;

        #pragma unroll
        for (int kk = 0; kk < 4; kk++) {
            uint32_t kcb = (uint32_t)(kk * 8) * 4u;
            uint32_t ah[4][4], bh[4][2];
            #pragma unroll
            for (int mi = 0; mi < 4; mi++) {
                uint32_t base = (uint32_t)((mw + mi * 16) * SM_STRIDE) * 4u + kcb + aoff;
                ldsm_x4(ah[mi], uA + base);
            }
            #pragma unroll
            for (int nj = 0; nj < 4; nj++) {
                uint32_t base = (uint32_t)((nw + nj * 8) * SM_STRIDE) * 4u + kcb + boff;
                ldsm_x2(bh[nj], uB + base);
            }
            #pragma unroll
            for (int mi = 0; mi < 4; mi++)
                #pragma unroll
                for (int nj = 0; nj < 4; nj++)
                    mma_f16(acc[mi][nj], ah[mi], bh[nj]);
        }
    }

    // ---- epilogue ----
    #pragma unroll
    for (int mi = 0; mi < 4; mi++) {
        int r0e = m0 + mw + mi * 16 + g;
        #pragma unroll
        for (int nj = 0; nj < 4; nj++) {
            int col = n0 + nw + nj * 8 + t * 2;
            if (SEL == 0) {
                #pragma unroll
                for (int half = 0; half < 2; half++) {
                    int row = r0e + half * 8;
                    if (row < M) {
                        uint32_t hp = pack2h(acc[mi][nj][2 * half], acc[mi][nj][2 * half + 1]);
                        *(uint32_t*)((char*)g_qkv + ((size_t)row * N + col) * 2) = hp;
                    }
                }
            } else {
                float b0 = bias[col], b1 = bias[col + 1];
                if (r0e < M)
                    *(float2*)(Cext + (size_t)r0e * N + col) =
                        make_float2(acc[mi][nj][0] + b0, acc[mi][nj][1] + b1);
                if (r0e + 8 < M)
                    *(float2*)(Cext + (size_t)(r0e + 8) * N + col) =
                        make_float2(acc[mi][nj][2] + b0, acc[mi][nj][3] + b1);
            }
        }
    }
}

// ================= tensor-core flash attention (rows 1..1024), fp16, 3-stage =================
#define ATT_STG_BYTES 18432u
#define ATT_SMEM      (3 * 18432)

__global__ __launch_bounds__(256, 2) void attn_mma_kernel() {
    extern __shared__ uint32_t sh[];
    int qt = blockIdx.x;
    int bh_ = blockIdx.y;
    int b = bh_ / NH, h = bh_ % NH;

    int tid = threadIdx.x, wid = tid >> 5, lane = tid & 31;
    int g = lane >> 2, t = lane & 3;
    size_t base = (size_t)b * NTOK * QKVW;
    uint32_t sbase = smem_u32(sh);

    // ---- Q fragments: load fp16, scale, re-pack ----
    int row0 = 1 + qt * 128 + wid * 16;
    const float qsc = SCALE * LOG2E;
    const __half* Qp0 = g_qkv + base + (size_t)(row0 + g) * QKVW + h * 64;
    const __half* Qp1 = Qp0 + 8 * QKVW;
    uint32_t qh[4][4];
    #pragma unroll
    for (int kk = 0; kk < 4; kk++) {
        int k0 = kk * 16 + 2 * t;
        #pragma unroll
        for (int fi = 0; fi < 4; fi++) {
            int ko = k0 + (fi >> 1) * 8;
            const __half* p = (fi & 1) ? Qp1 : Qp0;
            __half2 v = *(const __half2*)(p + ko);
            qh[kk][fi] = pack2h(__half2float(v.x) * qsc, __half2float(v.y) * qsc);
        }
    }

    // K+V loader (cp.async)
    auto load_kv = [&](int c, int s) {
        int j0 = c * 64;
        uint32_t sb = sbase + (uint32_t)s * ATT_STG_BYTES;
        #pragma unroll
        for (int l = 0; l < 2; l++) {
            int idx = tid + l * 256;
            int r = idx >> 3, c8 = idx & 7;
            int j = j0 + r;
            uint32_t d = (uint32_t)(r * 36 + c8 * 4) * 4u;
            int ok = (j < NTOK) ? 16 : 0;
            size_t ko = base + (size_t)j * QKVW + DMODEL + h * 64 + c8 * 8;
            size_t vo = ko + DMODEL;
            CP_ASYNC16(sb + d,         (const char*)g_qkv + ko * 2, ok);
            CP_ASYNC16(sb + 9216u + d, (const char*)g_qkv + vo * 2, ok);
        }
    };

    int kfr = lane & 7, kfc = ((lane >> 3) & 1) * 4;
    uint32_t kfoff = (uint32_t)(kfr * 36 + kfc) * 4u;
    int vrow = (lane & 7) + ((lane >> 3) & 1) * 8;
    uint32_t vtoff = (uint32_t)vrow * 144u;

    float O[8][4];
    #pragma unroll
    for (int nj = 0; nj < 8; nj++)
        #pragma unroll
        for (int q = 0; q < 4; q++) O[nj][q] = 0.f;
    float mr0 = -1e30f, mr1 = -1e30f, lr0 = 0.f, lr1 = 0.f;

    load_kv(0, 0);
    CP_COMMIT();
    load_kv(1, 1);
    CP_COMMIT();

    for (int c = 0; c < 17; c++) {
        int s = c % 3;
        if (c + 1 < 17) CP_WAIT1(); else CP_WAIT0();
        __syncthreads();
        if (c + 2 < 17) {
            load_kv(c + 2, (c + 2) % 3);
            CP_COMMIT();
        }
        uint32_t uKH = sbase + (uint32_t)s * ATT_STG_BYTES;
        uint32_t uVH = uKH + 9216u + vtoff;
        int j0 = c * 64;

        // ---- S = Q K^T ----
        float S[8][4];
        #pragma unroll
        for (int nj = 0; nj < 8; nj++)
            #pragma unroll
            for (int q = 0; q < 4; q++) S[nj][q] = 0.f;

        #pragma unroll
        for (int kk = 0; kk < 4; kk++) {
            uint32_t kcb = (uint32_t)(kk * 8) * 4u;
            #pragma unroll
            for (int nj = 0; nj < 8; nj++) {
                uint32_t kb[2];
                ldsm_x2(kb, uKH + (uint32_t)(nj * 8 * 36) * 4u + kcb + kfoff);
                mma_f16(S[nj], qh[kk], kb);
            }
        }

        if (j0 + 64 > NTOK) {
            #pragma unroll
            for (int nj = 0; nj < 8; nj++) {
                int col = j0 + 8 * nj + 2 * t;
                if (col >= NTOK)     { S[nj][0] = -1e30f; S[nj][2] = -1e30f; }
                if (col + 1 >= NTOK) { S[nj][1] = -1e30f; S[nj][3] = -1e30f; }
            }
        }

        // ---- online softmax (log2 domain) ----
        float cm0 = -1e30f, cm1 = -1e30f;
        #pragma unroll
        for (int nj = 0; nj < 8; nj++) {
            cm0 = fmaxf(cm0, fmaxf(S[nj][0], S[nj][1]));
            cm1 = fmaxf(cm1, fmaxf(S[nj][2], S[nj][3]));
        }
        cm0 = fmaxf(cm0, __shfl_xor_sync(0xffffffffu, cm0, 1));
        cm0 = fmaxf(cm0, __shfl_xor_sync(0xffffffffu, cm0, 2));
        cm1 = fmaxf(cm1, __shfl_xor_sync(0xffffffffu, cm1, 1));
        cm1 = fmaxf(cm1, __shfl_xor_sync(0xffffffffu, cm1, 2));
        float mn0 = fmaxf(mr0, cm0), mn1 = fmaxf(mr1, cm1);
        float f0 = exp2f(mr0 - mn0), f1 = exp2f(mr1 - mn1);
        float ps0 = 0.f, ps1 = 0.f;
        #pragma unroll
        for (int nj = 0; nj < 8; nj++) {
            S[nj][0] = exp2f(S[nj][0] - mn0);
            S[nj][1] = exp2f(S[nj][1] - mn0);
            S[nj][2] = exp2f(S[nj][2] - mn1);
            S[nj][3] = exp2f(S[nj][3] - mn1);
            ps0 += S[nj][0] + S[nj][1];
            ps1 += S[nj][2] + S[nj][3];
        }
        ps0 += __shfl_xor_sync(0xffffffffu, ps0, 1);
        ps0 += __shfl_xor_sync(0xffffffffu, ps0, 2);
        ps1 += __shfl_xor_sync(0xffffffffu, ps1, 1);
        ps1 += __shfl_xor_sync(0xffffffffu, ps1, 2);
        lr0 = lr0 * f0 + ps0;
        lr1 = lr1 * f1 + ps1;
        mr0 = mn0; mr1 = mn1;
        #pragma unroll
        for (int nj = 0; nj < 8; nj++) {
            O[nj][0] *= f0; O[nj][1] *= f0;
            O[nj][2] *= f1; O[nj][3] *= f1;
        }

        // ---- O += P @ V ----
        #pragma unroll
        for (int kk = 0; kk < 4; kk++) {
            int j2 = 2 * kk;
            uint32_t ph[4];
            ph[0] = pack2h(S[j2][0],     S[j2][1]);
            ph[1] = pack2h(S[j2][2],     S[j2][3]);
            ph[2] = pack2h(S[j2 + 1][0], S[j2 + 1][1]);
            ph[3] = pack2h(S[j2 + 1][2], S[j2 + 1][3]);
            uint32_t kbase = (uint32_t)(kk * 16) * 144u;
            #pragma unroll
            for (int nj = 0; nj < 8; nj++) {
                uint32_t vh[2];
                ldsm_x2_trans(vh, uVH + kbase + (uint32_t)nj * 16u);
                mma_f16(O[nj], ph, vh);
            }
        }
    }

    // ---- write out (fp16 ctx) ----
    float i0 = 1.f / lr0, i1 = 1.f / lr1;
    size_t o0 = ((size_t)b * NTOK + row0 + g) * DMODEL + h * 64;
    size_t o1 = o0 + (size_t)8 * DMODEL;
    #pragma unroll
    for (int nj = 0; nj < 8; nj++) {
        int col = 8 * nj + 2 * t;
        *(uint32_t*)((char*)g_ctx + (o0 + col) * 2) = pack2h(O[nj][0] * i0, O[nj][1] * i0);
        *(uint32_t*)((char*)g_ctx + (o1 + col) * 2) = pack2h(O[nj][2] * i1, O[nj][3] * i1);
    }
}

// ---------------- block reduction helpers ----------------
__device__ __forceinline__ float blockReduceSum(float v, float* red) {
    #pragma unroll
    for (int o = 16; o > 0; o >>= 1) v += __shfl_xor_sync(0xffffffffu, v, o);
    int lane = threadIdx.x & 31, w = threadIdx.x >> 5;
    __syncthreads();
    if (lane == 0) red[w] = v;
    __syncthreads();
    if (threadIdx.x == 0) {
        float s = 0.f;
        #pragma unroll
        for (int i = 0; i < 8; i++) s += red[i];
        red[0] = s;
    }
    __syncthreads();
    return red[0];
}

__device__ __forceinline__ float blockReduceMax(float v, float* red) {
    #pragma unroll
    for (int o = 16; o > 0; o >>= 1) v = fmaxf(v, __shfl_xor_sync(0xffffffffu, v, o));
    int lane = threadIdx.x & 31, w = threadIdx.x >> 5;
    __syncthreads();
    if (lane == 0) red[w] = v;
    __syncthreads();
    if (threadIdx.x == 0) {
        float s = -1e30f;
        #pragma unroll
        for (int i = 0; i < 8; i++) s = fmaxf(s, red[i]);
        red[0] = s;
    }
    __syncthreads();
    return red[0];
}

// ---------------- LayerNorm -> fp16 ----------------
__global__ __launch_bounds__(256) void ln_kernel(const float* __restrict__ x,
                                                 const float* __restrict__ w,
                                                 const float* __restrict__ bias) {
    int row = blockIdx.x;
    const float* xr = x + (size_t)row * DMODEL;
    int t = threadIdx.x;
    float v[3];
    float s = 0.f, sq = 0.f;
    #pragma unroll
    for (int i = 0; i < 3; i++) {
        v[i] = xr[t + i * 256];
        s += v[i];
        sq += v[i] * v[i];
    }
    __shared__ float red[32];
    __shared__ float stats[2];
    #pragma unroll
    for (int o = 16; o > 0; o >>= 1) {
        s  += __shfl_xor_sync(0xffffffffu, s, o);
        sq += __shfl_xor_sync(0xffffffffu, sq, o);
    }
    int lane = t & 31, wp = t >> 5;
    if (lane == 0) { red[wp] = s; red[8 + wp] = sq; }
    __syncthreads();
    if (t == 0) {
        float a = 0.f, b2 = 0.f;
        #pragma unroll
        for (int i = 0; i < 8; i++) { a += red[i]; b2 += red[8 + i]; }
        stats[0] = a; stats[1] = b2;
    }
    __syncthreads();
    float mean = stats[0] * (1.f / DMODEL);
    float var  = stats[1] * (1.f / DMODEL) - mean * mean;
    float inv  = rsqrtf(var + EPS);
    #pragma unroll
    for (int i = 0; i < 3; i++) {
        int c = t + i * 256;
        float o = (v[i] - mean) * inv * w[c] + bias[c];
        g_xn[(size_t)row * DMODEL + c] = __float2half_rn(o);
    }
}

// ---------------- CLS row (query row 0) ----------------
__global__ __launch_bounds__(256) void cls_kernel(const float* __restrict__ canny,
                                                  const float* __restrict__ noise) {
    int bh = blockIdx.x;
    int b = bh / NH, h = bh % NH;
    __shared__ float sm[NTOK];
    __shared__ float q0[64];
    __shared__ float red[32];
    __shared__ float part[4][64];
    int tid = threadIdx.x;
    size_t base = (size_t)b * NTOK * QKVW;

    if (tid < 64)
        q0[tid] = __half2float(g_qkv[base + h * 64 + tid]);
    __syncthreads();

    for (int j = tid; j < NTOK; j += 256) {
        size_t ko = base + (size_t)j * QKVW + DMODEL + h * 64;
        float dot = 0.f;
        #pragma unroll
        for (int d2 = 0; d2 < 32; d2++) {
            __half2 kh = *(const __half2*)(g_qkv + ko + 2 * d2);
            dot += q0[2 * d2] * __half2float(kh.x) + q0[2 * d2 + 1] * __half2float(kh.y);
        }
        sm[j] = dot * SCALE;
    }
    __syncthreads();

    float mx = -1e30f, cs = 0.f, ns = 0.f;
    for (int j = tid; j < NPATCH; j += 256) {
        mx = fmaxf(mx, sm[j + 1]);
        cs += canny[(size_t)b * NPATCH + j] + 1.f;
        ns += noise[(size_t)b * NPATCH + j];
    }
    mx = blockReduceMax(mx, red);
    cs = blockReduceSum(cs, red);
    ns = blockReduceSum(ns, red);
    float se = 0.f;
    for (int j = tid; j < NPATCH; j += 256) se += exp2f((sm[j + 1] - mx) * LOG2E);
    se = blockReduceSum(se, red);
    float inv_se = 1.f / se, inv_cs = 1.f / cs, inv_ns = 1.f / ns;
    for (int j = tid; j < NPATCH; j += 256) {
        float a = exp2f((sm[j + 1] - mx) * LOG2E) * inv_se;
        sm[j + 1] = a + (canny[(size_t)b * NPATCH + j] + 1.f) * inv_cs
                      + noise[(size_t)b * NPATCH + j] * inv_ns;
    }
    __syncthreads();

    float mx2 = -1e30f;
    for (int j = tid; j < NTOK; j += 256) mx2 = fmaxf(mx2, sm[j]);
    mx2 = blockReduceMax(mx2, red);
    float se2 = 0.f;
    for (int j = tid; j < NTOK; j += 256) se2 += exp2f((sm[j] - mx2) * LOG2E);
    se2 = blockReduceSum(se2, red);
    float inv2 = 1.f / se2;
    for (int j = tid; j < NTOK; j += 256) sm[j] = exp2f((sm[j] - mx2) * LOG2E) * inv2;
    __syncthreads();

    int d = tid & 63, qp = tid >> 6;
    float acc = 0.f;
    for (int j = qp; j < NTOK; j += 4) {
        size_t vo = base + (size_t)j * QKVW + 2 * DMODEL + h * 64 + d;
        acc += sm[j] * __half2float(g_qkv[vo]);
    }
    part[qp][d] = acc;
    __syncthreads();
    if (tid < 64) {
        float o = part[0][tid] + part[1][tid] + part[2][tid] + part[3][tid];
        g_ctx[(size_t)b * NTOK * DMODEL + h * 64 + tid] = __float2half_rn(o);
    }
}

// ---------------- launch ----------------
extern "C" void kernel_launch(void* const* d_in, const int* in_sizes, int n_in,
                              void* d_out, int out_size) {
    const float* x     = (const float*)d_in[0];
    const float* canny = (const float*)d_in[1];
    const float* noise = (const float*)d_in[2];
    const float* ln_w  = (const float*)d_in[3];
    const float* ln_b  = (const float*)d_in[4];
    const float* w_qkv = (const float*)d_in[5];
    const float* w_out = (const float*)d_in[6];
    const float* b_out = (const float*)d_in[7];
    float* out = (float*)d_out;

    cudaFuncSetAttribute(gemm_mma<0>, cudaFuncAttributeMaxDynamicSharedMemorySize, GEMM_SMEM);
    cudaFuncSetAttribute(gemm_mma<1>, cudaFuncAttributeMaxDynamicSharedMemorySize, GEMM_SMEM);
    cudaFuncSetAttribute(attn_mma_kernel, cudaFuncAttributeMaxDynamicSharedMemorySize, ATT_SMEM);

    __half *wqkvT, *woutT;
    cudaGetSymbolAddress((void**)&wqkvT, g_wqkvT);
    cudaGetSymbolAddress((void**)&woutT, g_woutT);

    // 1. LayerNorm (-> fp16)
    ln_kernel<<<MTOT, 256>>>(x, ln_w, ln_b);

    // 1b. transpose weights to [N, K] fp16
    {
        dim3 g1(QKVW / 32, DMODEL / 32);
        transpose_h_kernel<<<g1, 256>>>(w_qkv, wqkvT, DMODEL, QKVW);
        dim3 g2(DMODEL / 32, DMODEL / 32);
        transpose_h_kernel<<<g2, 256>>>(w_out, woutT, DMODEL, DMODEL);
    }

    // 2. QKV GEMM (fp16, BK=64, 3-stage) -> g_qkv
    {
        dim3 grid(QKVW / 128, (MTOT + 127) / 128);
        gemm_mma<0><<<grid, 256, GEMM_SMEM>>>(wqkvT, nullptr, nullptr, MTOT, QKVW, DMODEL);
    }

    // 3. attention rows 1..1024 (2 CTA/SM, 3-stage)
    {
        dim3 g_attn(8, BATCH * NH);
        attn_mma_kernel<<<g_attn, 256, ATT_SMEM>>>();
    }

    // 4. CLS row with prior injection
    cls_kernel<<<BATCH * NH, 256>>>(canny, noise);

    // 5. output projection (fp16, BK=64, 3-stage) -> d_out (fp32 + bias)
    {
        dim3 grid(DMODEL / 128, (MTOT + 127) / 128);
        gemm_mma<1><<<grid, 256, GEMM_SMEM>>>(woutT, b_out, out, MTOT, DMODEL, DMODEL);
    }
}

// round 16
// speedup vs baseline: 3.5377x; 1.1128x over previous
#include <cuda_runtime.h>
#include <cuda_fp16.h>
#include <math.h>
#include <stdint.h>

#define BATCH   8
#define NTOK    1025
#define DMODEL  768
#define NH      12
#define HDIM    64
#define NPATCH  1024
#define QKVW    (3*DMODEL)          // 2304
#define EPS     1e-5f
#define LOG2E   1.4426950408889634f
#define SCALE   0.03608439182435161f   // 768^-0.5
#define MTOT    (BATCH*NTOK)        // 8200

// ---------------- scratch (device globals; no allocation) ----------------
__device__ __half g_xn   [(size_t)MTOT * DMODEL];
__device__ __half g_qkv  [(size_t)MTOT * QKVW];
__device__ __half g_ctx  [(size_t)MTOT * DMODEL];
__device__ __half g_wqkvT[(size_t)QKVW * DMODEL];
__device__ __half g_woutT[(size_t)DMODEL * DMODEL];

// ---------------- helpers ----------------
__device__ __forceinline__ uint32_t smem_u32(const void* p) {
    uint32_t a;
    asm("{ .reg .u64 t; cvta.to.shared.u64 t, %1; cvt.u32.u64 %0, t; }" : "=r"(a) : "l"(p));
    return a;
}

__device__ __forceinline__ void mma_f16(float* c, const uint32_t* a, const uint32_t* b) {
    asm volatile(
        "mma.sync.aligned.m16n8k16.row.col.f32.f16.f16.f32 "
        "{%0,%1,%2,%3}, {%4,%5,%6,%7}, {%8,%9}, {%0,%1,%2,%3};"
        : "+f"(c[0]), "+f"(c[1]), "+f"(c[2]), "+f"(c[3])
        : "r"(a[0]), "r"(a[1]), "r"(a[2]), "r"(a[3]), "r"(b[0]), "r"(b[1]));
}

__device__ __forceinline__ void ldsm_x4(uint32_t* f, uint32_t addr) {
    asm volatile("ldmatrix.sync.aligned.m8n8.x4.shared.b16 {%0,%1,%2,%3}, [%4];"
        : "=r"(f[0]), "=r"(f[1]), "=r"(f[2]), "=r"(f[3]) : "r"(addr));
}
__device__ __forceinline__ void ldsm_x2(uint32_t* f, uint32_t addr) {
    asm volatile("ldmatrix.sync.aligned.m8n8.x2.shared.b16 {%0,%1}, [%2];"
        : "=r"(f[0]), "=r"(f[1]) : "r"(addr));
}
__device__ __forceinline__ void ldsm_x2_trans(uint32_t* f, uint32_t addr) {
    asm volatile("ldmatrix.sync.aligned.m8n8.x2.trans.shared.b16 {%0,%1}, [%2];"
        : "=r"(f[0]), "=r"(f[1]) : "r"(addr));
}

#define CP_ASYNC16(dst, src, nbytes) \
    asm volatile("cp.async.cg.shared.global [%0], [%1], 16, %2;" \
                 :: "r"(dst), "l"(src), "r"(nbytes))
#define CP_COMMIT() asm volatile("cp.async.commit_group;")
#define CP_WAIT1()  asm volatile("cp.async.wait_group 1;")
#define CP_WAIT0()  asm volatile("cp.async.wait_group 0;")

// plain fp16 pack of two floats
__device__ __forceinline__ uint32_t pack2h(float a, float b) {
    __half ha = __float2half_rn(a), hb = __float2half_rn(b);
    return (uint32_t)__half_as_ushort(ha) | ((uint32_t)__half_as_ushort(hb) << 16);
}

// ================= prep kernel: LN (warp-per-row) + both weight transposes =================
// grid.x = 1025 (LN, 8 rows/block) + 1728 (w_qkv tiles) + 576 (w_out tiles)
#define LN_BLOCKS   1025
#define TQ_TILES_X  (QKVW / 32)     // 72
#define TQ_TILES    (TQ_TILES_X * (DMODEL / 32))   // 1728
#define TO_TILES_X  (DMODEL / 32)   // 24
#define TO_TILES    (TO_TILES_X * (DMODEL / 32))   // 576

__global__ __launch_bounds__(256) void prep_kernel(const float* __restrict__ x,
                                                   const float* __restrict__ lw,
                                                   const float* __restrict__ lb,
                                                   const float* __restrict__ w_qkv,
                                                   const float* __restrict__ w_out) {
    int bid = blockIdx.x;
    int tid = threadIdx.x;

    if (bid < LN_BLOCKS) {
        // ---- LayerNorm: warp per row, 8 rows per block ----
        int wid = tid >> 5, lane = tid & 31;
        int row = bid * 8 + wid;
        if (row >= MTOT) return;
        const float* xr = x + (size_t)row * DMODEL;
        float2 v[12];
        float s = 0.f, sq = 0.f;
        #pragma unroll
        for (int i = 0; i < 12; i++) {
            v[i] = *(const float2*)(xr + 2 * lane + 64 * i);
            s += v[i].x + v[i].y;
            sq += v[i].x * v[i].x + v[i].y * v[i].y;
        }
        #pragma unroll
        for (int o = 16; o > 0; o >>= 1) {
            s  += __shfl_xor_sync(0xffffffffu, s, o);
            sq += __shfl_xor_sync(0xffffffffu, sq, o);
        }
        float mean = s * (1.f / DMODEL);
        float var  = sq * (1.f / DMODEL) - mean * mean;
        float inv  = rsqrtf(var + EPS);
        __half* dst = g_xn + (size_t)row * DMODEL;
        #pragma unroll
        for (int i = 0; i < 12; i++) {
            int c = 2 * lane + 64 * i;
            float2 wv = *(const float2*)(lw + c);
            float2 bv = *(const float2*)(lb + c);
            float a = (v[i].x - mean) * inv * wv.x + bv.x;
            float b2 = (v[i].y - mean) * inv * wv.y + bv.y;
            *(uint32_t*)((char*)dst + (size_t)c * 2) = pack2h(a, b2);
        }
        return;
    }

    // ---- weight transpose tiles ----
    __shared__ float tbuf[32][33];
    const float* src;
    __half* dsth;
    int K, N, tile;
    int t1 = bid - LN_BLOCKS;
    if (t1 < TQ_TILES) {
        src = w_qkv; dsth = g_wqkvT; K = DMODEL; N = QKVW;
        tile = t1;
    } else {
        src = w_out; dsth = g_woutT; K = DMODEL; N = DMODEL;
        tile = t1 - TQ_TILES;
    }
    int tilesX = N / 32;
    int nx = (tile % tilesX) * 32, kx = (tile / tilesX) * 32;
    int lx = tid & 31, ly = tid >> 5;
    #pragma unroll
    for (int i = ly; i < 32; i += 8)
        tbuf[i][lx] = src[(size_t)(kx + i) * N + nx + lx];
    __syncthreads();
    #pragma unroll
    for (int i = ly; i < 32; i += 8)
        dsth[(size_t)(nx + i) * K + kx + lx] = __float2half_rn(tbuf[lx][i]);
}

// ================= tensor-core GEMM (fp16, BK=64, 3-stage cp.async, 2 CTA/SM) =================
#define SM_STRIDE 36
#define ARR_BYTES (128 * SM_STRIDE * 4)     // 18432
#define STG_BYTES (2 * ARR_BYTES)           // 36864
#define GEMM_SMEM (3 * STG_BYTES)           // 110592

template<int SEL>
__global__ __launch_bounds__(256, 2) void gemm_mma(const __half* __restrict__ Bmat,
                                                   const float* __restrict__ bias,
                                                   float* __restrict__ Cext,
                                                   int M, int N, int K) {
    const __half* A = (SEL == 0) ? g_xn : g_ctx;

    extern __shared__ char smem[];
    uint32_t sbase = smem_u32(smem);

    int tid = threadIdx.x;
    int wid = tid >> 5, lane = tid & 31;
    int g = lane >> 2, t = lane & 3;
    int wm = wid & 1, wn = wid >> 1;
    int m0 = blockIdx.y * 128, n0 = blockIdx.x * 128;
    int mw = wm * 64, nw = wn * 32;

    int rA = (lane & 7) + ((lane >> 3) & 1) * 8;
    int cA = (lane >> 4) * 4;
    uint32_t aoff = (uint32_t)(rA * SM_STRIDE + cA) * 4u;
    int rB = lane & 7;
    int cB = ((lane >> 3) & 1) * 4;
    uint32_t boff = (uint32_t)(rB * SM_STRIDE + cB) * 4u;

    float acc[4][4][4];
    #pragma unroll
    for (int i = 0; i < 4; i++)
        #pragma unroll
        for (int j = 0; j < 4; j++)
            #pragma unroll
            for (int q = 0; q < 4; q++) acc[i][j][q] = 0.f;

    int nch = K / 64;   // 12

    auto load_stage = [&](int ch, int s) {
        int kb = ch * 64;
        uint32_t so = sbase + (uint32_t)s * STG_BYTES;
        #pragma unroll
        for (int l = 0; l < 4; l++) {
            int idx = tid + l * 256;
            int r = idx >> 3, c8 = idx & 7;
            uint32_t d = (uint32_t)(r * SM_STRIDE + c8 * 4) * 4u;
            int okA = (m0 + r < M) ? 16 : 0;
            size_t ao = (size_t)(m0 + r) * K + kb + c8 * 8;
            size_t bo = (size_t)(n0 + r) * K + kb + c8 * 8;
            CP_ASYNC16(so + d,             A    + ao, okA);
            CP_ASYNC16(so + ARR_BYTES + d, Bmat + bo, 16);
        }
    };

    load_stage(0, 0);
    CP_COMMIT();
    load_stage(1, 1);
    CP_COMMIT();

    for (int ch = 0; ch < nch; ch++) {
        int s = ch % 3;
        if (ch + 1 < nch) CP_WAIT1(); else CP_WAIT0();
        __syncthreads();
        if (ch + 2 < nch) {
            load_stage(ch + 2, (ch + 2) % 3);
            CP_COMMIT();
        }

        uint32_t uA = sbase + (uint32_t)s * STG_BYTES;
        uint32_t uB = uA + ARR_BYTES;

        #pragma unroll
        for (int kk = 0; kk < 4; kk++) {
            uint32_t kcb = (uint32_t)(kk * 8) * 4u;
            uint32_t ah[4][4], bh[4][2];
            #pragma unroll
            for (int mi = 0; mi < 4; mi++) {
                uint32_t base = (uint32_t)((mw + mi * 16) * SM_STRIDE) * 4u + kcb + aoff;
                ldsm_x4(ah[mi], uA + base);
            }
            #pragma unroll
            for (int nj = 0; nj < 4; nj++) {
                uint32_t base = (uint32_t)((nw + nj * 8) * SM_STRIDE) * 4u + kcb + boff;
                ldsm_x2(bh[nj], uB + base);
            }
            #pragma unroll
            for (int mi = 0; mi < 4; mi++)
                #pragma unroll
                for (int nj = 0; nj < 4; nj++)
                    mma_f16(acc[mi][nj], ah[mi], bh[nj]);
        }
    }

    // ---- epilogue ----
    #pragma unroll
    for (int mi = 0; mi < 4; mi++) {
        int r0e = m0 + mw + mi * 16 + g;
        #pragma unroll
        for (int nj = 0; nj < 4; nj++) {
            int col = n0 + nw + nj * 8 + t * 2;
            if (SEL == 0) {
                #pragma unroll
                for (int half = 0; half < 2; half++) {
                    int row = r0e + half * 8;
                    if (row < M) {
                        uint32_t hp = pack2h(acc[mi][nj][2 * half], acc[mi][nj][2 * half + 1]);
                        *(uint32_t*)((char*)g_qkv + ((size_t)row * N + col) * 2) = hp;
                    }
                }
            } else {
                float b0 = bias[col], b1 = bias[col + 1];
                if (r0e < M)
                    *(float2*)(Cext + (size_t)r0e * N + col) =
                        make_float2(acc[mi][nj][0] + b0, acc[mi][nj][1] + b1);
                if (r0e + 8 < M)
                    *(float2*)(Cext + (size_t)(r0e + 8) * N + col) =
                        make_float2(acc[mi][nj][2] + b0, acc[mi][nj][3] + b1);
            }
        }
    }
}

// ================= attention + CLS fused: grid (9, 96) =================
// qt<8: flash attention for 128 q rows. qt==8: CLS row for (b,h).
#define ATT_STG_BYTES 18432u
#define ATT_SMEM      (3 * 18432)

__device__ __forceinline__ float warpReduceSum(float v) {
    #pragma unroll
    for (int o = 16; o > 0; o >>= 1) v += __shfl_xor_sync(0xffffffffu, v, o);
    return v;
}

__global__ __launch_bounds__(256, 2) void attn_mma_kernel(const float* __restrict__ canny,
                                                          const float* __restrict__ noise) {
    extern __shared__ uint32_t sh[];
    int qt = blockIdx.x;
    int bh_ = blockIdx.y;
    int b = bh_ / NH, h = bh_ % NH;
    int tid = threadIdx.x;
    size_t base = (size_t)b * NTOK * QKVW;

    if (qt == 8) {
        // ================= CLS row =================
        float* sm   = (float*)sh;            // [NTOK]
        float* q0   = sm + NTOK;             // [64]
        float* red  = q0 + 64;               // [32]
        float* part = red + 32;              // [4][64]

        if (tid < 64) q0[tid] = __half2float(g_qkv[base + h * 64 + tid]);
        __syncthreads();

        for (int j = tid; j < NTOK; j += 256) {
            size_t ko = base + (size_t)j * QKVW + DMODEL + h * 64;
            float dot = 0.f;
            #pragma unroll
            for (int d2 = 0; d2 < 32; d2++) {
                __half2 kh = *(const __half2*)(g_qkv + ko + 2 * d2);
                dot += q0[2 * d2] * __half2float(kh.x) + q0[2 * d2 + 1] * __half2float(kh.y);
            }
            sm[j] = dot * SCALE;
        }
        __syncthreads();

        int lane = tid & 31, wp = tid >> 5;
        // block reduce helpers inline
        auto bSum = [&](float v) {
            v = warpReduceSum(v);
            __syncthreads();
            if (lane == 0) red[wp] = v;
            __syncthreads();
            if (tid == 0) {
                float s2 = 0.f;
                #pragma unroll
                for (int i = 0; i < 8; i++) s2 += red[i];
                red[0] = s2;
            }
            __syncthreads();
            return red[0];
        };
        auto bMax = [&](float v) {
            #pragma unroll
            for (int o = 16; o > 0; o >>= 1) v = fmaxf(v, __shfl_xor_sync(0xffffffffu, v, o));
            __syncthreads();
            if (lane == 0) red[wp] = v;
            __syncthreads();
            if (tid == 0) {
                float s2 = -1e30f;
                #pragma unroll
                for (int i = 0; i < 8; i++) s2 = fmaxf(s2, red[i]);
                red[0] = s2;
            }
            __syncthreads();
            return red[0];
        };

        float mx = -1e30f, cs = 0.f, ns = 0.f;
        for (int j = tid; j < NPATCH; j += 256) {
            mx = fmaxf(mx, sm[j + 1]);
            cs += canny[(size_t)b * NPATCH + j] + 1.f;
            ns += noise[(size_t)b * NPATCH + j];
        }
        mx = bMax(mx);
        cs = bSum(cs);
        ns = bSum(ns);
        float se = 0.f;
        for (int j = tid; j < NPATCH; j += 256) se += exp2f((sm[j + 1] - mx) * LOG2E);
        se = bSum(se);
        float inv_se = 1.f / se, inv_cs = 1.f / cs, inv_ns = 1.f / ns;
        for (int j = tid; j < NPATCH; j += 256) {
            float a = exp2f((sm[j + 1] - mx) * LOG2E) * inv_se;
            sm[j + 1] = a + (canny[(size_t)b * NPATCH + j] + 1.f) * inv_cs
                          + noise[(size_t)b * NPATCH + j] * inv_ns;
        }
        __syncthreads();

        float mx2 = -1e30f;
        for (int j = tid; j < NTOK; j += 256) mx2 = fmaxf(mx2, sm[j]);
        mx2 = bMax(mx2);
        float se2 = 0.f;
        for (int j = tid; j < NTOK; j += 256) se2 += exp2f((sm[j] - mx2) * LOG2E);
        se2 = bSum(se2);
        float inv2 = 1.f / se2;
        for (int j = tid; j < NTOK; j += 256) sm[j] = exp2f((sm[j] - mx2) * LOG2E) * inv2;
        __syncthreads();

        int d = tid & 63, qp = tid >> 6;
        float acc = 0.f;
        for (int j = qp; j < NTOK; j += 4) {
            size_t vo = base + (size_t)j * QKVW + 2 * DMODEL + h * 64 + d;
            acc += sm[j] * __half2float(g_qkv[vo]);
        }
        part[qp * 64 + d] = acc;
        __syncthreads();
        if (tid < 64) {
            float o = part[tid] + part[64 + tid] + part[128 + tid] + part[192 + tid];
            g_ctx[(size_t)b * NTOK * DMODEL + h * 64 + tid] = __float2half_rn(o);
        }
        return;
    }

    // ================= flash attention =================
    int wid = tid >> 5, lane = tid & 31;
    int g = lane >> 2, t = lane & 3;
    uint32_t sbase = smem_u32(sh);

    int row0 = 1 + qt * 128 + wid * 16;
    const float qsc = SCALE * LOG2E;
    const __half* Qp0 = g_qkv + base + (size_t)(row0 + g) * QKVW + h * 64;
    const __half* Qp1 = Qp0 + 8 * QKVW;
    uint32_t qh[4][4];
    #pragma unroll
    for (int kk = 0; kk < 4; kk++) {
        int k0 = kk * 16 + 2 * t;
        #pragma unroll
        for (int fi = 0; fi < 4; fi++) {
            int ko = k0 + (fi >> 1) * 8;
            const __half* p = (fi & 1) ? Qp1 : Qp0;
            __half2 v = *(const __half2*)(p + ko);
            qh[kk][fi] = pack2h(__half2float(v.x) * qsc, __half2float(v.y) * qsc);
        }
    }

    auto load_kv = [&](int c, int s) {
        int j0 = c * 64;
        uint32_t sb = sbase + (uint32_t)s * ATT_STG_BYTES;
        #pragma unroll
        for (int l = 0; l < 2; l++) {
            int idx = tid + l * 256;
            int r = idx >> 3, c8 = idx & 7;
            int j = j0 + r;
            uint32_t d = (uint32_t)(r * 36 + c8 * 4) * 4u;
            int ok = (j < NTOK) ? 16 : 0;
            size_t ko = base + (size_t)j * QKVW + DMODEL + h * 64 + c8 * 8;
            size_t vo = ko + DMODEL;
            CP_ASYNC16(sb + d,         (const char*)g_qkv + ko * 2, ok);
            CP_ASYNC16(sb + 9216u + d, (const char*)g_qkv + vo * 2, ok);
        }
    };

    int kfr = lane & 7, kfc = ((lane >> 3) & 1) * 4;
    uint32_t kfoff = (uint32_t)(kfr * 36 + kfc) * 4u;
    int vrow = (lane & 7) + ((lane >> 3) & 1) * 8;
    uint32_t vtoff = (uint32_t)vrow * 144u;

    float O[8][4];
    #pragma unroll
    for (int nj = 0; nj < 8; nj++)
        #pragma unroll
        for (int q = 0; q < 4; q++) O[nj][q] = 0.f;
    float mr0 = -1e30f, mr1 = -1e30f, lr0 = 0.f, lr1 = 0.f;

    load_kv(0, 0);
    CP_COMMIT();
    load_kv(1, 1);
    CP_COMMIT();

    for (int c = 0; c < 17; c++) {
        int s = c % 3;
        if (c + 1 < 17) CP_WAIT1(); else CP_WAIT0();
        __syncthreads();
        if (c + 2 < 17) {
            load_kv(c + 2, (c + 2) % 3);
            CP_COMMIT();
        }
        uint32_t uKH = sbase + (uint32_t)s * ATT_STG_BYTES;
        uint32_t uVH = uKH + 9216u + vtoff;
        int j0 = c * 64;

        float S[8][4];
        #pragma unroll
        for (int nj = 0; nj < 8; nj++)
            #pragma unroll
            for (int q = 0; q < 4; q++) S[nj][q] = 0.f;

        #pragma unroll
        for (int kk = 0; kk < 4; kk++) {
            uint32_t kcb = (uint32_t)(kk * 8) * 4u;
            #pragma unroll
            for (int nj = 0; nj < 8; nj++) {
                uint32_t kb[2];
                ldsm_x2(kb, uKH + (uint32_t)(nj * 8 * 36) * 4u + kcb + kfoff);
                mma_f16(S[nj], qh[kk], kb);
            }
        }

        if (j0 + 64 > NTOK) {
            #pragma unroll
            for (int nj = 0; nj < 8; nj++) {
                int col = j0 + 8 * nj + 2 * t;
                if (col >= NTOK)     { S[nj][0] = -1e30f; S[nj][2] = -1e30f; }
                if (col + 1 >= NTOK) { S[nj][1] = -1e30f; S[nj][3] = -1e30f; }
            }
        }

        float cm0 = -1e30f, cm1 = -1e30f;
        #pragma unroll
        for (int nj = 0; nj < 8; nj++) {
            cm0 = fmaxf(cm0, fmaxf(S[nj][0], S[nj][1]));
            cm1 = fmaxf(cm1, fmaxf(S[nj][2], S[nj][3]));
        }
        cm0 = fmaxf(cm0, __shfl_xor_sync(0xffffffffu, cm0, 1));
        cm0 = fmaxf(cm0, __shfl_xor_sync(0xffffffffu, cm0, 2));
        cm1 = fmaxf(cm1, __shfl_xor_sync(0xffffffffu, cm1, 1));
        cm1 = fmaxf(cm1, __shfl_xor_sync(0xffffffffu, cm1, 2));
        float mn0 = fmaxf(mr0, cm0), mn1 = fmaxf(mr1, cm1);
        float f0 = exp2f(mr0 - mn0), f1 = exp2f(mr1 - mn1);
        float ps0 = 0.f, ps1 = 0.f;
        #pragma unroll
        for (int nj = 0; nj < 8; nj++) {
            S[nj][0] = exp2f(S[nj][0] - mn0);
            S[nj][1] = exp2f(S[nj][1] - mn0);
            S[nj][2] = exp2f(S[nj][2] - mn1);
            S[nj][3] = exp2f(S[nj][3] - mn1);
            ps0 += S[nj][0] + S[nj][1];
            ps1 += S[nj][2] + S[nj][3];
        }
        ps0 += __shfl_xor_sync(0xffffffffu, ps0, 1);
        ps0 += __shfl_xor_sync(0xffffffffu, ps0, 2);
        ps1 += __shfl_xor_sync(0xffffffffu, ps1, 1);
        ps1 += __shfl_xor_sync(0xffffffffu, ps1, 2);
        lr0 = lr0 * f0 + ps0;
        lr1 = lr1 * f1 + ps1;
        mr0 = mn0; mr1 = mn1;
        #pragma unroll
        for (int nj = 0; nj < 8; nj++) {
            O[nj][0] *= f0; O[nj][1] *= f0;
            O[nj][2] *= f1; O[nj][3] *= f1;
        }

        #pragma unroll
        for (int kk = 0; kk < 4; kk++) {
            int j2 = 2 * kk;
            uint32_t ph[4];
            ph[0] = pack2h(S[j2][0],     S[j2][1]);
            ph[1] = pack2h(S[j2][2],     S[j2][3]);
            ph[2] = pack2h(S[j2 + 1][0], S[j2 + 1][1]);
            ph[3] = pack2h(S[j2 + 1][2], S[j2 + 1][3]);
            uint32_t kbase = (uint32_t)(kk * 16) * 144u;
            #pragma unroll
            for (int nj = 0; nj < 8; nj++) {
                uint32_t vh[2];
                ldsm_x2_trans(vh, uVH + kbase + (uint32_t)nj * 16u);
                mma_f16(O[nj], ph, vh);
            }
        }
    }

    float i0 = 1.f / lr0, i1 = 1.f / lr1;
    size_t o0 = ((size_t)b * NTOK + row0 + g) * DMODEL + h * 64;
    size_t o1 = o0 + (size_t)8 * DMODEL;
    #pragma unroll
    for (int nj = 0; nj < 8; nj++) {
        int col = 8 * nj + 2 * t;
        *(uint32_t*)((char*)g_ctx + (o0 + col) * 2) = pack2h(O[nj][0] * i0, O[nj][1] * i0);
        *(uint32_t*)((char*)g_ctx + (o1 + col) * 2) = pack2h(O[nj][2] * i1, O[nj][3] * i1);
    }
}

// ---------------- launch ----------------
extern "C" void kernel_launch(void* const* d_in, const int* in_sizes, int n_in,
                              void* d_out, int out_size) {
    const float* x     = (const float*)d_in[0];
    const float* canny = (const float*)d_in[1];
    const float* noise = (const float*)d_in[2];
    const float* ln_w  = (const float*)d_in[3];
    const float* ln_b  = (const float*)d_in[4];
    const float* w_qkv = (const float*)d_in[5];
    const float* w_out = (const float*)d_in[6];
    const float* b_out = (const float*)d_in[7];
    float* out = (float*)d_out;

    cudaFuncSetAttribute(gemm_mma<0>, cudaFuncAttributeMaxDynamicSharedMemorySize, GEMM_SMEM);
    cudaFuncSetAttribute(gemm_mma<1>, cudaFuncAttributeMaxDynamicSharedMemorySize, GEMM_SMEM);
    cudaFuncSetAttribute(attn_mma_kernel, cudaFuncAttributeMaxDynamicSharedMemorySize, ATT_SMEM);

    __half *wqkvT, *woutT;
    cudaGetSymbolAddress((void**)&wqkvT, g_wqkvT);
    cudaGetSymbolAddress((void**)&woutT, g_woutT);

    // 1. prep: LN + transposes (single launch)
    prep_kernel<<<LN_BLOCKS + TQ_TILES + TO_TILES, 256>>>(x, ln_w, ln_b, w_qkv, w_out);

    // 2. QKV GEMM (fp16, BK=64, 3-stage) -> g_qkv
    {
        dim3 grid(QKVW / 128, (MTOT + 127) / 128);
        gemm_mma<0><<<grid, 256, GEMM_SMEM>>>(wqkvT, nullptr, nullptr, MTOT, QKVW, DMODEL);
    }

    // 3. attention + CLS fused: grid (9, 96)
    {
        dim3 g_attn(9, BATCH * NH);
        attn_mma_kernel<<<g_attn, 256, ATT_SMEM>>>(canny, noise);
    }

    // 4. output projection (fp16, BK=64, 3-stage) -> d_out (fp32 + bias)
    {
        dim3 grid(DMODEL / 128, (MTOT + 127) / 128);
        gemm_mma<1><<<grid, 256, GEMM_SMEM>>>(woutT, b_out, out, MTOT, DMODEL, DMODEL);
    }
}

// round 17
// speedup vs baseline: 3.5437x; 1.0017x over previous
#include <cuda_runtime.h>
#include <cuda_fp16.h>
#include <math.h>
#include <stdint.h>

#define BATCH   8
#define NTOK    1025
#define DMODEL  768
#define NH      12
#define HDIM    64
#define NPATCH  1024
#define QKVW    (3*DMODEL)          // 2304
#define EPS     1e-5f
#define LOG2E   1.4426950408889634f
#define SCALE   0.03608439182435161f   // 768^-0.5
#define MTOT    (BATCH*NTOK)        // 8200

// ---------------- scratch (device globals; no allocation) ----------------
__device__ __half g_xn   [(size_t)MTOT * DMODEL];
__device__ __half g_qkv  [(size_t)MTOT * QKVW];
__device__ __half g_ctx  [(size_t)MTOT * DMODEL];
__device__ __half g_wqkvT[(size_t)QKVW * DMODEL];
__device__ __half g_woutT[(size_t)DMODEL * DMODEL];

// ---------------- helpers ----------------
__device__ __forceinline__ uint32_t smem_u32(const void* p) {
    uint32_t a;
    asm("{ .reg .u64 t; cvta.to.shared.u64 t, %1; cvt.u32.u64 %0, t; }" : "=r"(a) : "l"(p));
    return a;
}

__device__ __forceinline__ void mma_f16(float* c, const uint32_t* a, const uint32_t* b) {
    asm volatile(
        "mma.sync.aligned.m16n8k16.row.col.f32.f16.f16.f32 "
        "{%0,%1,%2,%3}, {%4,%5,%6,%7}, {%8,%9}, {%0,%1,%2,%3};"
        : "+f"(c[0]), "+f"(c[1]), "+f"(c[2]), "+f"(c[3])
        : "r"(a[0]), "r"(a[1]), "r"(a[2]), "r"(a[3]), "r"(b[0]), "r"(b[1]));
}

__device__ __forceinline__ void ldsm_x4(uint32_t* f, uint32_t addr) {
    asm volatile("ldmatrix.sync.aligned.m8n8.x4.shared.b16 {%0,%1,%2,%3}, [%4];"
        : "=r"(f[0]), "=r"(f[1]), "=r"(f[2]), "=r"(f[3]) : "r"(addr));
}
__device__ __forceinline__ void ldsm_x2(uint32_t* f, uint32_t addr) {
    asm volatile("ldmatrix.sync.aligned.m8n8.x2.shared.b16 {%0,%1}, [%2];"
        : "=r"(f[0]), "=r"(f[1]) : "r"(addr));
}
__device__ __forceinline__ void ldsm_x2_trans(uint32_t* f, uint32_t addr) {
    asm volatile("ldmatrix.sync.aligned.m8n8.x2.trans.shared.b16 {%0,%1}, [%2];"
        : "=r"(f[0]), "=r"(f[1]) : "r"(addr));
}

#define CP_ASYNC16(dst, src, nbytes) \
    asm volatile("cp.async.cg.shared.global [%0], [%1], 16, %2;" \
                 :: "r"(dst), "l"(src), "r"(nbytes))
#define CP_COMMIT() asm volatile("cp.async.commit_group;")
#define CP_WAIT1()  asm volatile("cp.async.wait_group 1;")
#define CP_WAIT0()  asm volatile("cp.async.wait_group 0;")

// plain fp16 pack of two floats
__device__ __forceinline__ uint32_t pack2h(float a, float b) {
    __half ha = __float2half_rn(a), hb = __float2half_rn(b);
    return (uint32_t)__half_as_ushort(ha) | ((uint32_t)__half_as_ushort(hb) << 16);
}

// ================= prep kernel: LN (warp-per-row) + both weight transposes =================
#define LN_BLOCKS   1025
#define TQ_TILES_X  (QKVW / 32)     // 72
#define TQ_TILES    (TQ_TILES_X * (DMODEL / 32))   // 1728
#define TO_TILES_X  (DMODEL / 32)   // 24
#define TO_TILES    (TO_TILES_X * (DMODEL / 32))   // 576

__global__ __launch_bounds__(256) void prep_kernel(const float* __restrict__ x,
                                                   const float* __restrict__ lw,
                                                   const float* __restrict__ lb,
                                                   const float* __restrict__ w_qkv,
                                                   const float* __restrict__ w_out) {
    int bid = blockIdx.x;
    int tid = threadIdx.x;

    if (bid < LN_BLOCKS) {
        int wid = tid >> 5, lane = tid & 31;
        int row = bid * 8 + wid;
        if (row >= MTOT) return;
        const float* xr = x + (size_t)row * DMODEL;
        float2 v[12];
        float s = 0.f, sq = 0.f;
        #pragma unroll
        for (int i = 0; i < 12; i++) {
            v[i] = *(const float2*)(xr + 2 * lane + 64 * i);
            s += v[i].x + v[i].y;
            sq += v[i].x * v[i].x + v[i].y * v[i].y;
        }
        #pragma unroll
        for (int o = 16; o > 0; o >>= 1) {
            s  += __shfl_xor_sync(0xffffffffu, s, o);
            sq += __shfl_xor_sync(0xffffffffu, sq, o);
        }
        float mean = s * (1.f / DMODEL);
        float var  = sq * (1.f / DMODEL) - mean * mean;
        float inv  = rsqrtf(var + EPS);
        __half* dst = g_xn + (size_t)row * DMODEL;
        #pragma unroll
        for (int i = 0; i < 12; i++) {
            int c = 2 * lane + 64 * i;
            float2 wv = *(const float2*)(lw + c);
            float2 bv = *(const float2*)(lb + c);
            float a = (v[i].x - mean) * inv * wv.x + bv.x;
            float b2 = (v[i].y - mean) * inv * wv.y + bv.y;
            *(uint32_t*)((char*)dst + (size_t)c * 2) = pack2h(a, b2);
        }
        return;
    }

    __shared__ float tbuf[32][33];
    const float* src;
    __half* dsth;
    int K, N, tile;
    int t1 = bid - LN_BLOCKS;
    if (t1 < TQ_TILES) {
        src = w_qkv; dsth = g_wqkvT; K = DMODEL; N = QKVW;
        tile = t1;
    } else {
        src = w_out; dsth = g_woutT; K = DMODEL; N = DMODEL;
        tile = t1 - TQ_TILES;
    }
    int tilesX = N / 32;
    int nx = (tile % tilesX) * 32, kx = (tile / tilesX) * 32;
    int lx = tid & 31, ly = tid >> 5;
    #pragma unroll
    for (int i = ly; i < 32; i += 8)
        tbuf[i][lx] = src[(size_t)(kx + i) * N + nx + lx];
    __syncthreads();
    #pragma unroll
    for (int i = ly; i < 32; i += 8)
        dsth[(size_t)(nx + i) * K + kx + lx] = __float2half_rn(tbuf[lx][i]);
}

// ================= tensor-core GEMM (fp16, BK=64, 3-stage cp.async, 2 CTA/SM) =================
// NJ = warp n-tiles (BN = 32*NJ). SEL=0: A=g_xn -> g_qkv fp16. SEL=1: A=g_ctx -> fp32 + bias.
#define SM_STRIDE 36
#define ARR_A_BYTES (128 * SM_STRIDE * 4)     // 18432

template<int SEL, int NJ>
__global__ __launch_bounds__(256, 2) void gemm_mma(const __half* __restrict__ Bmat,
                                                   const float* __restrict__ bias,
                                                   float* __restrict__ Cext,
                                                   int M, int N, int K) {
    constexpr int BN = 32 * NJ;
    constexpr uint32_t ARR_B = (uint32_t)BN * SM_STRIDE * 4;
    constexpr uint32_t STG = ARR_A_BYTES + ARR_B;
    const __half* A = (SEL == 0) ? g_xn : g_ctx;

    extern __shared__ char smem[];
    uint32_t sbase = smem_u32(smem);

    int tid = threadIdx.x;
    int wid = tid >> 5, lane = tid & 31;
    int g = lane >> 2, t = lane & 3;
    int wm = wid & 1, wn = wid >> 1;
    int m0 = blockIdx.y * 128, n0 = blockIdx.x * BN;
    int mw = wm * 64, nw = wn * (NJ * 8);

    int rA = (lane & 7) + ((lane >> 3) & 1) * 8;
    int cA = (lane >> 4) * 4;
    uint32_t aoff = (uint32_t)(rA * SM_STRIDE + cA) * 4u;
    int rB = lane & 7;
    int cB = ((lane >> 3) & 1) * 4;
    uint32_t boff = (uint32_t)(rB * SM_STRIDE + cB) * 4u;

    float acc[4][NJ][4];
    #pragma unroll
    for (int i = 0; i < 4; i++)
        #pragma unroll
        for (int j = 0; j < NJ; j++)
            #pragma unroll
            for (int q = 0; q < 4; q++) acc[i][j][q] = 0.f;

    int nch = K / 64;   // 12

    auto load_stage = [&](int ch, int s) {
        int kb = ch * 64;
        uint32_t so = sbase + (uint32_t)s * STG;
        // A: 128 rows x 8 x 16B
        #pragma unroll
        for (int l = 0; l < 4; l++) {
            int idx = tid + l * 256;
            int r = idx >> 3, c8 = idx & 7;
            uint32_t d = (uint32_t)(r * SM_STRIDE + c8 * 4) * 4u;
            int okA = (m0 + r < M) ? 16 : 0;
            size_t ao = (size_t)(m0 + r) * K + kb + c8 * 8;
            CP_ASYNC16(so + d, A + ao, okA);
        }
        // B: BN rows x 8 x 16B
        #pragma unroll
        for (int l = 0; l < BN / 32; l++) {
            int idx = tid + l * 256;
            int r = idx >> 3, c8 = idx & 7;
            uint32_t d = (uint32_t)(r * SM_STRIDE + c8 * 4) * 4u;
            size_t bo = (size_t)(n0 + r) * K + kb + c8 * 8;
            CP_ASYNC16(so + ARR_A_BYTES + d, Bmat + bo, 16);
        }
    };

    load_stage(0, 0);
    CP_COMMIT();
    load_stage(1, 1);
    CP_COMMIT();

    for (int ch = 0; ch < nch; ch++) {
        int s = ch % 3;
        if (ch + 1 < nch) CP_WAIT1(); else CP_WAIT0();
        __syncthreads();
        if (ch + 2 < nch) {
            load_stage(ch + 2, (ch + 2) % 3);
            CP_COMMIT();
        }

        uint32_t uA = sbase + (uint32_t)s * STG;
        uint32_t uB = uA + ARR_A_BYTES;

        #pragma unroll
        for (int kk = 0; kk < 4; kk++) {
            uint32_t kcb = (uint32_t)(kk * 8) * 4u;
            uint32_t ah[4][4], bh[NJ][2];
            #pragma unroll
            for (int mi = 0; mi < 4; mi++) {
                uint32_t base = (uint32_t)((mw + mi * 16) * SM_STRIDE) * 4u + kcb + aoff;
                ldsm_x4(ah[mi], uA + base);
            }
            #pragma unroll
            for (int nj = 0; nj < NJ; nj++) {
                uint32_t base = (uint32_t)((nw + nj * 8) * SM_STRIDE) * 4u + kcb + boff;
                ldsm_x2(bh[nj], uB + base);
            }
            #pragma unroll
            for (int mi = 0; mi < 4; mi++)
                #pragma unroll
                for (int nj = 0; nj < NJ; nj++)
                    mma_f16(acc[mi][nj], ah[mi], bh[nj]);
        }
    }

    // ---- epilogue ----
    #pragma unroll
    for (int mi = 0; mi < 4; mi++) {
        int r0e = m0 + mw + mi * 16 + g;
        #pragma unroll
        for (int nj = 0; nj < NJ; nj++) {
            int col = n0 + nw + nj * 8 + t * 2;
            if (SEL == 0) {
                #pragma unroll
                for (int half = 0; half < 2; half++) {
                    int row = r0e + half * 8;
                    if (row < M) {
                        uint32_t hp = pack2h(acc[mi][nj][2 * half], acc[mi][nj][2 * half + 1]);
                        *(uint32_t*)((char*)g_qkv + ((size_t)row * N + col) * 2) = hp;
                    }
                }
            } else {
                float b0 = bias[col], b1 = bias[col + 1];
                if (r0e < M)
                    *(float2*)(Cext + (size_t)r0e * N + col) =
                        make_float2(acc[mi][nj][0] + b0, acc[mi][nj][1] + b1);
                if (r0e + 8 < M)
                    *(float2*)(Cext + (size_t)(r0e + 8) * N + col) =
                        make_float2(acc[mi][nj][2] + b0, acc[mi][nj][3] + b1);
            }
        }
    }
}

#define GEMM0_SMEM (3 * (ARR_A_BYTES + 128 * SM_STRIDE * 4))   // NJ=4
#define GEMM1_SMEM (3 * (ARR_A_BYTES + 96 * SM_STRIDE * 4))    // NJ=3

// ================= attention + CLS fused: grid (9, 96) =================
#define ATT_STG_BYTES 18432u
#define ATT_SMEM      (3 * 18432)

__device__ __forceinline__ float warpReduceSum(float v) {
    #pragma unroll
    for (int o = 16; o > 0; o >>= 1) v += __shfl_xor_sync(0xffffffffu, v, o);
    return v;
}

__global__ __launch_bounds__(256, 2) void attn_mma_kernel(const float* __restrict__ canny,
                                                          const float* __restrict__ noise) {
    extern __shared__ uint32_t sh[];
    int qt = blockIdx.x;
    int bh_ = blockIdx.y;
    int b = bh_ / NH, h = bh_ % NH;
    int tid = threadIdx.x;
    size_t base = (size_t)b * NTOK * QKVW;

    if (qt == 8) {
        // ================= CLS row =================
        float* sm   = (float*)sh;
        float* q0   = sm + NTOK;
        float* red  = q0 + 64;
        float* part = red + 32;

        if (tid < 64) q0[tid] = __half2float(g_qkv[base + h * 64 + tid]);
        __syncthreads();

        for (int j = tid; j < NTOK; j += 256) {
            size_t ko = base + (size_t)j * QKVW + DMODEL + h * 64;
            float dot = 0.f;
            #pragma unroll
            for (int d2 = 0; d2 < 32; d2++) {
                __half2 kh = *(const __half2*)(g_qkv + ko + 2 * d2);
                dot += q0[2 * d2] * __half2float(kh.x) + q0[2 * d2 + 1] * __half2float(kh.y);
            }
            sm[j] = dot * SCALE;
        }
        __syncthreads();

        int lane = tid & 31, wp = tid >> 5;
        auto bSum = [&](float v) {
            v = warpReduceSum(v);
            __syncthreads();
            if (lane == 0) red[wp] = v;
            __syncthreads();
            if (tid == 0) {
                float s2 = 0.f;
                #pragma unroll
                for (int i = 0; i < 8; i++) s2 += red[i];
                red[0] = s2;
            }
            __syncthreads();
            return red[0];
        };
        auto bMax = [&](float v) {
            #pragma unroll
            for (int o = 16; o > 0; o >>= 1) v = fmaxf(v, __shfl_xor_sync(0xffffffffu, v, o));
            __syncthreads();
            if (lane == 0) red[wp] = v;
            __syncthreads();
            if (tid == 0) {
                float s2 = -1e30f;
                #pragma unroll
                for (int i = 0; i < 8; i++) s2 = fmaxf(s2, red[i]);
                red[0] = s2;
            }
            __syncthreads();
            return red[0];
        };

        float mx = -1e30f, cs = 0.f, ns = 0.f;
        for (int j = tid; j < NPATCH; j += 256) {
            mx = fmaxf(mx, sm[j + 1]);
            cs += canny[(size_t)b * NPATCH + j] + 1.f;
            ns += noise[(size_t)b * NPATCH + j];
        }
        mx = bMax(mx);
        cs = bSum(cs);
        ns = bSum(ns);
        float se = 0.f;
        for (int j = tid; j < NPATCH; j += 256) se += exp2f((sm[j + 1] - mx) * LOG2E);
        se = bSum(se);
        float inv_se = 1.f / se, inv_cs = 1.f / cs, inv_ns = 1.f / ns;
        for (int j = tid; j < NPATCH; j += 256) {
            float a = exp2f((sm[j + 1] - mx) * LOG2E) * inv_se;
            sm[j + 1] = a + (canny[(size_t)b * NPATCH + j] + 1.f) * inv_cs
                          + noise[(size_t)b * NPATCH + j] * inv_ns;
        }
        __syncthreads();

        float mx2 = -1e30f;
        for (int j = tid; j < NTOK; j += 256) mx2 = fmaxf(mx2, sm[j]);
        mx2 = bMax(mx2);
        float se2 = 0.f;
        for (int j = tid; j < NTOK; j += 256) se2 += exp2f((sm[j] - mx2) * LOG2E);
        se2 = bSum(se2);
        float inv2 = 1.f / se2;
        for (int j = tid; j < NTOK; j += 256) sm[j] = exp2f((sm[j] - mx2) * LOG2E) * inv2;
        __syncthreads();

        int d = tid & 63, qp = tid >> 6;
        float acc = 0.f;
        for (int j = qp; j < NTOK; j += 4) {
            size_t vo = base + (size_t)j * QKVW + 2 * DMODEL + h * 64 + d;
            acc += sm[j] * __half2float(g_qkv[vo]);
        }
        part[qp * 64 + d] = acc;
        __syncthreads();
        if (tid < 64) {
            float o = part[tid] + part[64 + tid] + part[128 + tid] + part[192 + tid];
            g_ctx[(size_t)b * NTOK * DMODEL + h * 64 + tid] = __float2half_rn(o);
        }
        return;
    }

    // ================= flash attention =================
    int wid = tid >> 5, lane = tid & 31;
    int g = lane >> 2, t = lane & 3;
    uint32_t sbase = smem_u32(sh);

    int row0 = 1 + qt * 128 + wid * 16;
    const float qsc = SCALE * LOG2E;
    const __half* Qp0 = g_qkv + base + (size_t)(row0 + g) * QKVW + h * 64;
    const __half* Qp1 = Qp0 + 8 * QKVW;
    uint32_t qh[4][4];
    #pragma unroll
    for (int kk = 0; kk < 4; kk++) {
        int k0 = kk * 16 + 2 * t;
        #pragma unroll
        for (int fi = 0; fi < 4; fi++) {
            int ko = k0 + (fi >> 1) * 8;
            const __half* p = (fi & 1) ? Qp1 : Qp0;
            __half2 v = *(const __half2*)(p + ko);
            qh[kk][fi] = pack2h(__half2float(v.x) * qsc, __half2float(v.y) * qsc);
        }
    }

    auto load_kv = [&](int c, int s) {
        int j0 = c * 64;
        uint32_t sb = sbase + (uint32_t)s * ATT_STG_BYTES;
        #pragma unroll
        for (int l = 0; l < 2; l++) {
            int idx = tid + l * 256;
            int r = idx >> 3, c8 = idx & 7;
            int j = j0 + r;
            uint32_t d = (uint32_t)(r * 36 + c8 * 4) * 4u;
            int ok = (j < NTOK) ? 16 : 0;
            size_t ko = base + (size_t)j * QKVW + DMODEL + h * 64 + c8 * 8;
            size_t vo = ko + DMODEL;
            CP_ASYNC16(sb + d,         (const char*)g_qkv + ko * 2, ok);
            CP_ASYNC16(sb + 9216u + d, (const char*)g_qkv + vo * 2, ok);
        }
    };

    int kfr = lane & 7, kfc = ((lane >> 3) & 1) * 4;
    uint32_t kfoff = (uint32_t)(kfr * 36 + kfc) * 4u;
    int vrow = (lane & 7) + ((lane >> 3) & 1) * 8;
    uint32_t vtoff = (uint32_t)vrow * 144u;

    float O[8][4];
    #pragma unroll
    for (int nj = 0; nj < 8; nj++)
        #pragma unroll
        for (int q = 0; q < 4; q++) O[nj][q] = 0.f;
    float mr0 = -1e30f, mr1 = -1e30f, lr0 = 0.f, lr1 = 0.f;

    load_kv(0, 0);
    CP_COMMIT();
    load_kv(1, 1);
    CP_COMMIT();

    for (int c = 0; c < 17; c++) {
        int s = c % 3;
        if (c + 1 < 17) CP_WAIT1(); else CP_WAIT0();
        __syncthreads();
        if (c + 2 < 17) {
            load_kv(c + 2, (c + 2) % 3);
            CP_COMMIT();
        }
        uint32_t uKH = sbase + (uint32_t)s * ATT_STG_BYTES;
        uint32_t uVH = uKH + 9216u + vtoff;
        int j0 = c * 64;

        float S[8][4];
        #pragma unroll
        for (int nj = 0; nj < 8; nj++)
            #pragma unroll
            for (int q = 0; q < 4; q++) S[nj][q] = 0.f;

        #pragma unroll
        for (int kk = 0; kk < 4; kk++) {
            uint32_t kcb = (uint32_t)(kk * 8) * 4u;
            #pragma unroll
            for (int nj = 0; nj < 8; nj++) {
                uint32_t kb[2];
                ldsm_x2(kb, uKH + (uint32_t)(nj * 8 * 36) * 4u + kcb + kfoff);
                mma_f16(S[nj], qh[kk], kb);
            }
        }

        if (j0 + 64 > NTOK) {
            #pragma unroll
            for (int nj = 0; nj < 8; nj++) {
                int col = j0 + 8 * nj + 2 * t;
                if (col >= NTOK)     { S[nj][0] = -1e30f; S[nj][2] = -1e30f; }
                if (col + 1 >= NTOK) { S[nj][1] = -1e30f; S[nj][3] = -1e30f; }
            }
        }

        float cm0 = -1e30f, cm1 = -1e30f;
        #pragma unroll
        for (int nj = 0; nj < 8; nj++) {
            cm0 = fmaxf(cm0, fmaxf(S[nj][0], S[nj][1]));
            cm1 = fmaxf(cm1, fmaxf(S[nj][2], S[nj][3]));
        }
        cm0 = fmaxf(cm0, __shfl_xor_sync(0xffffffffu, cm0, 1));
        cm0 = fmaxf(cm0, __shfl_xor_sync(0xffffffffu, cm0, 2));
        cm1 = fmaxf(cm1, __shfl_xor_sync(0xffffffffu, cm1, 1));
        cm1 = fmaxf(cm1, __shfl_xor_sync(0xffffffffu, cm1, 2));
        float mn0 = fmaxf(mr0, cm0), mn1 = fmaxf(mr1, cm1);
        float f0 = exp2f(mr0 - mn0), f1 = exp2f(mr1 - mn1);
        float ps0 = 0.f, ps1 = 0.f;
        #pragma unroll
        for (int nj = 0; nj < 8; nj++) {
            S[nj][0] = exp2f(S[nj][0] - mn0);
            S[nj][1] = exp2f(S[nj][1] - mn0);
            S[nj][2] = exp2f(S[nj][2] - mn1);
            S[nj][3] = exp2f(S[nj][3] - mn1);
            ps0 += S[nj][0] + S[nj][1];
            ps1 += S[nj][2] + S[nj][3];
        }
        ps0 += __shfl_xor_sync(0xffffffffu, ps0, 1);
        ps0 += __shfl_xor_sync(0xffffffffu, ps0, 2);
        ps1 += __shfl_xor_sync(0xffffffffu, ps1, 1);
        ps1 += __shfl_xor_sync(0xffffffffu, ps1, 2);
        lr0 = lr0 * f0 + ps0;
        lr1 = lr1 * f1 + ps1;
        mr0 = mn0; mr1 = mn1;
        #pragma unroll
        for (int nj = 0; nj < 8; nj++) {
            O[nj][0] *= f0; O[nj][1] *= f0;
            O[nj][2] *= f1; O[nj][3] *= f1;
        }

        #pragma unroll
        for (int kk = 0; kk < 4; kk++) {
            int j2 = 2 * kk;
            uint32_t ph[4];
            ph[0] = pack2h(S[j2][0],     S[j2][1]);
            ph[1] = pack2h(S[j2][2],     S[j2][3]);
            ph[2] = pack2h(S[j2 + 1][0], S[j2 + 1][1]);
            ph[3] = pack2h(S[j2 + 1][2], S[j2 + 1][3]);
            uint32_t kbase = (uint32_t)(kk * 16) * 144u;
            #pragma unroll
            for (int nj = 0; nj < 8; nj++) {
                uint32_t vh[2];
                ldsm_x2_trans(vh, uVH + kbase + (uint32_t)nj * 16u);
                mma_f16(O[nj], ph, vh);
            }
        }
    }

    float i0 = 1.f / lr0, i1 = 1.f / lr1;
    size_t o0 = ((size_t)b * NTOK + row0 + g) * DMODEL + h * 64;
    size_t o1 = o0 + (size_t)8 * DMODEL;
    #pragma unroll
    for (int nj = 0; nj < 8; nj++) {
        int col = 8 * nj + 2 * t;
        *(uint32_t*)((char*)g_ctx + (o0 + col) * 2) = pack2h(O[nj][0] * i0, O[nj][1] * i0);
        *(uint32_t*)((char*)g_ctx + (o1 + col) * 2) = pack2h(O[nj][2] * i1, O[nj][3] * i1);
    }
}

// ---------------- launch ----------------
extern "C" void kernel_launch(void* const* d_in, const int* in_sizes, int n_in,
                              void* d_out, int out_size) {
    const float* x     = (const float*)d_in[0];
    const float* canny = (const float*)d_in[1];
    const float* noise = (const float*)d_in[2];
    const float* ln_w  = (const float*)d_in[3];
    const float* ln_b  = (const float*)d_in[4];
    const float* w_qkv = (const float*)d_in[5];
    const float* w_out = (const float*)d_in[6];
    const float* b_out = (const float*)d_in[7];
    float* out = (float*)d_out;

    cudaFuncSetAttribute((const void*)gemm_mma<0, 4>, cudaFuncAttributeMaxDynamicSharedMemorySize, GEMM0_SMEM);
    cudaFuncSetAttribute((const void*)gemm_mma<1, 3>, cudaFuncAttributeMaxDynamicSharedMemorySize, GEMM1_SMEM);
    cudaFuncSetAttribute(attn_mma_kernel, cudaFuncAttributeMaxDynamicSharedMemorySize, ATT_SMEM);

    __half *wqkvT, *woutT;
    cudaGetSymbolAddress((void**)&wqkvT, g_wqkvT);
    cudaGetSymbolAddress((void**)&woutT, g_woutT);

    // 1. prep: LN + transposes (single launch)
    prep_kernel<<<LN_BLOCKS + TQ_TILES + TO_TILES, 256>>>(x, ln_w, ln_b, w_qkv, w_out);

    // 2. QKV GEMM (fp16, BK=64, 3-stage, BN=128) -> g_qkv
    {
        dim3 grid(QKVW / 128, (MTOT + 127) / 128);
        gemm_mma<0, 4><<<grid, 256, GEMM0_SMEM>>>(wqkvT, nullptr, nullptr, MTOT, QKVW, DMODEL);
    }

    // 3. attention + CLS fused: grid (9, 96)
    {
        dim3 g_attn(9, BATCH * NH);
        attn_mma_kernel<<<g_attn, 256, ATT_SMEM>>>(canny, noise);
    }

    // 4. output projection (fp16, BK=64, 3-stage, BN=96) -> d_out (fp32 + bias)
    {
        dim3 grid(DMODEL / 96, (MTOT + 127) / 128);
        gemm_mma<1, 3><<<grid, 256, GEMM1_SMEM>>>(woutT, b_out, out, MTOT, DMODEL, DMODEL);
    }
}